// round 1
// baseline (speedup 1.0000x reference)
#include <cuda_runtime.h>
#include <cuda_bf16.h>
#include <cstdint>

// ---------------- Problem constants (fixed for this problem) ----------------
#define NB   8         // batch
#define LQ   1000      // queries
#define NQ   (NB*LQ)   // 8000
#define DIM  256
#define HEADS 8
#define HD   32
#define LVLS 4
#define PTS  4
#define LIN  21760
#define DFF  512

// level tables (from SHAPES = [(128,128),(64,64),(32,32),(16,16)])
__device__ __constant__ int c_H[4]  = {128, 64, 32, 16};
__device__ __constant__ int c_W[4]  = {128, 64, 32, 16};
__device__ __constant__ int c_S[4]  = {0, 16384, 20480, 21504};

// ---------------- Scratch (no runtime allocation allowed) ----------------
__device__ float g_value[(size_t)LIN * NB * DIM];   // [N, Lin, H, HD] = 178 MB
__device__ float g_q    [(size_t)NQ * DIM];
__device__ float g_off  [(size_t)NQ * DIM];          // H*L*P*2 = 256
__device__ float g_attn [(size_t)NQ * 128];          // H*L*P = 128 logits
__device__ float g_samp [(size_t)NQ * DIM];
__device__ float g_ms   [(size_t)NQ * DIM];
__device__ float g_tgt  [(size_t)NQ * DIM];
__device__ float g_ffh  [(size_t)NQ * DFF];
__device__ float g_ff   [(size_t)NQ * DIM];

// ---------------- elementwise q = pre_tgt + pre_query_pos ----------------
__global__ void addq_kernel(const float* __restrict__ a, const float* __restrict__ b,
                            float* __restrict__ o, int n)
{
    int i = blockIdx.x * blockDim.x + threadIdx.x;
    if (i < n) o[i] = a[i] + b[i];
}

// ---------------- fp32 tiled SGEMM: C[M,N] = A[M,K] @ B[K,N] + bias ----------------
// BM=BN=128, BK=8, 256 threads, 8x8 per thread. N,K must be multiples of 8; N mult of 128.
template<int ACT, bool MASK>
__global__ void sgemm_kernel(const float* __restrict__ A, const float* __restrict__ B,
                             const float* __restrict__ bias, float* __restrict__ C,
                             int M, int N, int K, const unsigned char* __restrict__ rowmask)
{
    __shared__ float As[8][128];
    __shared__ float Bs[8][128];

    const int tid  = threadIdx.x;
    const int brow = blockIdx.y * 128;
    const int bcol = blockIdx.x * 128;
    const int trow = (tid >> 4) * 8;
    const int tcol = (tid & 15) * 8;

    const int arow = tid >> 1;          // 0..127
    const int ak   = (tid & 1) * 4;     // 0 or 4
    const int bkr  = tid >> 5;          // 0..7
    const int bc4  = (tid & 31) * 4;    // 0..124

    float acc[8][8];
    #pragma unroll
    for (int i = 0; i < 8; i++)
        #pragma unroll
        for (int j = 0; j < 8; j++) acc[i][j] = 0.f;

    for (int k0 = 0; k0 < K; k0 += 8) {
        float4 av;
        if (brow + arow < M)
            av = *reinterpret_cast<const float4*>(A + (size_t)(brow + arow) * K + k0 + ak);
        else
            av = make_float4(0.f, 0.f, 0.f, 0.f);
        As[ak + 0][arow] = av.x;
        As[ak + 1][arow] = av.y;
        As[ak + 2][arow] = av.z;
        As[ak + 3][arow] = av.w;

        float4 bv = *reinterpret_cast<const float4*>(B + (size_t)(k0 + bkr) * N + bcol + bc4);
        *reinterpret_cast<float4*>(&Bs[bkr][bc4]) = bv;

        __syncthreads();

        #pragma unroll
        for (int k = 0; k < 8; k++) {
            float ra[8], rb[8];
            #pragma unroll
            for (int i = 0; i < 8; i++) ra[i] = As[k][trow + i];
            #pragma unroll
            for (int j = 0; j < 8; j++) rb[j] = Bs[k][tcol + j];
            #pragma unroll
            for (int i = 0; i < 8; i++)
                #pragma unroll
                for (int j = 0; j < 8; j++)
                    acc[i][j] += ra[i] * rb[j];
        }
        __syncthreads();
    }

    #pragma unroll
    for (int i = 0; i < 8; i++) {
        int r = brow + trow + i;
        if (r >= M) break;
        bool zero = false;
        if (MASK) zero = (rowmask[r] != 0);
        #pragma unroll
        for (int j = 0; j < 8; j += 4) {
            float4 v;
            v.x = acc[i][j + 0] + bias[bcol + tcol + j + 0];
            v.y = acc[i][j + 1] + bias[bcol + tcol + j + 1];
            v.z = acc[i][j + 2] + bias[bcol + tcol + j + 2];
            v.w = acc[i][j + 3] + bias[bcol + tcol + j + 3];
            if (ACT == 1) {
                v.x = fmaxf(v.x, 0.f); v.y = fmaxf(v.y, 0.f);
                v.z = fmaxf(v.z, 0.f); v.w = fmaxf(v.w, 0.f);
            }
            if (MASK && zero) { v.x = v.y = v.z = v.w = 0.f; }
            *reinterpret_cast<float4*>(C + (size_t)r * N + bcol + tcol + j) = v;
        }
    }
}

// ---------------- MS-deform sampling: softmax + bilinear gather + weighted sum ----
// One block per query (nq), one warp per head. lane = channel (HD=32).
__global__ void msda_kernel(const float* __restrict__ value,   // [N,Lin,H,HD]
                            const float* __restrict__ offb,    // [NQ, 256]
                            const float* __restrict__ logits,  // [NQ, 128]
                            const float* __restrict__ refpts,  // [N,Lq,L,2] -> [NQ,8]
                            float* __restrict__ samp)          // [NQ, 256]
{
    const int nq   = blockIdx.x;
    const int h    = threadIdx.x >> 5;
    const int lane = threadIdx.x & 31;
    const int n    = nq / LQ;

    // softmax over 16 logits (L*P) for this head; lanes 0..15 hold them.
    float logit = (lane < 16) ? logits[(size_t)nq * 128 + h * 16 + lane] : -1e30f;
    float m = logit;
    #pragma unroll
    for (int o = 8; o > 0; o >>= 1) m = fmaxf(m, __shfl_xor_sync(0xffffffffu, m, o, 16));
    float e = (lane < 16) ? __expf(logit - m) : 0.f;
    float s = e;
    #pragma unroll
    for (int o = 8; o > 0; o >>= 1) s += __shfl_xor_sync(0xffffffffu, s, o, 16);
    float w = e / s;   // valid on lanes 0..15

    // offsets for this head: 32 floats (l*8 + p*2 + c), lane = index
    float offv = offb[(size_t)nq * 256 + h * 32 + lane];
    // ref points: 8 floats (l*2 + c) on lanes 0..7
    float refv = (lane < 8) ? refpts[(size_t)nq * 8 + lane] : 0.f;

    const float* vbase = value + ((size_t)n * LIN * HEADS + h) * HD + lane;

    float acc = 0.f;
    #pragma unroll
    for (int i = 0; i < 16; i++) {
        const int l = i >> 2;
        const int p = i & 3;
        const float wi   = __shfl_sync(0xffffffffu, w,    i);
        const float offx = __shfl_sync(0xffffffffu, offv, l * 8 + p * 2 + 0);
        const float offy = __shfl_sync(0xffffffffu, offv, l * 8 + p * 2 + 1);
        const float refx = __shfl_sync(0xffffffffu, refv, l * 2 + 0);
        const float refy = __shfl_sync(0xffffffffu, refv, l * 2 + 1);

        const int Hl = c_H[l], Wl = c_W[l], st = c_S[l];
        const float x = refx * (float)Wl + offx - 0.5f;
        const float y = refy * (float)Hl + offy - 0.5f;
        const float x0f = floorf(x), y0f = floorf(y);
        const float fx = x - x0f, fy = y - y0f;
        const int x0 = (int)x0f, y0 = (int)y0f;
        const int x1 = x0 + 1,   y1 = y0 + 1;

        const bool vx0 = (x0 >= 0) & (x0 < Wl);
        const bool vx1 = (x1 >= 0) & (x1 < Wl);
        const bool vy0 = (y0 >= 0) & (y0 < Hl);
        const bool vy1 = (y1 >= 0) & (y1 < Hl);

        float sv = 0.f;
        if (vy0) {
            const float* row = vbase + (size_t)(st + y0 * Wl) * HEADS * HD;
            if (vx0) sv += (1.f - fx) * (1.f - fy) * row[(size_t)x0 * HEADS * HD];
            if (vx1) sv += fx * (1.f - fy)         * row[(size_t)x1 * HEADS * HD];
        }
        if (vy1) {
            const float* row = vbase + (size_t)(st + y1 * Wl) * HEADS * HD;
            if (vx0) sv += (1.f - fx) * fy * row[(size_t)x0 * HEADS * HD];
            if (vx1) sv += fx * fy         * row[(size_t)x1 * HEADS * HD];
        }
        acc += wi * sv;
    }
    samp[(size_t)nq * 256 + h * 32 + lane] = acc;
}

// ---------------- fused residual + LayerNorm (rows of 256) ----------------
__global__ void ln_kernel(const float* __restrict__ a, const float* __restrict__ b,
                          const float* __restrict__ g, const float* __restrict__ be,
                          float* __restrict__ out)
{
    const int row = blockIdx.x;
    const int t   = threadIdx.x;             // 256 threads
    const float x = a[(size_t)row * 256 + t] + b[(size_t)row * 256 + t];

    float s = x, s2 = x * x;
    #pragma unroll
    for (int o = 16; o > 0; o >>= 1) {
        s  += __shfl_xor_sync(0xffffffffu, s,  o);
        s2 += __shfl_xor_sync(0xffffffffu, s2, o);
    }
    __shared__ float ws[8], ws2[8];
    __shared__ float sm, sv;
    if ((t & 31) == 0) { ws[t >> 5] = s; ws2[t >> 5] = s2; }
    __syncthreads();
    if (t == 0) {
        float S = 0.f, S2 = 0.f;
        #pragma unroll
        for (int i = 0; i < 8; i++) { S += ws[i]; S2 += ws2[i]; }
        const float mean = S * (1.f / 256.f);
        sm = mean;
        sv = rsqrtf(S2 * (1.f / 256.f) - mean * mean + 1e-5f);
    }
    __syncthreads();
    out[(size_t)row * 256 + t] = (x - sm) * sv * g[t] + be[t];
}

// ---------------- launch ----------------
extern "C" void kernel_launch(void* const* d_in, const int* in_sizes, int n_in,
                              void* d_out, int out_size)
{
    const float* pre_tgt  = (const float*)d_in[0];
    const float* pre_qpos = (const float*)d_in[1];
    const float* src      = (const float*)d_in[2];
    const float* ref_pts  = (const float*)d_in[3];
    const unsigned char* mask = (const unsigned char*)d_in[4];
    // d_in[5] spatial shapes, d_in[6] level starts — fixed, baked into constants
    const float* W_value = (const float*)d_in[7];
    const float* b_value = (const float*)d_in[8];
    const float* W_off   = (const float*)d_in[9];
    const float* b_off   = (const float*)d_in[10];
    const float* W_attn  = (const float*)d_in[11];
    const float* b_attn  = (const float*)d_in[12];
    const float* W_out   = (const float*)d_in[13];
    const float* b_out   = (const float*)d_in[14];
    const float* g1      = (const float*)d_in[15];
    const float* be1     = (const float*)d_in[16];
    const float* W1      = (const float*)d_in[17];
    const float* b1      = (const float*)d_in[18];
    const float* W2      = (const float*)d_in[19];
    const float* b2      = (const float*)d_in[20];
    const float* g3      = (const float*)d_in[21];
    const float* be3     = (const float*)d_in[22];

    float *p_value, *p_q, *p_off, *p_attn, *p_samp, *p_ms, *p_tgt, *p_ffh, *p_ff;
    cudaGetSymbolAddress((void**)&p_value, g_value);
    cudaGetSymbolAddress((void**)&p_q,     g_q);
    cudaGetSymbolAddress((void**)&p_off,   g_off);
    cudaGetSymbolAddress((void**)&p_attn,  g_attn);
    cudaGetSymbolAddress((void**)&p_samp,  g_samp);
    cudaGetSymbolAddress((void**)&p_ms,    g_ms);
    cudaGetSymbolAddress((void**)&p_tgt,   g_tgt);
    cudaGetSymbolAddress((void**)&p_ffh,   g_ffh);
    cudaGetSymbolAddress((void**)&p_ff,    g_ff);

    const int MV = NB * LIN;   // 174080

    // 1. q = pre_tgt + pre_query_pos
    addq_kernel<<<(NQ * DIM + 255) / 256, 256>>>(pre_tgt, pre_qpos, p_q, NQ * DIM);

    // 2. value = mask(src @ W_value + b_value)   [174080, 256]
    sgemm_kernel<0, true ><<<dim3(DIM / 128, (MV + 127) / 128), 256>>>(
        src, W_value, b_value, p_value, MV, DIM, DIM, mask);

    // 3. off = q @ W_off + b_off   [8000, 256]
    sgemm_kernel<0, false><<<dim3(DIM / 128, (NQ + 127) / 128), 256>>>(
        p_q, W_off, b_off, p_off, NQ, DIM, DIM, nullptr);

    // 4. attn logits = q @ W_attn + b_attn   [8000, 128]
    sgemm_kernel<0, false><<<dim3(1, (NQ + 127) / 128), 256>>>(
        p_q, W_attn, b_attn, p_attn, NQ, 128, DIM, nullptr);

    // 5. sampling (softmax fused)
    msda_kernel<<<NQ, 256>>>(p_value, p_off, p_attn, ref_pts, p_samp);

    // 6. ms out = samp @ W_out + b_out
    sgemm_kernel<0, false><<<dim3(DIM / 128, (NQ + 127) / 128), 256>>>(
        p_samp, W_out, b_out, p_ms, NQ, DIM, DIM, nullptr);

    // 7. tgt = LN(pre_tgt + ms, g1, be1)
    ln_kernel<<<NQ, 256>>>(pre_tgt, p_ms, g1, be1, p_tgt);

    // 8. ffh = relu(tgt @ W1 + b1)   [8000, 512]
    sgemm_kernel<1, false><<<dim3(DFF / 128, (NQ + 127) / 128), 256>>>(
        p_tgt, W1, b1, p_ffh, NQ, DFF, DIM, nullptr);

    // 9. ff = ffh @ W2 + b2   [8000, 256]
    sgemm_kernel<0, false><<<dim3(DIM / 128, (NQ + 127) / 128), 256>>>(
        p_ffh, W2, b2, p_ff, NQ, DIM, DFF, nullptr);

    // 10. out = LN(tgt + ff, g3, be3)
    ln_kernel<<<NQ, 256>>>(p_tgt, p_ff, g3, be3, (float*)d_out);
}

// round 3
// speedup vs baseline: 2.3800x; 2.3800x over previous
#include <cuda_runtime.h>
#include <cstdint>

// ---------------- Problem constants ----------------
#define NB   8
#define LQ   1000
#define NQ   (NB*LQ)
#define DIM  256
#define HEADS 8
#define HD   32
#define LIN  21760
#define DFF  512

__device__ __constant__ int c_H[4]  = {128, 64, 32, 16};
__device__ __constant__ int c_W[4]  = {128, 64, 32, 16};
__device__ __constant__ int c_S[4]  = {0, 16384, 20480, 21504};

// ---------------- Scratch (static device memory; no runtime alloc) ----------------
__device__ float g_value[(size_t)LIN * NB * DIM];   // 178 MB
__device__ float g_q    [(size_t)NQ * DIM];
__device__ float g_off  [(size_t)NQ * DIM];
__device__ float g_attn [(size_t)NQ * 128];
__device__ float g_samp [(size_t)NQ * DIM];
__device__ float g_ms   [(size_t)NQ * DIM];
__device__ float g_tgt  [(size_t)NQ * DIM];
__device__ float g_ffh  [(size_t)NQ * DFF];
__device__ float g_ff   [(size_t)NQ * DIM];
// transposed weights [N, K]
__device__ float g_WvT  [DIM * DIM];
__device__ float g_WoffT[DIM * DIM];
__device__ float g_WattnT[128 * DIM];
__device__ float g_WoutT[DIM * DIM];
__device__ float g_W1T  [DFF * DIM];
__device__ float g_W2T  [DIM * DFF];

// ---------------- tf32 helpers (baseline sm_80+ ISA only) ----------------
__device__ __forceinline__ float tf32r(float x) {
    uint32_t u;
    asm("cvt.rna.tf32.f32 %0, %1;" : "=r"(u) : "f"(x));
    return __uint_as_float(u);
}

__device__ __forceinline__ void mma_tf32(float* d, const uint32_t* a, const uint32_t* b) {
    asm volatile(
        "mma.sync.aligned.m16n8k8.row.col.f32.tf32.tf32.f32 "
        "{%0,%1,%2,%3}, {%4,%5,%6,%7}, {%8,%9}, {%0,%1,%2,%3};"
        : "+f"(d[0]), "+f"(d[1]), "+f"(d[2]), "+f"(d[3])
        : "r"(a[0]), "r"(a[1]), "r"(a[2]), "r"(a[3]), "r"(b[0]), "r"(b[1]));
}

#define SMS 20   // padded smem stride (floats) — conflict-free for fragment reads

// ---------------- tf32 mma.sync GEMM: C[M,N] = A[M,K] @ Bt[N,K]^T + bias ----------------
// grid(N/128, ceil(M/128)), 256 threads. K mult of 16, N mult of 128.
template<int ACT, bool MASK>
__global__ void __launch_bounds__(256, 2) mma_gemm(
    const float* __restrict__ A, const float* __restrict__ Bt,
    const float* __restrict__ bias, float* __restrict__ C,
    int M, int N, int K, const unsigned char* __restrict__ rowmask)
{
    __shared__ float As[2][128 * SMS];
    __shared__ float Bs[2][128 * SMS];

    const int tid  = threadIdx.x;
    const int lane = tid & 31;
    const int wid  = tid >> 5;
    const int wr   = wid & 3;       // warp row (4)
    const int wc   = wid >> 2;      // warp col (2)
    const int gid  = lane >> 2;
    const int tig  = lane & 3;
    const int brow = blockIdx.y * 128;
    const int bcol = blockIdx.x * 128;

    const int r_st = tid >> 2;          // staging row 0..63 (+64 for second)
    const int k_st = (tid & 3) * 4;     // staging k offset

    float acc[2][8][4];
    #pragma unroll
    for (int i = 0; i < 2; i++)
        #pragma unroll
        for (int j = 0; j < 8; j++)
            #pragma unroll
            for (int l = 0; l < 4; l++) acc[i][j][l] = 0.f;

    const int KT = K >> 4;
    float4 ra[2], rb[2];

    // ---- g2r for kt=0
    #pragma unroll
    for (int i = 0; i < 2; i++) {
        int r = r_st + i * 64;
        int garow = brow + r; if (garow >= M) garow = M - 1;
        ra[i] = *reinterpret_cast<const float4*>(A  + (size_t)garow * K + k_st);
        rb[i] = *reinterpret_cast<const float4*>(Bt + (size_t)(bcol + r) * K + k_st);
    }
    // ---- r2s buf 0 (with tf32 rounding)
    #pragma unroll
    for (int i = 0; i < 2; i++) {
        int r = r_st + i * 64;
        float4 av = make_float4(tf32r(ra[i].x), tf32r(ra[i].y), tf32r(ra[i].z), tf32r(ra[i].w));
        float4 bv = make_float4(tf32r(rb[i].x), tf32r(rb[i].y), tf32r(rb[i].z), tf32r(rb[i].w));
        *reinterpret_cast<float4*>(&As[0][r * SMS + k_st]) = av;
        *reinterpret_cast<float4*>(&Bs[0][r * SMS + k_st]) = bv;
    }
    __syncthreads();

    for (int kt = 0; kt < KT; kt++) {
        const int buf = kt & 1;
        if (kt + 1 < KT) {
            const int kc = (kt + 1) * 16;
            #pragma unroll
            for (int i = 0; i < 2; i++) {
                int r = r_st + i * 64;
                int garow = brow + r; if (garow >= M) garow = M - 1;
                ra[i] = *reinterpret_cast<const float4*>(A  + (size_t)garow * K + kc + k_st);
                rb[i] = *reinterpret_cast<const float4*>(Bt + (size_t)(bcol + r) * K + kc + k_st);
            }
        }

        // ---- compute on buf
        const float* as = As[buf];
        const float* bs = Bs[buf];
        #pragma unroll
        for (int ks = 0; ks < 2; ks++) {
            const int k0 = ks * 8;
            uint32_t af[2][4];
            #pragma unroll
            for (int mt = 0; mt < 2; mt++) {
                const int mb = wr * 32 + mt * 16;
                af[mt][0] = __float_as_uint(as[(mb + gid    ) * SMS + k0 + tig    ]);
                af[mt][1] = __float_as_uint(as[(mb + gid + 8) * SMS + k0 + tig    ]);
                af[mt][2] = __float_as_uint(as[(mb + gid    ) * SMS + k0 + tig + 4]);
                af[mt][3] = __float_as_uint(as[(mb + gid + 8) * SMS + k0 + tig + 4]);
            }
            #pragma unroll
            for (int nt = 0; nt < 8; nt++) {
                const int nb = wc * 64 + nt * 8 + gid;
                uint32_t bf[2];
                bf[0] = __float_as_uint(bs[nb * SMS + k0 + tig    ]);
                bf[1] = __float_as_uint(bs[nb * SMS + k0 + tig + 4]);
                mma_tf32(acc[0][nt], af[0], bf);
                mma_tf32(acc[1][nt], af[1], bf);
            }
        }

        if (kt + 1 < KT) {
            const int nb2 = (kt + 1) & 1;
            #pragma unroll
            for (int i = 0; i < 2; i++) {
                int r = r_st + i * 64;
                float4 av = make_float4(tf32r(ra[i].x), tf32r(ra[i].y), tf32r(ra[i].z), tf32r(ra[i].w));
                float4 bv = make_float4(tf32r(rb[i].x), tf32r(rb[i].y), tf32r(rb[i].z), tf32r(rb[i].w));
                *reinterpret_cast<float4*>(&As[nb2][r * SMS + k_st]) = av;
                *reinterpret_cast<float4*>(&Bs[nb2][r * SMS + k_st]) = bv;
            }
            __syncthreads();
        }
    }

    // ---- epilogue: registers -> global
    #pragma unroll
    for (int mt = 0; mt < 2; mt++) {
        const int r0 = brow + wr * 32 + mt * 16 + gid;
        const int r1 = r0 + 8;
        const bool v0 = r0 < M, v1 = r1 < M;
        bool z0 = false, z1 = false;
        if (MASK) {
            if (v0) z0 = (rowmask[r0] != 0);
            if (v1) z1 = (rowmask[r1] != 0);
        }
        #pragma unroll
        for (int nt = 0; nt < 8; nt++) {
            const int col = bcol + wc * 64 + nt * 8 + 2 * tig;
            const float b0 = bias[col], b1 = bias[col + 1];
            float2 u, v;
            u.x = acc[mt][nt][0] + b0; u.y = acc[mt][nt][1] + b1;
            v.x = acc[mt][nt][2] + b0; v.y = acc[mt][nt][3] + b1;
            if (ACT == 1) {
                u.x = fmaxf(u.x, 0.f); u.y = fmaxf(u.y, 0.f);
                v.x = fmaxf(v.x, 0.f); v.y = fmaxf(v.y, 0.f);
            }
            if (MASK) {
                if (z0) { u.x = 0.f; u.y = 0.f; }
                if (z1) { v.x = 0.f; v.y = 0.f; }
            }
            if (v0) *reinterpret_cast<float2*>(C + (size_t)r0 * N + col) = u;
            if (v1) *reinterpret_cast<float2*>(C + (size_t)r1 * N + col) = v;
        }
    }
}

// ---------------- weight transpose: Wt[N,K] = W[K,N] ----------------
__global__ void transpose_kernel(const float* __restrict__ W, float* __restrict__ Wt,
                                 int K, int N)
{
    __shared__ float t[32][33];
    const int bx = blockIdx.x * 32;
    const int by = blockIdx.y * 32;
    const int x = threadIdx.x, y = threadIdx.y;
    #pragma unroll
    for (int i = 0; i < 32; i += 8)
        t[y + i][x] = W[(size_t)(by + y + i) * N + bx + x];
    __syncthreads();
    #pragma unroll
    for (int i = 0; i < 32; i += 8)
        Wt[(size_t)(bx + y + i) * K + by + x] = t[x][y + i];
}

// ---------------- elementwise q = a + b ----------------
__global__ void addq_kernel(const float* __restrict__ a, const float* __restrict__ b,
                            float* __restrict__ o, int n)
{
    int i = blockIdx.x * blockDim.x + threadIdx.x;
    if (i < n) o[i] = a[i] + b[i];
}

// ---------------- MS-deform sampling (softmax fused), warp per (query,head) ----------
__global__ void msda_kernel(const float* __restrict__ value,
                            const float* __restrict__ offb,
                            const float* __restrict__ logits,
                            const float* __restrict__ refpts,
                            float* __restrict__ samp)
{
    const int nq   = blockIdx.x;
    const int h    = threadIdx.x >> 5;
    const int lane = threadIdx.x & 31;
    const int n    = nq / LQ;

    float logit = (lane < 16) ? logits[(size_t)nq * 128 + h * 16 + lane] : -1e30f;
    float m = logit;
    #pragma unroll
    for (int o = 8; o > 0; o >>= 1) m = fmaxf(m, __shfl_xor_sync(0xffffffffu, m, o, 16));
    float e = (lane < 16) ? __expf(logit - m) : 0.f;
    float s = e;
    #pragma unroll
    for (int o = 8; o > 0; o >>= 1) s += __shfl_xor_sync(0xffffffffu, s, o, 16);
    float w = e / s;

    float offv = offb[(size_t)nq * 256 + h * 32 + lane];
    float refv = (lane < 8) ? refpts[(size_t)nq * 8 + lane] : 0.f;

    const float* vbase = value + ((size_t)n * LIN * HEADS + h) * HD + lane;

    float acc = 0.f;
    #pragma unroll
    for (int i = 0; i < 16; i++) {
        const int l = i >> 2;
        const int p = i & 3;
        const float wi   = __shfl_sync(0xffffffffu, w,    i);
        const float offx = __shfl_sync(0xffffffffu, offv, l * 8 + p * 2 + 0);
        const float offy = __shfl_sync(0xffffffffu, offv, l * 8 + p * 2 + 1);
        const float refx = __shfl_sync(0xffffffffu, refv, l * 2 + 0);
        const float refy = __shfl_sync(0xffffffffu, refv, l * 2 + 1);

        const int Hl = c_H[l], Wl = c_W[l], st = c_S[l];
        const float x = refx * (float)Wl + offx - 0.5f;
        const float y = refy * (float)Hl + offy - 0.5f;
        const float x0f = floorf(x), y0f = floorf(y);
        const float fx = x - x0f, fy = y - y0f;
        const int x0 = (int)x0f, y0 = (int)y0f;
        const int x1 = x0 + 1,   y1 = y0 + 1;

        const bool vx0 = (x0 >= 0) & (x0 < Wl);
        const bool vx1 = (x1 >= 0) & (x1 < Wl);
        const bool vy0 = (y0 >= 0) & (y0 < Hl);
        const bool vy1 = (y1 >= 0) & (y1 < Hl);

        float sv = 0.f;
        if (vy0) {
            const float* rowp = vbase + (size_t)(st + y0 * Wl) * HEADS * HD;
            if (vx0) sv += (1.f - fx) * (1.f - fy) * rowp[(size_t)x0 * HEADS * HD];
            if (vx1) sv += fx * (1.f - fy)         * rowp[(size_t)x1 * HEADS * HD];
        }
        if (vy1) {
            const float* rowp = vbase + (size_t)(st + y1 * Wl) * HEADS * HD;
            if (vx0) sv += (1.f - fx) * fy * rowp[(size_t)x0 * HEADS * HD];
            if (vx1) sv += fx * fy         * rowp[(size_t)x1 * HEADS * HD];
        }
        acc += wi * sv;
    }
    samp[(size_t)nq * 256 + h * 32 + lane] = acc;
}

// ---------------- fused residual + LayerNorm ----------------
__global__ void ln_kernel(const float* __restrict__ a, const float* __restrict__ b,
                          const float* __restrict__ g, const float* __restrict__ be,
                          float* __restrict__ out)
{
    const int row = blockIdx.x;
    const int t   = threadIdx.x;
    const float x = a[(size_t)row * 256 + t] + b[(size_t)row * 256 + t];

    float s = x, s2 = x * x;
    #pragma unroll
    for (int o = 16; o > 0; o >>= 1) {
        s  += __shfl_xor_sync(0xffffffffu, s,  o);
        s2 += __shfl_xor_sync(0xffffffffu, s2, o);
    }
    __shared__ float ws[8], ws2[8];
    __shared__ float sm, sv;
    if ((t & 31) == 0) { ws[t >> 5] = s; ws2[t >> 5] = s2; }
    __syncthreads();
    if (t == 0) {
        float S = 0.f, S2 = 0.f;
        #pragma unroll
        for (int i = 0; i < 8; i++) { S += ws[i]; S2 += ws2[i]; }
        const float mean = S * (1.f / 256.f);
        sm = mean;
        sv = rsqrtf(S2 * (1.f / 256.f) - mean * mean + 1e-5f);
    }
    __syncthreads();
    out[(size_t)row * 256 + t] = (x - sm) * sv * g[t] + be[t];
}

// ---------------- launch ----------------
extern "C" void kernel_launch(void* const* d_in, const int* in_sizes, int n_in,
                              void* d_out, int out_size)
{
    const float* pre_tgt  = (const float*)d_in[0];
    const float* pre_qpos = (const float*)d_in[1];
    const float* src      = (const float*)d_in[2];
    const float* ref_pts  = (const float*)d_in[3];
    const unsigned char* mask = (const unsigned char*)d_in[4];
    const float* W_value = (const float*)d_in[7];
    const float* b_value = (const float*)d_in[8];
    const float* W_off   = (const float*)d_in[9];
    const float* b_off   = (const float*)d_in[10];
    const float* W_attn  = (const float*)d_in[11];
    const float* b_attn  = (const float*)d_in[12];
    const float* W_out   = (const float*)d_in[13];
    const float* b_out   = (const float*)d_in[14];
    const float* g1      = (const float*)d_in[15];
    const float* be1     = (const float*)d_in[16];
    const float* W1      = (const float*)d_in[17];
    const float* b1      = (const float*)d_in[18];
    const float* W2      = (const float*)d_in[19];
    const float* b2      = (const float*)d_in[20];
    const float* g3      = (const float*)d_in[21];
    const float* be3     = (const float*)d_in[22];

    float *p_value, *p_q, *p_off, *p_attn, *p_samp, *p_ms, *p_tgt, *p_ffh, *p_ff;
    float *p_WvT, *p_WoffT, *p_WattnT, *p_WoutT, *p_W1T, *p_W2T;
    cudaGetSymbolAddress((void**)&p_value, g_value);
    cudaGetSymbolAddress((void**)&p_q,     g_q);
    cudaGetSymbolAddress((void**)&p_off,   g_off);
    cudaGetSymbolAddress((void**)&p_attn,  g_attn);
    cudaGetSymbolAddress((void**)&p_samp,  g_samp);
    cudaGetSymbolAddress((void**)&p_ms,    g_ms);
    cudaGetSymbolAddress((void**)&p_tgt,   g_tgt);
    cudaGetSymbolAddress((void**)&p_ffh,   g_ffh);
    cudaGetSymbolAddress((void**)&p_ff,    g_ff);
    cudaGetSymbolAddress((void**)&p_WvT,   g_WvT);
    cudaGetSymbolAddress((void**)&p_WoffT, g_WoffT);
    cudaGetSymbolAddress((void**)&p_WattnT,g_WattnT);
    cudaGetSymbolAddress((void**)&p_WoutT, g_WoutT);
    cudaGetSymbolAddress((void**)&p_W1T,   g_W1T);
    cudaGetSymbolAddress((void**)&p_W2T,   g_W2T);

    const int MV = NB * LIN;   // 174080
    dim3 tb(32, 8);

    // q = pre_tgt + pre_query_pos
    addq_kernel<<<(NQ * DIM + 255) / 256, 256>>>(pre_tgt, pre_qpos, p_q, NQ * DIM);

    // transpose weights to [N,K]
    transpose_kernel<<<dim3(DIM / 32, DIM / 32), tb>>>(W_value, p_WvT,   DIM, DIM);
    transpose_kernel<<<dim3(DIM / 32, DIM / 32), tb>>>(W_off,   p_WoffT, DIM, DIM);
    transpose_kernel<<<dim3(128 / 32, DIM / 32), tb>>>(W_attn,  p_WattnT,DIM, 128);
    transpose_kernel<<<dim3(DIM / 32, DIM / 32), tb>>>(W_out,   p_WoutT, DIM, DIM);
    transpose_kernel<<<dim3(DFF / 32, DIM / 32), tb>>>(W1,      p_W1T,   DIM, DFF);
    transpose_kernel<<<dim3(DIM / 32, DFF / 32), tb>>>(W2,      p_W2T,   DFF, DIM);

    // value = mask(src @ W_value + b_value)   [174080, 256]
    mma_gemm<0, true ><<<dim3(DIM / 128, MV / 128), 256>>>(
        src, p_WvT, b_value, p_value, MV, DIM, DIM, mask);

    // off = q @ W_off + b_off   [8000, 256]
    mma_gemm<0, false><<<dim3(DIM / 128, (NQ + 127) / 128), 256>>>(
        p_q, p_WoffT, b_off, p_off, NQ, DIM, DIM, nullptr);

    // attn logits = q @ W_attn + b_attn   [8000, 128]
    mma_gemm<0, false><<<dim3(1, (NQ + 127) / 128), 256>>>(
        p_q, p_WattnT, b_attn, p_attn, NQ, 128, DIM, nullptr);

    // sampling
    msda_kernel<<<NQ, 256>>>(p_value, p_off, p_attn, ref_pts, p_samp);

    // ms out = samp @ W_out + b_out
    mma_gemm<0, false><<<dim3(DIM / 128, (NQ + 127) / 128), 256>>>(
        p_samp, p_WoutT, b_out, p_ms, NQ, DIM, DIM, nullptr);

    // tgt = LN(pre_tgt + ms)
    ln_kernel<<<NQ, 256>>>(pre_tgt, p_ms, g1, be1, p_tgt);

    // ffh = relu(tgt @ W1 + b1)   [8000, 512]
    mma_gemm<1, false><<<dim3(DFF / 128, (NQ + 127) / 128), 256>>>(
        p_tgt, p_W1T, b1, p_ffh, NQ, DFF, DIM, nullptr);

    // ff = ffh @ W2 + b2   [8000, 256]
    mma_gemm<0, false><<<dim3(DIM / 128, (NQ + 127) / 128), 256>>>(
        p_ffh, p_W2T, b2, p_ff, NQ, DIM, DFF, nullptr);

    // out = LN(tgt + ff)
    ln_kernel<<<NQ, 256>>>(p_tgt, p_ff, g3, be3, (float*)d_out);
}

// round 4
// speedup vs baseline: 2.5045x; 1.0523x over previous
#include <cuda_runtime.h>
#include <cuda_bf16.h>
#include <cstdint>

// ---------------- Problem constants ----------------
#define NB   8
#define LQ   1000
#define NQ   (NB*LQ)
#define DIM  256
#define HEADS 8
#define HD   32
#define LIN  21760
#define DFF  512
#define NOA  384    // concat off(256) + attn(128)

__device__ __constant__ int c_H[4]  = {128, 64, 32, 16};
__device__ __constant__ int c_W[4]  = {128, 64, 32, 16};
__device__ __constant__ int c_S[4]  = {0, 16384, 20480, 21504};

// ---------------- Scratch ----------------
__device__ __nv_bfloat16 g_value[(size_t)LIN * NB * DIM];   // 89 MB (bf16)
__device__ float g_q    [(size_t)NQ * DIM];
__device__ float g_oa   [(size_t)NQ * NOA];                 // off(0:256) | attn logits(256:384)
__device__ float g_samp [(size_t)NQ * DIM];
__device__ float g_ms   [(size_t)NQ * DIM];
__device__ float g_tgt  [(size_t)NQ * DIM];
__device__ float g_ffh  [(size_t)NQ * DFF];
__device__ float g_ff   [(size_t)NQ * DIM];
// transposed weights [N, K]
__device__ float g_WvT  [DIM * DIM];
__device__ float g_WoaT [NOA * DIM];
__device__ float g_boa  [NOA];
__device__ float g_WoutT[DIM * DIM];
__device__ float g_W1T  [DFF * DIM];
__device__ float g_W2T  [DIM * DFF];

// ---------------- tf32 helpers ----------------
__device__ __forceinline__ float tf32r(float x) {
    uint32_t u;
    asm("cvt.rna.tf32.f32 %0, %1;" : "=r"(u) : "f"(x));
    return __uint_as_float(u);
}
__device__ __forceinline__ void mma_tf32(float* d, const uint32_t* a, const uint32_t* b) {
    asm volatile(
        "mma.sync.aligned.m16n8k8.row.col.f32.tf32.tf32.f32 "
        "{%0,%1,%2,%3}, {%4,%5,%6,%7}, {%8,%9}, {%0,%1,%2,%3};"
        : "+f"(d[0]), "+f"(d[1]), "+f"(d[2]), "+f"(d[3])
        : "r"(a[0]), "r"(a[1]), "r"(a[2]), "r"(a[3]), "r"(b[0]), "r"(b[1]));
}

#define SMS 20

// ---------------- tf32 mma GEMM: C[M,N] = A[M,K] @ Bt[N,K]^T + bias ----------------
// OUT: 0 = fp32 out, 1 = bf16 out. ACT: 1 = relu.
template<int ACT, bool MASK, int OUT>
__global__ void __launch_bounds__(256, 2) mma_gemm(
    const float* __restrict__ A, const float* __restrict__ Bt,
    const float* __restrict__ bias, void* __restrict__ Cv,
    int M, int N, int K, const unsigned char* __restrict__ rowmask)
{
    __shared__ float As[2][128 * SMS];
    __shared__ float Bs[2][128 * SMS];

    const int tid  = threadIdx.x;
    const int lane = tid & 31;
    const int wid  = tid >> 5;
    const int wr   = wid & 3;
    const int wc   = wid >> 2;
    const int gid  = lane >> 2;
    const int tig  = lane & 3;
    const int brow = blockIdx.y * 128;
    const int bcol = blockIdx.x * 128;

    const int r_st = tid >> 2;
    const int k_st = (tid & 3) * 4;

    float acc[2][8][4];
    #pragma unroll
    for (int i = 0; i < 2; i++)
        #pragma unroll
        for (int j = 0; j < 8; j++)
            #pragma unroll
            for (int l = 0; l < 4; l++) acc[i][j][l] = 0.f;

    const int KT = K >> 4;
    float4 ra[2], rb[2];

    #pragma unroll
    for (int i = 0; i < 2; i++) {
        int r = r_st + i * 64;
        int garow = brow + r; if (garow >= M) garow = M - 1;
        ra[i] = *reinterpret_cast<const float4*>(A  + (size_t)garow * K + k_st);
        rb[i] = *reinterpret_cast<const float4*>(Bt + (size_t)(bcol + r) * K + k_st);
    }
    #pragma unroll
    for (int i = 0; i < 2; i++) {
        int r = r_st + i * 64;
        float4 av = make_float4(tf32r(ra[i].x), tf32r(ra[i].y), tf32r(ra[i].z), tf32r(ra[i].w));
        float4 bv = make_float4(tf32r(rb[i].x), tf32r(rb[i].y), tf32r(rb[i].z), tf32r(rb[i].w));
        *reinterpret_cast<float4*>(&As[0][r * SMS + k_st]) = av;
        *reinterpret_cast<float4*>(&Bs[0][r * SMS + k_st]) = bv;
    }
    __syncthreads();

    for (int kt = 0; kt < KT; kt++) {
        const int buf = kt & 1;
        if (kt + 1 < KT) {
            const int kc = (kt + 1) * 16;
            #pragma unroll
            for (int i = 0; i < 2; i++) {
                int r = r_st + i * 64;
                int garow = brow + r; if (garow >= M) garow = M - 1;
                ra[i] = *reinterpret_cast<const float4*>(A  + (size_t)garow * K + kc + k_st);
                rb[i] = *reinterpret_cast<const float4*>(Bt + (size_t)(bcol + r) * K + kc + k_st);
            }
        }

        const float* as = As[buf];
        const float* bs = Bs[buf];
        #pragma unroll
        for (int ks = 0; ks < 2; ks++) {
            const int k0 = ks * 8;
            uint32_t af[2][4];
            #pragma unroll
            for (int mt = 0; mt < 2; mt++) {
                const int mb = wr * 32 + mt * 16;
                af[mt][0] = __float_as_uint(as[(mb + gid    ) * SMS + k0 + tig    ]);
                af[mt][1] = __float_as_uint(as[(mb + gid + 8) * SMS + k0 + tig    ]);
                af[mt][2] = __float_as_uint(as[(mb + gid    ) * SMS + k0 + tig + 4]);
                af[mt][3] = __float_as_uint(as[(mb + gid + 8) * SMS + k0 + tig + 4]);
            }
            #pragma unroll
            for (int nt = 0; nt < 8; nt++) {
                const int nb = wc * 64 + nt * 8 + gid;
                uint32_t bf[2];
                bf[0] = __float_as_uint(bs[nb * SMS + k0 + tig    ]);
                bf[1] = __float_as_uint(bs[nb * SMS + k0 + tig + 4]);
                mma_tf32(acc[0][nt], af[0], bf);
                mma_tf32(acc[1][nt], af[1], bf);
            }
        }

        if (kt + 1 < KT) {
            const int nb2 = (kt + 1) & 1;
            #pragma unroll
            for (int i = 0; i < 2; i++) {
                int r = r_st + i * 64;
                float4 av = make_float4(tf32r(ra[i].x), tf32r(ra[i].y), tf32r(ra[i].z), tf32r(ra[i].w));
                float4 bv = make_float4(tf32r(rb[i].x), tf32r(rb[i].y), tf32r(rb[i].z), tf32r(rb[i].w));
                *reinterpret_cast<float4*>(&As[nb2][r * SMS + k_st]) = av;
                *reinterpret_cast<float4*>(&Bs[nb2][r * SMS + k_st]) = bv;
            }
            __syncthreads();
        }
    }

    float* Cf = (float*)Cv;
    __nv_bfloat16* Cb = (__nv_bfloat16*)Cv;

    #pragma unroll
    for (int mt = 0; mt < 2; mt++) {
        const int r0 = brow + wr * 32 + mt * 16 + gid;
        const int r1 = r0 + 8;
        const bool v0 = r0 < M, v1 = r1 < M;
        bool z0 = false, z1 = false;
        if (MASK) {
            if (v0) z0 = (rowmask[r0] != 0);
            if (v1) z1 = (rowmask[r1] != 0);
        }
        #pragma unroll
        for (int nt = 0; nt < 8; nt++) {
            const int col = bcol + wc * 64 + nt * 8 + 2 * tig;
            const float b0 = bias[col], b1 = bias[col + 1];
            float2 u, v;
            u.x = acc[mt][nt][0] + b0; u.y = acc[mt][nt][1] + b1;
            v.x = acc[mt][nt][2] + b0; v.y = acc[mt][nt][3] + b1;
            if (ACT == 1) {
                u.x = fmaxf(u.x, 0.f); u.y = fmaxf(u.y, 0.f);
                v.x = fmaxf(v.x, 0.f); v.y = fmaxf(v.y, 0.f);
            }
            if (MASK) {
                if (z0) { u.x = 0.f; u.y = 0.f; }
                if (z1) { v.x = 0.f; v.y = 0.f; }
            }
            if (OUT == 0) {
                if (v0) *reinterpret_cast<float2*>(Cf + (size_t)r0 * N + col) = u;
                if (v1) *reinterpret_cast<float2*>(Cf + (size_t)r1 * N + col) = v;
            } else {
                if (v0) *reinterpret_cast<__nv_bfloat162*>(Cb + (size_t)r0 * N + col) =
                            __floats2bfloat162_rn(u.x, u.y);
                if (v1) *reinterpret_cast<__nv_bfloat162*>(Cb + (size_t)r1 * N + col) =
                            __floats2bfloat162_rn(v.x, v.y);
            }
        }
    }
}

// ---------------- batched weight prep A: transposes Wv, Wout, W1, W2 ----------------
__global__ void wprepA_kernel(const float* __restrict__ Wv,  float* __restrict__ WvT,
                              const float* __restrict__ Wo,  float* __restrict__ WoT,
                              const float* __restrict__ W1,  float* __restrict__ W1T,
                              const float* __restrict__ W2,  float* __restrict__ W2T)
{
    __shared__ float t[32][33];
    const float* W; float* Wt; int K, N;
    switch (blockIdx.z) {
        case 0: W = Wv; Wt = WvT; K = DIM; N = DIM; break;
        case 1: W = Wo; Wt = WoT; K = DIM; N = DIM; break;
        case 2: W = W1; Wt = W1T; K = DIM; N = DFF; break;
        default:W = W2; Wt = W2T; K = DFF; N = DIM; break;
    }
    const int bx = blockIdx.x * 32;
    const int by = blockIdx.y * 32;
    if (bx >= N || by >= K) return;
    const int x = threadIdx.x, y = threadIdx.y;
    #pragma unroll
    for (int i = 0; i < 32; i += 8)
        t[y + i][x] = W[(size_t)(by + y + i) * N + bx + x];
    __syncthreads();
    #pragma unroll
    for (int i = 0; i < 32; i += 8)
        Wt[(size_t)(bx + y + i) * K + by + x] = t[x][y + i];
}

// ---------------- weight prep B: WoaT = [W_off^T ; W_attn^T], boa = [b_off ; b_attn] --
__global__ void wprepB_kernel(const float* __restrict__ Woff, const float* __restrict__ boff,
                              const float* __restrict__ Watt, const float* __restrict__ batt,
                              float* __restrict__ WoaT, float* __restrict__ boa)
{
    __shared__ float t[32][33];
    const int bx = blockIdx.x * 32;   // n in 0..383
    const int by = blockIdx.y * 32;   // k in 0..255
    const int x = threadIdx.x, y = threadIdx.y;
    const bool isAtt = (bx >= 256);
    const float* W = isAtt ? Watt : Woff;
    const int    nN = isAtt ? 128 : 256;
    const int    nb = isAtt ? bx - 256 : bx;
    #pragma unroll
    for (int i = 0; i < 32; i += 8)
        t[y + i][x] = W[(size_t)(by + y + i) * nN + nb + x];
    __syncthreads();
    #pragma unroll
    for (int i = 0; i < 32; i += 8)
        WoaT[(size_t)(bx + y + i) * DIM + by + x] = t[x][y + i];
    if (blockIdx.y == 0 && y == 0) {
        int n = bx + x;
        boa[n] = (n < 256) ? boff[n] : batt[n - 256];
    }
}

// ---------------- elementwise q = a + b ----------------
__global__ void addq_kernel(const float* __restrict__ a, const float* __restrict__ b,
                            float* __restrict__ o, int n)
{
    int i = blockIdx.x * blockDim.x + threadIdx.x;
    if (i < n) o[i] = a[i] + b[i];
}

// ---------------- MS-deform sampling (softmax fused), bf16 value ----------
__global__ void msda_kernel(const __nv_bfloat16* __restrict__ value,
                            const float* __restrict__ oa,     // [NQ, 384]
                            const float* __restrict__ refpts,
                            float* __restrict__ samp)
{
    const int nq   = blockIdx.x;
    const int h    = threadIdx.x >> 5;
    const int lane = threadIdx.x & 31;
    const int n    = nq / LQ;

    float logit = (lane < 16) ? oa[(size_t)nq * NOA + 256 + h * 16 + lane] : -1e30f;
    float m = logit;
    #pragma unroll
    for (int o = 8; o > 0; o >>= 1) m = fmaxf(m, __shfl_xor_sync(0xffffffffu, m, o, 16));
    float e = (lane < 16) ? __expf(logit - m) : 0.f;
    float s = e;
    #pragma unroll
    for (int o = 8; o > 0; o >>= 1) s += __shfl_xor_sync(0xffffffffu, s, o, 16);
    float w = e / s;

    float offv = oa[(size_t)nq * NOA + h * 32 + lane];
    float refv = (lane < 8) ? refpts[(size_t)nq * 8 + lane] : 0.f;

    const __nv_bfloat16* vbase = value + ((size_t)n * LIN * HEADS + h) * HD + lane;

    float acc = 0.f;
    #pragma unroll
    for (int i = 0; i < 16; i++) {
        const int l = i >> 2;
        const int p = i & 3;
        const float wi   = __shfl_sync(0xffffffffu, w,    i);
        const float offx = __shfl_sync(0xffffffffu, offv, l * 8 + p * 2 + 0);
        const float offy = __shfl_sync(0xffffffffu, offv, l * 8 + p * 2 + 1);
        const float refx = __shfl_sync(0xffffffffu, refv, l * 2 + 0);
        const float refy = __shfl_sync(0xffffffffu, refv, l * 2 + 1);

        const int Hl = c_H[l], Wl = c_W[l], st = c_S[l];
        const float x = refx * (float)Wl + offx - 0.5f;
        const float y = refy * (float)Hl + offy - 0.5f;
        const float x0f = floorf(x), y0f = floorf(y);
        const float fx = x - x0f, fy = y - y0f;
        const int x0 = (int)x0f, y0 = (int)y0f;
        const int x1 = x0 + 1,   y1 = y0 + 1;

        const bool vx0 = (x0 >= 0) & (x0 < Wl);
        const bool vx1 = (x1 >= 0) & (x1 < Wl);
        const bool vy0 = (y0 >= 0) & (y0 < Hl);
        const bool vy1 = (y1 >= 0) & (y1 < Hl);

        float sv = 0.f;
        if (vy0) {
            const __nv_bfloat16* rowp = vbase + (size_t)(st + y0 * Wl) * HEADS * HD;
            if (vx0) sv += (1.f - fx) * (1.f - fy) * __bfloat162float(rowp[(size_t)x0 * HEADS * HD]);
            if (vx1) sv += fx * (1.f - fy)         * __bfloat162float(rowp[(size_t)x1 * HEADS * HD]);
        }
        if (vy1) {
            const __nv_bfloat16* rowp = vbase + (size_t)(st + y1 * Wl) * HEADS * HD;
            if (vx0) sv += (1.f - fx) * fy * __bfloat162float(rowp[(size_t)x0 * HEADS * HD]);
            if (vx1) sv += fx * fy         * __bfloat162float(rowp[(size_t)x1 * HEADS * HD]);
        }
        acc += wi * sv;
    }
    samp[(size_t)nq * 256 + h * 32 + lane] = acc;
}

// ---------------- fused residual + LayerNorm (warp per row) ----------------
__global__ void ln_kernel(const float* __restrict__ a, const float* __restrict__ b,
                          const float* __restrict__ g, const float* __restrict__ be,
                          float* __restrict__ out)
{
    const int row  = blockIdx.x * 8 + (threadIdx.x >> 5);
    const int lane = threadIdx.x & 31;
    const size_t base = (size_t)row * 256;

    float4 a0 = *reinterpret_cast<const float4*>(a + base + lane * 4);
    float4 a1 = *reinterpret_cast<const float4*>(a + base + 128 + lane * 4);
    float4 b0 = *reinterpret_cast<const float4*>(b + base + lane * 4);
    float4 b1 = *reinterpret_cast<const float4*>(b + base + 128 + lane * 4);
    float x0 = a0.x + b0.x, x1 = a0.y + b0.y, x2 = a0.z + b0.z, x3 = a0.w + b0.w;
    float x4 = a1.x + b1.x, x5 = a1.y + b1.y, x6 = a1.z + b1.z, x7 = a1.w + b1.w;

    float s  = x0 + x1 + x2 + x3 + x4 + x5 + x6 + x7;
    float s2 = x0*x0 + x1*x1 + x2*x2 + x3*x3 + x4*x4 + x5*x5 + x6*x6 + x7*x7;
    #pragma unroll
    for (int o = 16; o > 0; o >>= 1) {
        s  += __shfl_xor_sync(0xffffffffu, s,  o);
        s2 += __shfl_xor_sync(0xffffffffu, s2, o);
    }
    const float mean = s * (1.f / 256.f);
    const float rstd = rsqrtf(s2 * (1.f / 256.f) - mean * mean + 1e-5f);

    float4 g0 = *reinterpret_cast<const float4*>(g + lane * 4);
    float4 g1 = *reinterpret_cast<const float4*>(g + 128 + lane * 4);
    float4 e0 = *reinterpret_cast<const float4*>(be + lane * 4);
    float4 e1 = *reinterpret_cast<const float4*>(be + 128 + lane * 4);

    float4 o0, o1;
    o0.x = (x0 - mean) * rstd * g0.x + e0.x;
    o0.y = (x1 - mean) * rstd * g0.y + e0.y;
    o0.z = (x2 - mean) * rstd * g0.z + e0.z;
    o0.w = (x3 - mean) * rstd * g0.w + e0.w;
    o1.x = (x4 - mean) * rstd * g1.x + e1.x;
    o1.y = (x5 - mean) * rstd * g1.y + e1.y;
    o1.z = (x6 - mean) * rstd * g1.z + e1.z;
    o1.w = (x7 - mean) * rstd * g1.w + e1.w;
    *reinterpret_cast<float4*>(out + base + lane * 4)       = o0;
    *reinterpret_cast<float4*>(out + base + 128 + lane * 4) = o1;
}

// ---------------- launch ----------------
extern "C" void kernel_launch(void* const* d_in, const int* in_sizes, int n_in,
                              void* d_out, int out_size)
{
    const float* pre_tgt  = (const float*)d_in[0];
    const float* pre_qpos = (const float*)d_in[1];
    const float* src      = (const float*)d_in[2];
    const float* ref_pts  = (const float*)d_in[3];
    const unsigned char* mask = (const unsigned char*)d_in[4];
    const float* W_value = (const float*)d_in[7];
    const float* b_value = (const float*)d_in[8];
    const float* W_off   = (const float*)d_in[9];
    const float* b_off   = (const float*)d_in[10];
    const float* W_attn  = (const float*)d_in[11];
    const float* b_attn  = (const float*)d_in[12];
    const float* W_out   = (const float*)d_in[13];
    const float* b_out   = (const float*)d_in[14];
    const float* g1      = (const float*)d_in[15];
    const float* be1     = (const float*)d_in[16];
    const float* W1      = (const float*)d_in[17];
    const float* b1      = (const float*)d_in[18];
    const float* W2      = (const float*)d_in[19];
    const float* b2      = (const float*)d_in[20];
    const float* g3      = (const float*)d_in[21];
    const float* be3     = (const float*)d_in[22];

    __nv_bfloat16* p_value;
    float *p_q, *p_oa, *p_samp, *p_ms, *p_tgt, *p_ffh, *p_ff;
    float *p_WvT, *p_WoaT, *p_boa, *p_WoutT, *p_W1T, *p_W2T;
    cudaGetSymbolAddress((void**)&p_value, g_value);
    cudaGetSymbolAddress((void**)&p_q,     g_q);
    cudaGetSymbolAddress((void**)&p_oa,    g_oa);
    cudaGetSymbolAddress((void**)&p_samp,  g_samp);
    cudaGetSymbolAddress((void**)&p_ms,    g_ms);
    cudaGetSymbolAddress((void**)&p_tgt,   g_tgt);
    cudaGetSymbolAddress((void**)&p_ffh,   g_ffh);
    cudaGetSymbolAddress((void**)&p_ff,    g_ff);
    cudaGetSymbolAddress((void**)&p_WvT,   g_WvT);
    cudaGetSymbolAddress((void**)&p_WoaT,  g_WoaT);
    cudaGetSymbolAddress((void**)&p_boa,   g_boa);
    cudaGetSymbolAddress((void**)&p_WoutT, g_WoutT);
    cudaGetSymbolAddress((void**)&p_W1T,   g_W1T);
    cudaGetSymbolAddress((void**)&p_W2T,   g_W2T);

    const int MV = NB * LIN;   // 174080
    dim3 tb(32, 8);

    // 1. q = pre_tgt + pre_query_pos
    addq_kernel<<<(NQ * DIM + 255) / 256, 256>>>(pre_tgt, pre_qpos, p_q, NQ * DIM);
    // 2. weight prep A (Wv, Wout, W1, W2 transposes)
    wprepA_kernel<<<dim3(16, 16, 4), tb>>>(W_value, p_WvT, W_out, p_WoutT, W1, p_W1T, W2, p_W2T);
    // 3. weight prep B (concat off+attn)
    wprepB_kernel<<<dim3(12, 8), tb>>>(W_off, b_off, W_attn, b_attn, p_WoaT, p_boa);
    // 4. value = mask(src @ Wv + bv) -> bf16   [174080, 256]
    mma_gemm<0, true, 1><<<dim3(DIM / 128, MV / 128), 256>>>(
        src, p_WvT, b_value, p_value, MV, DIM, DIM, mask);
    // 5. oa = q @ [Woff|Wattn] + [boff|battn]   [8000, 384]
    mma_gemm<0, false, 0><<<dim3(NOA / 128, (NQ + 127) / 128), 256>>>(
        p_q, p_WoaT, p_boa, p_oa, NQ, NOA, DIM, nullptr);
    // 6. sampling  (launch #6 -> ncu -s 5 profiles this)
    msda_kernel<<<NQ, 256>>>(p_value, p_oa, ref_pts, p_samp);
    // 7. ms = samp @ Wout + bout
    mma_gemm<0, false, 0><<<dim3(DIM / 128, (NQ + 127) / 128), 256>>>(
        p_samp, p_WoutT, b_out, p_ms, NQ, DIM, DIM, nullptr);
    // 8. tgt = LN(pre_tgt + ms)
    ln_kernel<<<NQ / 8, 256>>>(pre_tgt, p_ms, g1, be1, p_tgt);
    // 9. ffh = relu(tgt @ W1 + b1)
    mma_gemm<1, false, 0><<<dim3(DFF / 128, (NQ + 127) / 128), 256>>>(
        p_tgt, p_W1T, b1, p_ffh, NQ, DFF, DIM, nullptr);
    // 10. ff = ffh @ W2 + b2
    mma_gemm<0, false, 0><<<dim3(DIM / 128, (NQ + 127) / 128), 256>>>(
        p_ffh, p_W2T, b2, p_ff, NQ, DIM, DFF, nullptr);
    // 11. out = LN(tgt + ff)
    ln_kernel<<<NQ / 8, 256>>>(p_tgt, p_ff, g3, be3, (float*)d_out);
}

// round 6
// speedup vs baseline: 2.7613x; 1.1025x over previous
#include <cuda_runtime.h>
#include <cuda_bf16.h>
#include <cstdint>

// ---------------- Problem constants ----------------
#define NB   8
#define LQ   1000
#define NQ   (NB*LQ)
#define DIM  256
#define HEADS 8
#define HD   32
#define LIN  21760
#define DFF  512
#define NOA  384    // concat off(256) + attn(128)

__device__ __constant__ int c_H[4]  = {128, 64, 32, 16};
__device__ __constant__ int c_W[4]  = {128, 64, 32, 16};
__device__ __constant__ int c_S[4]  = {0, 16384, 20480, 21504};

// ---------------- Scratch ----------------
__device__ __nv_bfloat16 g_value[(size_t)LIN * NB * DIM];   // 89 MB (bf16)
__device__ float g_q    [(size_t)NQ * DIM];
__device__ float g_oa   [(size_t)NQ * NOA];
__device__ float g_samp [(size_t)NQ * DIM];
__device__ float g_ms   [(size_t)NQ * DIM];
__device__ float g_tgt  [(size_t)NQ * DIM];
__device__ float g_ffh  [(size_t)NQ * DFF];
__device__ float g_ff   [(size_t)NQ * DIM];
__device__ float g_WvT  [DIM * DIM];
__device__ float g_WoaT [NOA * DIM];
__device__ float g_boa  [NOA];
__device__ float g_WoutT[DIM * DIM];
__device__ float g_W1T  [DFF * DIM];
__device__ float g_W2T  [DIM * DFF];

// ---------------- helpers ----------------
__device__ __forceinline__ float tf32r(float x) {
    uint32_t u;
    asm("cvt.rna.tf32.f32 %0, %1;" : "=r"(u) : "f"(x));
    return __uint_as_float(u);
}
__device__ __forceinline__ void mma_tf32(float* d, const uint32_t* a, const uint32_t* b) {
    asm volatile(
        "mma.sync.aligned.m16n8k8.row.col.f32.tf32.tf32.f32 "
        "{%0,%1,%2,%3}, {%4,%5,%6,%7}, {%8,%9}, {%0,%1,%2,%3};"
        : "+f"(d[0]), "+f"(d[1]), "+f"(d[2]), "+f"(d[3])
        : "r"(a[0]), "r"(a[1]), "r"(a[2]), "r"(a[3]), "r"(b[0]), "r"(b[1]));
}
__device__ __forceinline__ void mma_bf16(float* d, const uint32_t* a, const uint32_t* b) {
    asm volatile(
        "mma.sync.aligned.m16n8k16.row.col.f32.bf16.bf16.f32 "
        "{%0,%1,%2,%3}, {%4,%5,%6,%7}, {%8,%9}, {%0,%1,%2,%3};"
        : "+f"(d[0]), "+f"(d[1]), "+f"(d[2]), "+f"(d[3])
        : "r"(a[0]), "r"(a[1]), "r"(a[2]), "r"(a[3]), "r"(b[0]), "r"(b[1]));
}
__device__ __forceinline__ void ldmx4(uint32_t* r, uint32_t addr) {
    asm volatile("ldmatrix.sync.aligned.m8n8.x4.shared.b16 {%0,%1,%2,%3}, [%4];"
        : "=r"(r[0]), "=r"(r[1]), "=r"(r[2]), "=r"(r[3]) : "r"(addr));
}
__device__ __forceinline__ uint32_t packbf(float lo, float hi) {
    __nv_bfloat162 h = __floats2bfloat162_rn(lo, hi);
    return *reinterpret_cast<uint32_t*>(&h);
}
__device__ __forceinline__ uint4 pack8bf(float4 a, float4 b) {
    uint4 u;
    u.x = packbf(a.x, a.y);
    u.y = packbf(a.z, a.w);
    u.z = packbf(b.x, b.y);
    u.w = packbf(b.z, b.w);
    return u;
}

// ================= bf16 mma GEMM (big GEMMs): C = A@Bt^T + bias =================
// BM=BN=128, BK=16. grid(N/128, ceil(M/128)), 256 threads. K mult of 16, N mult of 128.
#define SMSB 24   // smem stride in halves (48B) — conflict-free ldmatrix phases
template<int ACT, bool MASK, int OUT>
__global__ void __launch_bounds__(256, 2) mma_gemm_bf16(
    const float* __restrict__ A, const float* __restrict__ Bt,
    const float* __restrict__ bias, void* __restrict__ Cv,
    int M, int N, int K, const unsigned char* __restrict__ rowmask)
{
    __shared__ __nv_bfloat16 As[2][128 * SMSB];
    __shared__ __nv_bfloat16 Bs[2][128 * SMSB];

    const int tid  = threadIdx.x;
    const int lane = tid & 31;
    const int wid  = tid >> 5;
    const int wr   = wid & 3;
    const int wc   = wid >> 2;
    const int gid  = lane >> 2;
    const int tig  = lane & 3;
    const int brow = blockIdx.y * 128;
    const int bcol = blockIdx.x * 128;

    const int r_st = tid >> 1;          // staging row 0..127
    const int k_st = (tid & 1) * 8;     // 0 or 8 (floats)

    float acc[2][8][4];
    #pragma unroll
    for (int i = 0; i < 2; i++)
        #pragma unroll
        for (int j = 0; j < 8; j++)
            #pragma unroll
            for (int l = 0; l < 4; l++) acc[i][j][l] = 0.f;

    const uint32_t asb = (uint32_t)__cvta_generic_to_shared(&As[0][0]);
    const uint32_t bsb = (uint32_t)__cvta_generic_to_shared(&Bs[0][0]);
    const uint32_t bufoff = 128 * SMSB * 2;   // bytes between buffers
    const int a_off = ((lane & 7) + ((lane >> 3) & 1) * 8) * SMSB + (lane >> 4) * 8;
    const int b_off = ((lane & 7) + ((lane >> 4) & 1) * 8) * SMSB + ((lane >> 3) & 1) * 8;

    int garow = brow + r_st; if (garow >= M) garow = M - 1;
    const float* Arow = A  + (size_t)garow * K + k_st;
    const float* Brow = Bt + (size_t)(bcol + r_st) * K + k_st;

    const int KT = K >> 4;
    float4 ra0, ra1, rb0, rb1;

    ra0 = *reinterpret_cast<const float4*>(Arow);
    ra1 = *reinterpret_cast<const float4*>(Arow + 4);
    rb0 = *reinterpret_cast<const float4*>(Brow);
    rb1 = *reinterpret_cast<const float4*>(Brow + 4);
    *reinterpret_cast<uint4*>(&As[0][r_st * SMSB + k_st]) = pack8bf(ra0, ra1);
    *reinterpret_cast<uint4*>(&Bs[0][r_st * SMSB + k_st]) = pack8bf(rb0, rb1);
    __syncthreads();

    for (int kt = 0; kt < KT; kt++) {
        const int buf = kt & 1;
        if (kt + 1 < KT) {
            const int kc = (kt + 1) * 16;
            ra0 = *reinterpret_cast<const float4*>(Arow + kc);
            ra1 = *reinterpret_cast<const float4*>(Arow + kc + 4);
            rb0 = *reinterpret_cast<const float4*>(Brow + kc);
            rb1 = *reinterpret_cast<const float4*>(Brow + kc + 4);
        }

        // fragments via ldmatrix
        uint32_t af[2][4], bf[4][4];
        const uint32_t ab = asb + buf * bufoff;
        const uint32_t bb = bsb + buf * bufoff;
        #pragma unroll
        for (int mt = 0; mt < 2; mt++)
            ldmx4(af[mt], ab + (uint32_t)(((wr * 32 + mt * 16) * SMSB + a_off) * 2));
        #pragma unroll
        for (int p = 0; p < 4; p++)
            ldmx4(bf[p], bb + (uint32_t)(((wc * 64 + p * 16) * SMSB + b_off) * 2));

        #pragma unroll
        for (int nt = 0; nt < 8; nt++) {
            const uint32_t* bfr = &bf[nt >> 1][(nt & 1) * 2];
            mma_bf16(acc[0][nt], af[0], bfr);
            mma_bf16(acc[1][nt], af[1], bfr);
        }

        if (kt + 1 < KT) {
            __syncthreads();   // all warps done with buf^1 before overwrite
            const int nb2 = (kt + 1) & 1;
            *reinterpret_cast<uint4*>(&As[nb2][r_st * SMSB + k_st]) = pack8bf(ra0, ra1);
            *reinterpret_cast<uint4*>(&Bs[nb2][r_st * SMSB + k_st]) = pack8bf(rb0, rb1);
            __syncthreads();
        }
    }

    float* Cf = (float*)Cv;
    __nv_bfloat16* Cb = (__nv_bfloat16*)Cv;

    #pragma unroll
    for (int mt = 0; mt < 2; mt++) {
        const int r0 = brow + wr * 32 + mt * 16 + gid;
        const int r1 = r0 + 8;
        const bool v0 = r0 < M, v1 = r1 < M;
        bool z0 = false, z1 = false;
        if (MASK) {
            if (v0) z0 = (rowmask[r0] != 0);
            if (v1) z1 = (rowmask[r1] != 0);
        }
        #pragma unroll
        for (int nt = 0; nt < 8; nt++) {
            const int col = bcol + wc * 64 + nt * 8 + 2 * tig;
            const float b0 = bias[col], b1 = bias[col + 1];
            float2 u, v;
            u.x = acc[mt][nt][0] + b0; u.y = acc[mt][nt][1] + b1;
            v.x = acc[mt][nt][2] + b0; v.y = acc[mt][nt][3] + b1;
            if (ACT == 1) {
                u.x = fmaxf(u.x, 0.f); u.y = fmaxf(u.y, 0.f);
                v.x = fmaxf(v.x, 0.f); v.y = fmaxf(v.y, 0.f);
            }
            if (MASK) {
                if (z0) { u.x = 0.f; u.y = 0.f; }
                if (z1) { v.x = 0.f; v.y = 0.f; }
            }
            if (OUT == 0) {
                if (v0) *reinterpret_cast<float2*>(Cf + (size_t)r0 * N + col) = u;
                if (v1) *reinterpret_cast<float2*>(Cf + (size_t)r1 * N + col) = v;
            } else {
                __nv_bfloat162 hu = __floats2bfloat162_rn(u.x, u.y);
                __nv_bfloat162 hv = __floats2bfloat162_rn(v.x, v.y);
                if (v0) *reinterpret_cast<__nv_bfloat162*>(Cb + (size_t)r0 * N + col) = hu;
                if (v1) *reinterpret_cast<__nv_bfloat162*>(Cb + (size_t)r1 * N + col) = hv;
            }
        }
    }
}

// ================= tf32 mma GEMM (precision-sensitive oa GEMM) =================
#define SMS 20
template<int ACT>
__global__ void __launch_bounds__(256, 2) mma_gemm_tf32(
    const float* __restrict__ A, const float* __restrict__ Bt,
    const float* __restrict__ bias, float* __restrict__ C,
    int M, int N, int K)
{
    __shared__ float As[2][128 * SMS];
    __shared__ float Bs[2][128 * SMS];

    const int tid  = threadIdx.x;
    const int lane = tid & 31;
    const int wid  = tid >> 5;
    const int wr   = wid & 3;
    const int wc   = wid >> 2;
    const int gid  = lane >> 2;
    const int tig  = lane & 3;
    const int brow = blockIdx.y * 128;
    const int bcol = blockIdx.x * 128;

    const int r_st = tid >> 2;
    const int k_st = (tid & 3) * 4;

    float acc[2][8][4];
    #pragma unroll
    for (int i = 0; i < 2; i++)
        #pragma unroll
        for (int j = 0; j < 8; j++)
            #pragma unroll
            for (int l = 0; l < 4; l++) acc[i][j][l] = 0.f;

    const int KT = K >> 4;
    float4 ra[2], rb[2];

    #pragma unroll
    for (int i = 0; i < 2; i++) {
        int r = r_st + i * 64;
        int garow = brow + r; if (garow >= M) garow = M - 1;
        ra[i] = *reinterpret_cast<const float4*>(A  + (size_t)garow * K + k_st);
        rb[i] = *reinterpret_cast<const float4*>(Bt + (size_t)(bcol + r) * K + k_st);
    }
    #pragma unroll
    for (int i = 0; i < 2; i++) {
        int r = r_st + i * 64;
        float4 av = make_float4(tf32r(ra[i].x), tf32r(ra[i].y), tf32r(ra[i].z), tf32r(ra[i].w));
        float4 bv = make_float4(tf32r(rb[i].x), tf32r(rb[i].y), tf32r(rb[i].z), tf32r(rb[i].w));
        *reinterpret_cast<float4*>(&As[0][r * SMS + k_st]) = av;
        *reinterpret_cast<float4*>(&Bs[0][r * SMS + k_st]) = bv;
    }
    __syncthreads();

    for (int kt = 0; kt < KT; kt++) {
        const int buf = kt & 1;
        if (kt + 1 < KT) {
            const int kc = (kt + 1) * 16;
            #pragma unroll
            for (int i = 0; i < 2; i++) {
                int r = r_st + i * 64;
                int garow = brow + r; if (garow >= M) garow = M - 1;
                ra[i] = *reinterpret_cast<const float4*>(A  + (size_t)garow * K + kc + k_st);
                rb[i] = *reinterpret_cast<const float4*>(Bt + (size_t)(bcol + r) * K + kc + k_st);
            }
        }
        const float* as = As[buf];
        const float* bs = Bs[buf];
        #pragma unroll
        for (int ks = 0; ks < 2; ks++) {
            const int k0 = ks * 8;
            uint32_t af[2][4];
            #pragma unroll
            for (int mt = 0; mt < 2; mt++) {
                const int mb = wr * 32 + mt * 16;
                af[mt][0] = __float_as_uint(as[(mb + gid    ) * SMS + k0 + tig    ]);
                af[mt][1] = __float_as_uint(as[(mb + gid + 8) * SMS + k0 + tig    ]);
                af[mt][2] = __float_as_uint(as[(mb + gid    ) * SMS + k0 + tig + 4]);
                af[mt][3] = __float_as_uint(as[(mb + gid + 8) * SMS + k0 + tig + 4]);
            }
            #pragma unroll
            for (int nt = 0; nt < 8; nt++) {
                const int nb = wc * 64 + nt * 8 + gid;
                uint32_t bfr[2];
                bfr[0] = __float_as_uint(bs[nb * SMS + k0 + tig    ]);
                bfr[1] = __float_as_uint(bs[nb * SMS + k0 + tig + 4]);
                mma_tf32(acc[0][nt], af[0], bfr);
                mma_tf32(acc[1][nt], af[1], bfr);
            }
        }
        if (kt + 1 < KT) {
            const int nb2 = (kt + 1) & 1;
            #pragma unroll
            for (int i = 0; i < 2; i++) {
                int r = r_st + i * 64;
                float4 av = make_float4(tf32r(ra[i].x), tf32r(ra[i].y), tf32r(ra[i].z), tf32r(ra[i].w));
                float4 bv = make_float4(tf32r(rb[i].x), tf32r(rb[i].y), tf32r(rb[i].z), tf32r(rb[i].w));
                *reinterpret_cast<float4*>(&As[nb2][r * SMS + k_st]) = av;
                *reinterpret_cast<float4*>(&Bs[nb2][r * SMS + k_st]) = bv;
            }
            __syncthreads();
        }
    }

    #pragma unroll
    for (int mt = 0; mt < 2; mt++) {
        const int r0 = brow + wr * 32 + mt * 16 + gid;
        const int r1 = r0 + 8;
        const bool v0 = r0 < M, v1 = r1 < M;
        #pragma unroll
        for (int nt = 0; nt < 8; nt++) {
            const int col = bcol + wc * 64 + nt * 8 + 2 * tig;
            const float b0 = bias[col], b1 = bias[col + 1];
            float2 u, v;
            u.x = acc[mt][nt][0] + b0; u.y = acc[mt][nt][1] + b1;
            v.x = acc[mt][nt][2] + b0; v.y = acc[mt][nt][3] + b1;
            if (ACT == 1) {
                u.x = fmaxf(u.x, 0.f); u.y = fmaxf(u.y, 0.f);
                v.x = fmaxf(v.x, 0.f); v.y = fmaxf(v.y, 0.f);
            }
            if (v0) *reinterpret_cast<float2*>(C + (size_t)r0 * N + col) = u;
            if (v1) *reinterpret_cast<float2*>(C + (size_t)r1 * N + col) = v;
        }
    }
}

// ---------------- batched weight prep A ----------------
__global__ void wprepA_kernel(const float* __restrict__ Wv,  float* __restrict__ WvT,
                              const float* __restrict__ Wo,  float* __restrict__ WoT,
                              const float* __restrict__ W1,  float* __restrict__ W1T,
                              const float* __restrict__ W2,  float* __restrict__ W2T)
{
    __shared__ float t[32][33];
    const float* W; float* Wt; int K, N;
    switch (blockIdx.z) {
        case 0: W = Wv; Wt = WvT; K = DIM; N = DIM; break;
        case 1: W = Wo; Wt = WoT; K = DIM; N = DIM; break;
        case 2: W = W1; Wt = W1T; K = DIM; N = DFF; break;
        default:W = W2; Wt = W2T; K = DFF; N = DIM; break;
    }
    const int bx = blockIdx.x * 32;
    const int by = blockIdx.y * 32;
    if (bx >= N || by >= K) return;
    const int x = threadIdx.x, y = threadIdx.y;
    #pragma unroll
    for (int i = 0; i < 32; i += 8)
        t[y + i][x] = W[(size_t)(by + y + i) * N + bx + x];
    __syncthreads();
    #pragma unroll
    for (int i = 0; i < 32; i += 8)
        Wt[(size_t)(bx + y + i) * K + by + x] = t[x][y + i];
}

// ---------------- weight prep B: WoaT = [W_off^T ; W_attn^T] ----------------
__global__ void wprepB_kernel(const float* __restrict__ Woff, const float* __restrict__ boff,
                              const float* __restrict__ Watt, const float* __restrict__ batt,
                              float* __restrict__ WoaT, float* __restrict__ boa)
{
    __shared__ float t[32][33];
    const int bx = blockIdx.x * 32;
    const int by = blockIdx.y * 32;
    const int x = threadIdx.x, y = threadIdx.y;
    const bool isAtt = (bx >= 256);
    const float* W = isAtt ? Watt : Woff;
    const int    nN = isAtt ? 128 : 256;
    const int    nb = isAtt ? bx - 256 : bx;
    #pragma unroll
    for (int i = 0; i < 32; i += 8)
        t[y + i][x] = W[(size_t)(by + y + i) * nN + nb + x];
    __syncthreads();
    #pragma unroll
    for (int i = 0; i < 32; i += 8)
        WoaT[(size_t)(bx + y + i) * DIM + by + x] = t[x][y + i];
    if (blockIdx.y == 0 && y == 0) {
        int n = bx + x;
        boa[n] = (n < 256) ? boff[n] : batt[n - 256];
    }
}

// ---------------- elementwise q = a + b ----------------
__global__ void addq_kernel(const float* __restrict__ a, const float* __restrict__ b,
                            float* __restrict__ o, int n)
{
    int i = blockIdx.x * blockDim.x + threadIdx.x;
    if (i < n) o[i] = a[i] + b[i];
}

// ---------------- MS-deform sampling (softmax fused), bf16 value ----------
__global__ void msda_kernel(const __nv_bfloat16* __restrict__ value,
                            const float* __restrict__ oa,
                            const float* __restrict__ refpts,
                            float* __restrict__ samp)
{
    const int nq   = blockIdx.x;
    const int h    = threadIdx.x >> 5;
    const int lane = threadIdx.x & 31;
    const int n    = nq / LQ;

    float logit = (lane < 16) ? oa[(size_t)nq * NOA + 256 + h * 16 + lane] : -1e30f;
    float m = logit;
    #pragma unroll
    for (int o = 8; o > 0; o >>= 1) m = fmaxf(m, __shfl_xor_sync(0xffffffffu, m, o, 16));
    float e = (lane < 16) ? __expf(logit - m) : 0.f;
    float s = e;
    #pragma unroll
    for (int o = 8; o > 0; o >>= 1) s += __shfl_xor_sync(0xffffffffu, s, o, 16);
    float w = e / s;

    float offv = oa[(size_t)nq * NOA + h * 32 + lane];
    float refv = (lane < 8) ? refpts[(size_t)nq * 8 + lane] : 0.f;

    const __nv_bfloat16* vbase = value + ((size_t)n * LIN * HEADS + h) * HD + lane;

    float acc = 0.f;
    #pragma unroll
    for (int i = 0; i < 16; i++) {
        const int l = i >> 2;
        const int p = i & 3;
        const float wi   = __shfl_sync(0xffffffffu, w,    i);
        const float offx = __shfl_sync(0xffffffffu, offv, l * 8 + p * 2 + 0);
        const float offy = __shfl_sync(0xffffffffu, offv, l * 8 + p * 2 + 1);
        const float refx = __shfl_sync(0xffffffffu, refv, l * 2 + 0);
        const float refy = __shfl_sync(0xffffffffu, refv, l * 2 + 1);

        const int Hl = c_H[l], Wl = c_W[l], st = c_S[l];
        const float x = refx * (float)Wl + offx - 0.5f;
        const float y = refy * (float)Hl + offy - 0.5f;
        const float x0f = floorf(x), y0f = floorf(y);
        const float fx = x - x0f, fy = y - y0f;
        const int x0 = (int)x0f, y0 = (int)y0f;
        const int x1 = x0 + 1,   y1 = y0 + 1;

        const bool vx0 = (x0 >= 0) & (x0 < Wl);
        const bool vx1 = (x1 >= 0) & (x1 < Wl);
        const bool vy0 = (y0 >= 0) & (y0 < Hl);
        const bool vy1 = (y1 >= 0) & (y1 < Hl);

        float sv = 0.f;
        if (vy0) {
            const __nv_bfloat16* rowp = vbase + (size_t)(st + y0 * Wl) * HEADS * HD;
            if (vx0) sv += (1.f - fx) * (1.f - fy) * __bfloat162float(rowp[(size_t)x0 * HEADS * HD]);
            if (vx1) sv += fx * (1.f - fy)         * __bfloat162float(rowp[(size_t)x1 * HEADS * HD]);
        }
        if (vy1) {
            const __nv_bfloat16* rowp = vbase + (size_t)(st + y1 * Wl) * HEADS * HD;
            if (vx0) sv += (1.f - fx) * fy * __bfloat162float(rowp[(size_t)x0 * HEADS * HD]);
            if (vx1) sv += fx * fy         * __bfloat162float(rowp[(size_t)x1 * HEADS * HD]);
        }
        acc += wi * sv;
    }
    samp[(size_t)nq * 256 + h * 32 + lane] = acc;
}

// ---------------- fused residual + LayerNorm (warp per row) ----------------
__global__ void ln_kernel(const float* __restrict__ a, const float* __restrict__ b,
                          const float* __restrict__ g, const float* __restrict__ be,
                          float* __restrict__ out)
{
    const int row  = blockIdx.x * 8 + (threadIdx.x >> 5);
    const int lane = threadIdx.x & 31;
    const size_t base = (size_t)row * 256;

    float4 a0 = *reinterpret_cast<const float4*>(a + base + lane * 4);
    float4 a1 = *reinterpret_cast<const float4*>(a + base + 128 + lane * 4);
    float4 b0 = *reinterpret_cast<const float4*>(b + base + lane * 4);
    float4 b1 = *reinterpret_cast<const float4*>(b + base + 128 + lane * 4);
    float x0 = a0.x + b0.x, x1 = a0.y + b0.y, x2 = a0.z + b0.z, x3 = a0.w + b0.w;
    float x4 = a1.x + b1.x, x5 = a1.y + b1.y, x6 = a1.z + b1.z, x7 = a1.w + b1.w;

    float s  = x0 + x1 + x2 + x3 + x4 + x5 + x6 + x7;
    float s2 = x0*x0 + x1*x1 + x2*x2 + x3*x3 + x4*x4 + x5*x5 + x6*x6 + x7*x7;
    #pragma unroll
    for (int o = 16; o > 0; o >>= 1) {
        s  += __shfl_xor_sync(0xffffffffu, s,  o);
        s2 += __shfl_xor_sync(0xffffffffu, s2, o);
    }
    const float mean = s * (1.f / 256.f);
    const float rstd = rsqrtf(s2 * (1.f / 256.f) - mean * mean + 1e-5f);

    float4 g0 = *reinterpret_cast<const float4*>(g + lane * 4);
    float4 g1 = *reinterpret_cast<const float4*>(g + 128 + lane * 4);
    float4 e0 = *reinterpret_cast<const float4*>(be + lane * 4);
    float4 e1 = *reinterpret_cast<const float4*>(be + 128 + lane * 4);

    float4 o0, o1;
    o0.x = (x0 - mean) * rstd * g0.x + e0.x;
    o0.y = (x1 - mean) * rstd * g0.y + e0.y;
    o0.z = (x2 - mean) * rstd * g0.z + e0.z;
    o0.w = (x3 - mean) * rstd * g0.w + e0.w;
    o1.x = (x4 - mean) * rstd * g1.x + e1.x;
    o1.y = (x5 - mean) * rstd * g1.y + e1.y;
    o1.z = (x6 - mean) * rstd * g1.z + e1.z;
    o1.w = (x7 - mean) * rstd * g1.w + e1.w;
    *reinterpret_cast<float4*>(out + base + lane * 4)       = o0;
    *reinterpret_cast<float4*>(out + base + 128 + lane * 4) = o1;
}

// ---------------- launch ----------------
extern "C" void kernel_launch(void* const* d_in, const int* in_sizes, int n_in,
                              void* d_out, int out_size)
{
    const float* pre_tgt  = (const float*)d_in[0];
    const float* pre_qpos = (const float*)d_in[1];
    const float* src      = (const float*)d_in[2];
    const float* ref_pts  = (const float*)d_in[3];
    const unsigned char* mask = (const unsigned char*)d_in[4];
    const float* W_value = (const float*)d_in[7];
    const float* b_value = (const float*)d_in[8];
    const float* W_off   = (const float*)d_in[9];
    const float* b_off   = (const float*)d_in[10];
    const float* W_attn  = (const float*)d_in[11];
    const float* b_attn  = (const float*)d_in[12];
    const float* W_out   = (const float*)d_in[13];
    const float* b_out   = (const float*)d_in[14];
    const float* g1      = (const float*)d_in[15];
    const float* be1     = (const float*)d_in[16];
    const float* W1      = (const float*)d_in[17];
    const float* b1      = (const float*)d_in[18];
    const float* W2      = (const float*)d_in[19];
    const float* b2      = (const float*)d_in[20];
    const float* g3      = (const float*)d_in[21];
    const float* be3     = (const float*)d_in[22];

    __nv_bfloat16* p_value;
    float *p_q, *p_oa, *p_samp, *p_ms, *p_tgt, *p_ffh, *p_ff;
    float *p_WvT, *p_WoaT, *p_boa, *p_WoutT, *p_W1T, *p_W2T;
    cudaGetSymbolAddress((void**)&p_value, g_value);
    cudaGetSymbolAddress((void**)&p_q,     g_q);
    cudaGetSymbolAddress((void**)&p_oa,    g_oa);
    cudaGetSymbolAddress((void**)&p_samp,  g_samp);
    cudaGetSymbolAddress((void**)&p_ms,    g_ms);
    cudaGetSymbolAddress((void**)&p_tgt,   g_tgt);
    cudaGetSymbolAddress((void**)&p_ffh,   g_ffh);
    cudaGetSymbolAddress((void**)&p_ff,    g_ff);
    cudaGetSymbolAddress((void**)&p_WvT,   g_WvT);
    cudaGetSymbolAddress((void**)&p_WoaT,  g_WoaT);
    cudaGetSymbolAddress((void**)&p_boa,   g_boa);
    cudaGetSymbolAddress((void**)&p_WoutT, g_WoutT);
    cudaGetSymbolAddress((void**)&p_W1T,   g_W1T);
    cudaGetSymbolAddress((void**)&p_W2T,   g_W2T);

    const int MV = NB * LIN;   // 174080
    dim3 tb(32, 8);

    // 1. q = pre_tgt + pre_query_pos
    addq_kernel<<<(NQ * DIM + 255) / 256, 256>>>(pre_tgt, pre_qpos, p_q, NQ * DIM);
    // 2-3. weight prep
    wprepA_kernel<<<dim3(16, 16, 4), tb>>>(W_value, p_WvT, W_out, p_WoutT, W1, p_W1T, W2, p_W2T);
    wprepB_kernel<<<dim3(12, 8), tb>>>(W_off, b_off, W_attn, b_attn, p_WoaT, p_boa);
    // 4. value = mask(src @ Wv + bv) -> bf16   [174080, 256]   (bf16 mma)
    mma_gemm_bf16<0, true, 1><<<dim3(DIM / 128, MV / 128), 256>>>(
        src, p_WvT, b_value, p_value, MV, DIM, DIM, mask);
    // 5. oa = q @ [Woff|Wattn] + [boff|battn]   (tf32 — guards sampling coords)
    mma_gemm_tf32<0><<<dim3(NOA / 128, (NQ + 127) / 128), 256>>>(
        p_q, p_WoaT, p_boa, p_oa, NQ, NOA, DIM);
    // 6. sampling  (launch #6 -> ncu profiles this next)
    msda_kernel<<<NQ, 256>>>(p_value, p_oa, ref_pts, p_samp);
    // 7. ms = samp @ Wout + bout   (bf16 mma)
    mma_gemm_bf16<0, false, 0><<<dim3(DIM / 128, (NQ + 127) / 128), 256>>>(
        p_samp, p_WoutT, b_out, p_ms, NQ, DIM, DIM, nullptr);
    // 8. tgt = LN(pre_tgt + ms)
    ln_kernel<<<NQ / 8, 256>>>(pre_tgt, p_ms, g1, be1, p_tgt);
    // 9. ffh = relu(tgt @ W1 + b1)   (bf16 mma)
    mma_gemm_bf16<1, false, 0><<<dim3(DFF / 128, (NQ + 127) / 128), 256>>>(
        p_tgt, p_W1T, b1, p_ffh, NQ, DFF, DIM, nullptr);
    // 10. ff = ffh @ W2 + b2   (bf16 mma)
    mma_gemm_bf16<0, false, 0><<<dim3(DIM / 128, (NQ + 127) / 128), 256>>>(
        p_ffh, p_W2T, b2, p_ff, NQ, DIM, DFF, nullptr);
    // 11. out = LN(tgt + ff)
    ln_kernel<<<NQ / 8, 256>>>(p_tgt, p_ff, g3, be3, (float*)d_out);
}

// round 7
// speedup vs baseline: 2.8530x; 1.0332x over previous
#include <cuda_runtime.h>
#include <cuda_bf16.h>
#include <cstdint>

// ---------------- Problem constants ----------------
#define NB   8
#define LQ   1000
#define NQ   (NB*LQ)
#define DIM  256
#define HEADS 8
#define HD   32
#define LIN  21760
#define DFF  512
#define NOA  384    // concat off(256) + attn(128)

__device__ __constant__ int c_H[4]  = {128, 64, 32, 16};
__device__ __constant__ int c_W[4]  = {128, 64, 32, 16};
__device__ __constant__ int c_S[4]  = {0, 16384, 20480, 21504};

// ---------------- Scratch ----------------
__device__ __nv_bfloat16 g_value[(size_t)LIN * NB * DIM];   // 89 MB (bf16)
__device__ float g_q    [(size_t)NQ * DIM];
__device__ float g_oa   [(size_t)NQ * NOA];
__device__ float g_samp [(size_t)NQ * DIM];
__device__ float g_ms   [(size_t)NQ * DIM];
__device__ float g_tgt  [(size_t)NQ * DIM];
__device__ float g_ffh  [(size_t)NQ * DFF];
__device__ float g_ff   [(size_t)NQ * DIM];
__device__ float g_WvT  [DIM * DIM];
__device__ float g_WoaT [NOA * DIM];
__device__ float g_boa  [NOA];
__device__ float g_WoutT[DIM * DIM];
__device__ float g_W1T  [DFF * DIM];
__device__ float g_W2T  [DIM * DFF];

// ---------------- helpers ----------------
__device__ __forceinline__ float tf32r(float x) {
    uint32_t u;
    asm("cvt.rna.tf32.f32 %0, %1;" : "=r"(u) : "f"(x));
    return __uint_as_float(u);
}
__device__ __forceinline__ void mma_tf32(float* d, const uint32_t* a, const uint32_t* b) {
    asm volatile(
        "mma.sync.aligned.m16n8k8.row.col.f32.tf32.tf32.f32 "
        "{%0,%1,%2,%3}, {%4,%5,%6,%7}, {%8,%9}, {%0,%1,%2,%3};"
        : "+f"(d[0]), "+f"(d[1]), "+f"(d[2]), "+f"(d[3])
        : "r"(a[0]), "r"(a[1]), "r"(a[2]), "r"(a[3]), "r"(b[0]), "r"(b[1]));
}
__device__ __forceinline__ void mma_bf16(float* d, const uint32_t* a, const uint32_t* b) {
    asm volatile(
        "mma.sync.aligned.m16n8k16.row.col.f32.bf16.bf16.f32 "
        "{%0,%1,%2,%3}, {%4,%5,%6,%7}, {%8,%9}, {%0,%1,%2,%3};"
        : "+f"(d[0]), "+f"(d[1]), "+f"(d[2]), "+f"(d[3])
        : "r"(a[0]), "r"(a[1]), "r"(a[2]), "r"(a[3]), "r"(b[0]), "r"(b[1]));
}
__device__ __forceinline__ void ldmx4(uint32_t* r, uint32_t addr) {
    asm volatile("ldmatrix.sync.aligned.m8n8.x4.shared.b16 {%0,%1,%2,%3}, [%4];"
        : "=r"(r[0]), "=r"(r[1]), "=r"(r[2]), "=r"(r[3]) : "r"(addr));
}
__device__ __forceinline__ uint32_t packbf(float lo, float hi) {
    __nv_bfloat162 h = __floats2bfloat162_rn(lo, hi);
    return *reinterpret_cast<uint32_t*>(&h);
}

// ================= bf16 mma GEMM v4: C = A@Bt^T + bias =================
// BM=128, BN=256, BK=32. 256 threads (8 warps, 2x4, warp tile 64x64).
// Single smem buffer + register prefetch. K mult of 32, N mult of 256.
#define SMS4 40   // halves per smem row (80B): 5r mod 8 permutation -> conflict-free ldmatrix
template<int ACT, bool MASK, int OUT>
__global__ void __launch_bounds__(256, 1) mma_gemm_v4(
    const float* __restrict__ A, const float* __restrict__ Bt,
    const float* __restrict__ bias, void* __restrict__ Cv,
    int M, int N, int K, const unsigned char* __restrict__ rowmask)
{
    __shared__ __nv_bfloat16 As[128 * SMS4];   // 10 KB
    __shared__ __nv_bfloat16 Bs[256 * SMS4];   // 20 KB

    const int tid  = threadIdx.x;
    const int lane = tid & 31;
    const int wid  = tid >> 5;
    const int wr   = wid & 1;       // 2 warp rows of 64
    const int wc   = wid >> 1;      // 4 warp cols of 64
    const int gid  = lane >> 2;
    const int tig  = lane & 3;
    const int brow = blockIdx.y * 128;
    const int bcol = blockIdx.x * 256;

    const int r_st = tid >> 3;          // 0..31
    const int kq   = (tid & 7) * 4;     // float col within 32-chunk (coalesced 128B rows)

    float acc[4][8][4];
    #pragma unroll
    for (int i = 0; i < 4; i++)
        #pragma unroll
        for (int j = 0; j < 8; j++)
            #pragma unroll
            for (int l = 0; l < 4; l++) acc[i][j][l] = 0.f;

    const uint32_t asb = (uint32_t)__cvta_generic_to_shared(&As[0]);
    const uint32_t bsb = (uint32_t)__cvta_generic_to_shared(&Bs[0]);
    const int a_off = ((lane & 7) + ((lane >> 3) & 1) * 8) * SMS4 + (lane >> 4) * 8;
    const int b_off = ((lane & 7) + ((lane >> 4) & 1) * 8) * SMS4 + ((lane >> 3) & 1) * 8;

    // prefetch registers (packed to bf16 at load time)
    uint2 pa[4], pb[8];

    #define LD_CHUNK(kc) do {                                                          \
        _Pragma("unroll")                                                              \
        for (int i = 0; i < 4; i++) {                                                  \
            int gr = brow + r_st + 32 * i; if (gr >= M) gr = M - 1;                    \
            float4 v = *reinterpret_cast<const float4*>(A + (size_t)gr * K + (kc) + kq); \
            pa[i].x = packbf(v.x, v.y); pa[i].y = packbf(v.z, v.w);                    \
        }                                                                              \
        _Pragma("unroll")                                                              \
        for (int j = 0; j < 8; j++) {                                                  \
            float4 v = *reinterpret_cast<const float4*>(Bt + (size_t)(bcol + r_st + 32 * j) * K + (kc) + kq); \
            pb[j].x = packbf(v.x, v.y); pb[j].y = packbf(v.z, v.w);                    \
        }                                                                              \
    } while (0)

    #define ST_CHUNK() do {                                                            \
        _Pragma("unroll")                                                              \
        for (int i = 0; i < 4; i++)                                                    \
            *reinterpret_cast<uint2*>(&As[(r_st + 32 * i) * SMS4 + kq]) = pa[i];       \
        _Pragma("unroll")                                                              \
        for (int j = 0; j < 8; j++)                                                    \
            *reinterpret_cast<uint2*>(&Bs[(r_st + 32 * j) * SMS4 + kq]) = pb[j];       \
    } while (0)

    const int KT = K >> 5;
    LD_CHUNK(0);
    ST_CHUNK();
    __syncthreads();

    for (int kt = 0; kt < KT; kt++) {
        if (kt + 1 < KT) LD_CHUNK((kt + 1) * 32);

        #pragma unroll
        for (int ks = 0; ks < 2; ks++) {
            uint32_t af[4][4];
            #pragma unroll
            for (int mt = 0; mt < 4; mt++)
                ldmx4(af[mt], asb + (uint32_t)(((wr * 64 + mt * 16) * SMS4 + a_off + ks * 16) * 2));
            #pragma unroll
            for (int p = 0; p < 4; p++) {
                uint32_t bfq[4];
                ldmx4(bfq, bsb + (uint32_t)(((wc * 64 + p * 16) * SMS4 + b_off + ks * 16) * 2));
                #pragma unroll
                for (int h = 0; h < 2; h++)
                    #pragma unroll
                    for (int mt = 0; mt < 4; mt++)
                        mma_bf16(acc[mt][p * 2 + h], af[mt], &bfq[h * 2]);
            }
        }

        if (kt + 1 < KT) {
            __syncthreads();   // all warps done reading smem
            ST_CHUNK();
            __syncthreads();
        }
    }
    #undef LD_CHUNK
    #undef ST_CHUNK

    float* Cf = (float*)Cv;
    __nv_bfloat16* Cb = (__nv_bfloat16*)Cv;

    #pragma unroll
    for (int mt = 0; mt < 4; mt++) {
        const int r0 = brow + wr * 64 + mt * 16 + gid;
        const int r1 = r0 + 8;
        const bool v0 = r0 < M, v1 = r1 < M;
        bool z0 = false, z1 = false;
        if (MASK) {
            if (v0) z0 = (rowmask[r0] != 0);
            if (v1) z1 = (rowmask[r1] != 0);
        }
        #pragma unroll
        for (int nt = 0; nt < 8; nt++) {
            const int col = bcol + wc * 64 + nt * 8 + 2 * tig;
            const float b0 = bias[col], b1 = bias[col + 1];
            float2 u, v;
            u.x = acc[mt][nt][0] + b0; u.y = acc[mt][nt][1] + b1;
            v.x = acc[mt][nt][2] + b0; v.y = acc[mt][nt][3] + b1;
            if (ACT == 1) {
                u.x = fmaxf(u.x, 0.f); u.y = fmaxf(u.y, 0.f);
                v.x = fmaxf(v.x, 0.f); v.y = fmaxf(v.y, 0.f);
            }
            if (MASK) {
                if (z0) { u.x = 0.f; u.y = 0.f; }
                if (z1) { v.x = 0.f; v.y = 0.f; }
            }
            if (OUT == 0) {
                if (v0) *reinterpret_cast<float2*>(Cf + (size_t)r0 * N + col) = u;
                if (v1) *reinterpret_cast<float2*>(Cf + (size_t)r1 * N + col) = v;
            } else {
                __nv_bfloat162 hu = __floats2bfloat162_rn(u.x, u.y);
                __nv_bfloat162 hv = __floats2bfloat162_rn(v.x, v.y);
                if (v0) *reinterpret_cast<__nv_bfloat162*>(Cb + (size_t)r0 * N + col) = hu;
                if (v1) *reinterpret_cast<__nv_bfloat162*>(Cb + (size_t)r1 * N + col) = hv;
            }
        }
    }
}

// ================= tf32 mma GEMM (precision-sensitive oa GEMM) =================
#define SMS 20
template<int ACT>
__global__ void __launch_bounds__(256, 2) mma_gemm_tf32(
    const float* __restrict__ A, const float* __restrict__ Bt,
    const float* __restrict__ bias, float* __restrict__ C,
    int M, int N, int K)
{
    __shared__ float As[2][128 * SMS];
    __shared__ float Bs[2][128 * SMS];

    const int tid  = threadIdx.x;
    const int lane = tid & 31;
    const int wid  = tid >> 5;
    const int wr   = wid & 3;
    const int wc   = wid >> 2;
    const int gid  = lane >> 2;
    const int tig  = lane & 3;
    const int brow = blockIdx.y * 128;
    const int bcol = blockIdx.x * 128;

    const int r_st = tid >> 2;
    const int k_st = (tid & 3) * 4;

    float acc[2][8][4];
    #pragma unroll
    for (int i = 0; i < 2; i++)
        #pragma unroll
        for (int j = 0; j < 8; j++)
            #pragma unroll
            for (int l = 0; l < 4; l++) acc[i][j][l] = 0.f;

    const int KT = K >> 4;
    float4 ra[2], rb[2];

    #pragma unroll
    for (int i = 0; i < 2; i++) {
        int r = r_st + i * 64;
        int garow = brow + r; if (garow >= M) garow = M - 1;
        ra[i] = *reinterpret_cast<const float4*>(A  + (size_t)garow * K + k_st);
        rb[i] = *reinterpret_cast<const float4*>(Bt + (size_t)(bcol + r) * K + k_st);
    }
    #pragma unroll
    for (int i = 0; i < 2; i++) {
        int r = r_st + i * 64;
        float4 av = make_float4(tf32r(ra[i].x), tf32r(ra[i].y), tf32r(ra[i].z), tf32r(ra[i].w));
        float4 bv = make_float4(tf32r(rb[i].x), tf32r(rb[i].y), tf32r(rb[i].z), tf32r(rb[i].w));
        *reinterpret_cast<float4*>(&As[0][r * SMS + k_st]) = av;
        *reinterpret_cast<float4*>(&Bs[0][r * SMS + k_st]) = bv;
    }
    __syncthreads();

    for (int kt = 0; kt < KT; kt++) {
        const int buf = kt & 1;
        if (kt + 1 < KT) {
            const int kc = (kt + 1) * 16;
            #pragma unroll
            for (int i = 0; i < 2; i++) {
                int r = r_st + i * 64;
                int garow = brow + r; if (garow >= M) garow = M - 1;
                ra[i] = *reinterpret_cast<const float4*>(A  + (size_t)garow * K + kc + k_st);
                rb[i] = *reinterpret_cast<const float4*>(Bt + (size_t)(bcol + r) * K + kc + k_st);
            }
        }
        const float* as = As[buf];
        const float* bs = Bs[buf];
        #pragma unroll
        for (int ks = 0; ks < 2; ks++) {
            const int k0 = ks * 8;
            uint32_t af[2][4];
            #pragma unroll
            for (int mt = 0; mt < 2; mt++) {
                const int mb = wr * 32 + mt * 16;
                af[mt][0] = __float_as_uint(as[(mb + gid    ) * SMS + k0 + tig    ]);
                af[mt][1] = __float_as_uint(as[(mb + gid + 8) * SMS + k0 + tig    ]);
                af[mt][2] = __float_as_uint(as[(mb + gid    ) * SMS + k0 + tig + 4]);
                af[mt][3] = __float_as_uint(as[(mb + gid + 8) * SMS + k0 + tig + 4]);
            }
            #pragma unroll
            for (int nt = 0; nt < 8; nt++) {
                const int nb = wc * 64 + nt * 8 + gid;
                uint32_t bfr[2];
                bfr[0] = __float_as_uint(bs[nb * SMS + k0 + tig    ]);
                bfr[1] = __float_as_uint(bs[nb * SMS + k0 + tig + 4]);
                mma_tf32(acc[0][nt], af[0], bfr);
                mma_tf32(acc[1][nt], af[1], bfr);
            }
        }
        if (kt + 1 < KT) {
            const int nb2 = (kt + 1) & 1;
            #pragma unroll
            for (int i = 0; i < 2; i++) {
                int r = r_st + i * 64;
                float4 av = make_float4(tf32r(ra[i].x), tf32r(ra[i].y), tf32r(ra[i].z), tf32r(ra[i].w));
                float4 bv = make_float4(tf32r(rb[i].x), tf32r(rb[i].y), tf32r(rb[i].z), tf32r(rb[i].w));
                *reinterpret_cast<float4*>(&As[nb2][r * SMS + k_st]) = av;
                *reinterpret_cast<float4*>(&Bs[nb2][r * SMS + k_st]) = bv;
            }
            __syncthreads();
        }
    }

    #pragma unroll
    for (int mt = 0; mt < 2; mt++) {
        const int r0 = brow + wr * 32 + mt * 16 + gid;
        const int r1 = r0 + 8;
        const bool v0 = r0 < M, v1 = r1 < M;
        #pragma unroll
        for (int nt = 0; nt < 8; nt++) {
            const int col = bcol + wc * 64 + nt * 8 + 2 * tig;
            const float b0 = bias[col], b1 = bias[col + 1];
            float2 u, v;
            u.x = acc[mt][nt][0] + b0; u.y = acc[mt][nt][1] + b1;
            v.x = acc[mt][nt][2] + b0; v.y = acc[mt][nt][3] + b1;
            if (v0) *reinterpret_cast<float2*>(C + (size_t)r0 * N + col) = u;
            if (v1) *reinterpret_cast<float2*>(C + (size_t)r1 * N + col) = v;
        }
    }
}

// ---------------- batched weight prep A ----------------
__global__ void wprepA_kernel(const float* __restrict__ Wv,  float* __restrict__ WvT,
                              const float* __restrict__ Wo,  float* __restrict__ WoT,
                              const float* __restrict__ W1,  float* __restrict__ W1T,
                              const float* __restrict__ W2,  float* __restrict__ W2T)
{
    __shared__ float t[32][33];
    const float* W; float* Wt; int K, N;
    switch (blockIdx.z) {
        case 0: W = Wv; Wt = WvT; K = DIM; N = DIM; break;
        case 1: W = Wo; Wt = WoT; K = DIM; N = DIM; break;
        case 2: W = W1; Wt = W1T; K = DIM; N = DFF; break;
        default:W = W2; Wt = W2T; K = DFF; N = DIM; break;
    }
    const int bx = blockIdx.x * 32;
    const int by = blockIdx.y * 32;
    if (bx >= N || by >= K) return;
    const int x = threadIdx.x, y = threadIdx.y;
    #pragma unroll
    for (int i = 0; i < 32; i += 8)
        t[y + i][x] = W[(size_t)(by + y + i) * N + bx + x];
    __syncthreads();
    #pragma unroll
    for (int i = 0; i < 32; i += 8)
        Wt[(size_t)(bx + y + i) * K + by + x] = t[x][y + i];
}

// ---------------- weight prep B: WoaT = [W_off^T ; W_attn^T] ----------------
__global__ void wprepB_kernel(const float* __restrict__ Woff, const float* __restrict__ boff,
                              const float* __restrict__ Watt, const float* __restrict__ batt,
                              float* __restrict__ WoaT, float* __restrict__ boa)
{
    __shared__ float t[32][33];
    const int bx = blockIdx.x * 32;
    const int by = blockIdx.y * 32;
    const int x = threadIdx.x, y = threadIdx.y;
    const bool isAtt = (bx >= 256);
    const float* W = isAtt ? Watt : Woff;
    const int    nN = isAtt ? 128 : 256;
    const int    nb = isAtt ? bx - 256 : bx;
    #pragma unroll
    for (int i = 0; i < 32; i += 8)
        t[y + i][x] = W[(size_t)(by + y + i) * nN + nb + x];
    __syncthreads();
    #pragma unroll
    for (int i = 0; i < 32; i += 8)
        WoaT[(size_t)(bx + y + i) * DIM + by + x] = t[x][y + i];
    if (blockIdx.y == 0 && y == 0) {
        int n = bx + x;
        boa[n] = (n < 256) ? boff[n] : batt[n - 256];
    }
}

// ---------------- elementwise q = a + b ----------------
__global__ void addq_kernel(const float* __restrict__ a, const float* __restrict__ b,
                            float* __restrict__ o, int n)
{
    int i = blockIdx.x * blockDim.x + threadIdx.x;
    if (i < n) o[i] = a[i] + b[i];
}

// ---------------- MS-deform sampling (softmax fused), bf16 value ----------
__global__ void msda_kernel(const __nv_bfloat16* __restrict__ value,
                            const float* __restrict__ oa,
                            const float* __restrict__ refpts,
                            float* __restrict__ samp)
{
    const int nq   = blockIdx.x;
    const int h    = threadIdx.x >> 5;
    const int lane = threadIdx.x & 31;
    const int n    = nq / LQ;

    float logit = (lane < 16) ? oa[(size_t)nq * NOA + 256 + h * 16 + lane] : -1e30f;
    float m = logit;
    #pragma unroll
    for (int o = 8; o > 0; o >>= 1) m = fmaxf(m, __shfl_xor_sync(0xffffffffu, m, o, 16));
    float e = (lane < 16) ? __expf(logit - m) : 0.f;
    float s = e;
    #pragma unroll
    for (int o = 8; o > 0; o >>= 1) s += __shfl_xor_sync(0xffffffffu, s, o, 16);
    float w = e / s;

    float offv = oa[(size_t)nq * NOA + h * 32 + lane];
    float refv = (lane < 8) ? refpts[(size_t)nq * 8 + lane] : 0.f;

    const __nv_bfloat16* vbase = value + ((size_t)n * LIN * HEADS + h) * HD + lane;

    float acc = 0.f;
    #pragma unroll
    for (int i = 0; i < 16; i++) {
        const int l = i >> 2;
        const int p = i & 3;
        const float wi   = __shfl_sync(0xffffffffu, w,    i);
        const float offx = __shfl_sync(0xffffffffu, offv, l * 8 + p * 2 + 0);
        const float offy = __shfl_sync(0xffffffffu, offv, l * 8 + p * 2 + 1);
        const float refx = __shfl_sync(0xffffffffu, refv, l * 2 + 0);
        const float refy = __shfl_sync(0xffffffffu, refv, l * 2 + 1);

        const int Hl = c_H[l], Wl = c_W[l], st = c_S[l];
        const float x = refx * (float)Wl + offx - 0.5f;
        const float y = refy * (float)Hl + offy - 0.5f;
        const float x0f = floorf(x), y0f = floorf(y);
        const float fx = x - x0f, fy = y - y0f;
        const int x0 = (int)x0f, y0 = (int)y0f;
        const int x1 = x0 + 1,   y1 = y0 + 1;

        const bool vx0 = (x0 >= 0) & (x0 < Wl);
        const bool vx1 = (x1 >= 0) & (x1 < Wl);
        const bool vy0 = (y0 >= 0) & (y0 < Hl);
        const bool vy1 = (y1 >= 0) & (y1 < Hl);

        float sv = 0.f;
        if (vy0) {
            const __nv_bfloat16* rowp = vbase + (size_t)(st + y0 * Wl) * HEADS * HD;
            if (vx0) sv += (1.f - fx) * (1.f - fy) * __bfloat162float(rowp[(size_t)x0 * HEADS * HD]);
            if (vx1) sv += fx * (1.f - fy)         * __bfloat162float(rowp[(size_t)x1 * HEADS * HD]);
        }
        if (vy1) {
            const __nv_bfloat16* rowp = vbase + (size_t)(st + y1 * Wl) * HEADS * HD;
            if (vx0) sv += (1.f - fx) * fy * __bfloat162float(rowp[(size_t)x0 * HEADS * HD]);
            if (vx1) sv += fx * fy         * __bfloat162float(rowp[(size_t)x1 * HEADS * HD]);
        }
        acc += wi * sv;
    }
    samp[(size_t)nq * 256 + h * 32 + lane] = acc;
}

// ---------------- fused residual + LayerNorm (warp per row) ----------------
__global__ void ln_kernel(const float* __restrict__ a, const float* __restrict__ b,
                          const float* __restrict__ g, const float* __restrict__ be,
                          float* __restrict__ out)
{
    const int row  = blockIdx.x * 8 + (threadIdx.x >> 5);
    const int lane = threadIdx.x & 31;
    const size_t base = (size_t)row * 256;

    float4 a0 = *reinterpret_cast<const float4*>(a + base + lane * 4);
    float4 a1 = *reinterpret_cast<const float4*>(a + base + 128 + lane * 4);
    float4 b0 = *reinterpret_cast<const float4*>(b + base + lane * 4);
    float4 b1 = *reinterpret_cast<const float4*>(b + base + 128 + lane * 4);
    float x0 = a0.x + b0.x, x1 = a0.y + b0.y, x2 = a0.z + b0.z, x3 = a0.w + b0.w;
    float x4 = a1.x + b1.x, x5 = a1.y + b1.y, x6 = a1.z + b1.z, x7 = a1.w + b1.w;

    float s  = x0 + x1 + x2 + x3 + x4 + x5 + x6 + x7;
    float s2 = x0*x0 + x1*x1 + x2*x2 + x3*x3 + x4*x4 + x5*x5 + x6*x6 + x7*x7;
    #pragma unroll
    for (int o = 16; o > 0; o >>= 1) {
        s  += __shfl_xor_sync(0xffffffffu, s,  o);
        s2 += __shfl_xor_sync(0xffffffffu, s2, o);
    }
    const float mean = s * (1.f / 256.f);
    const float rstd = rsqrtf(s2 * (1.f / 256.f) - mean * mean + 1e-5f);

    float4 g0 = *reinterpret_cast<const float4*>(g + lane * 4);
    float4 g1 = *reinterpret_cast<const float4*>(g + 128 + lane * 4);
    float4 e0 = *reinterpret_cast<const float4*>(be + lane * 4);
    float4 e1 = *reinterpret_cast<const float4*>(be + 128 + lane * 4);

    float4 o0, o1;
    o0.x = (x0 - mean) * rstd * g0.x + e0.x;
    o0.y = (x1 - mean) * rstd * g0.y + e0.y;
    o0.z = (x2 - mean) * rstd * g0.z + e0.z;
    o0.w = (x3 - mean) * rstd * g0.w + e0.w;
    o1.x = (x4 - mean) * rstd * g1.x + e1.x;
    o1.y = (x5 - mean) * rstd * g1.y + e1.y;
    o1.z = (x6 - mean) * rstd * g1.z + e1.z;
    o1.w = (x7 - mean) * rstd * g1.w + e1.w;
    *reinterpret_cast<float4*>(out + base + lane * 4)       = o0;
    *reinterpret_cast<float4*>(out + base + 128 + lane * 4) = o1;
}

// ---------------- launch ----------------
extern "C" void kernel_launch(void* const* d_in, const int* in_sizes, int n_in,
                              void* d_out, int out_size)
{
    const float* pre_tgt  = (const float*)d_in[0];
    const float* pre_qpos = (const float*)d_in[1];
    const float* src      = (const float*)d_in[2];
    const float* ref_pts  = (const float*)d_in[3];
    const unsigned char* mask = (const unsigned char*)d_in[4];
    const float* W_value = (const float*)d_in[7];
    const float* b_value = (const float*)d_in[8];
    const float* W_off   = (const float*)d_in[9];
    const float* b_off   = (const float*)d_in[10];
    const float* W_attn  = (const float*)d_in[11];
    const float* b_attn  = (const float*)d_in[12];
    const float* W_out   = (const float*)d_in[13];
    const float* b_out   = (const float*)d_in[14];
    const float* g1      = (const float*)d_in[15];
    const float* be1     = (const float*)d_in[16];
    const float* W1      = (const float*)d_in[17];
    const float* b1      = (const float*)d_in[18];
    const float* W2      = (const float*)d_in[19];
    const float* b2      = (const float*)d_in[20];
    const float* g3      = (const float*)d_in[21];
    const float* be3     = (const float*)d_in[22];

    __nv_bfloat16* p_value;
    float *p_q, *p_oa, *p_samp, *p_ms, *p_tgt, *p_ffh, *p_ff;
    float *p_WvT, *p_WoaT, *p_boa, *p_WoutT, *p_W1T, *p_W2T;
    cudaGetSymbolAddress((void**)&p_value, g_value);
    cudaGetSymbolAddress((void**)&p_q,     g_q);
    cudaGetSymbolAddress((void**)&p_oa,    g_oa);
    cudaGetSymbolAddress((void**)&p_samp,  g_samp);
    cudaGetSymbolAddress((void**)&p_ms,    g_ms);
    cudaGetSymbolAddress((void**)&p_tgt,   g_tgt);
    cudaGetSymbolAddress((void**)&p_ffh,   g_ffh);
    cudaGetSymbolAddress((void**)&p_ff,    g_ff);
    cudaGetSymbolAddress((void**)&p_WvT,   g_WvT);
    cudaGetSymbolAddress((void**)&p_WoaT,  g_WoaT);
    cudaGetSymbolAddress((void**)&p_boa,   g_boa);
    cudaGetSymbolAddress((void**)&p_WoutT, g_WoutT);
    cudaGetSymbolAddress((void**)&p_W1T,   g_W1T);
    cudaGetSymbolAddress((void**)&p_W2T,   g_W2T);

    const int MV = NB * LIN;   // 174080
    dim3 tb(32, 8);

    // 1. q = pre_tgt + pre_query_pos
    addq_kernel<<<(NQ * DIM + 255) / 256, 256>>>(pre_tgt, pre_qpos, p_q, NQ * DIM);
    // 2-3. weight prep
    wprepA_kernel<<<dim3(16, 16, 4), tb>>>(W_value, p_WvT, W_out, p_WoutT, W1, p_W1T, W2, p_W2T);
    wprepB_kernel<<<dim3(12, 8), tb>>>(W_off, b_off, W_attn, b_attn, p_WoaT, p_boa);
    // 4. value = mask(src @ Wv + bv) -> bf16   [174080, 256]  (v4: BN=256 single pass)
    mma_gemm_v4<0, true, 1><<<dim3(1, MV / 128), 256>>>(
        src, p_WvT, b_value, p_value, MV, DIM, DIM, mask);
    // 5. oa = q @ [Woff|Wattn] + [boff|battn]   (tf32 — guards sampling coords)
    mma_gemm_tf32<0><<<dim3(NOA / 128, (NQ + 127) / 128), 256>>>(
        p_q, p_WoaT, p_boa, p_oa, NQ, NOA, DIM);
    // 6. sampling
    msda_kernel<<<NQ, 256>>>(p_value, p_oa, ref_pts, p_samp);
    // 7. ms = samp @ Wout + bout
    mma_gemm_v4<0, false, 0><<<dim3(1, (NQ + 127) / 128), 256>>>(
        p_samp, p_WoutT, b_out, p_ms, NQ, DIM, DIM, nullptr);
    // 8. tgt = LN(pre_tgt + ms)
    ln_kernel<<<NQ / 8, 256>>>(pre_tgt, p_ms, g1, be1, p_tgt);
    // 9. ffh = relu(tgt @ W1 + b1)   [8000, 512]
    mma_gemm_v4<1, false, 0><<<dim3(2, (NQ + 127) / 128), 256>>>(
        p_tgt, p_W1T, b1, p_ffh, NQ, DFF, DIM, nullptr);
    // 10. ff = ffh @ W2 + b2   [8000, 256], K=512
    mma_gemm_v4<0, false, 0><<<dim3(1, (NQ + 127) / 128), 256>>>(
        p_ffh, p_W2T, b2, p_ff, NQ, DIM, DFF, nullptr);
    // 11. out = LN(tgt + ff)
    ln_kernel<<<NQ / 8, 256>>>(p_tgt, p_ff, g3, be3, (float*)d_out);
}

// round 8
// speedup vs baseline: 3.2599x; 1.1426x over previous
#include <cuda_runtime.h>
#include <cuda_bf16.h>
#include <cstdint>

// ---------------- Problem constants ----------------
#define NB   8
#define LQ   1000
#define NQ   (NB*LQ)
#define DIM  256
#define HEADS 8
#define HD   32
#define LIN  21760
#define DFF  512
#define NOA  384    // concat off(256) + attn(128)

__device__ __constant__ int c_H[4]  = {128, 64, 32, 16};
__device__ __constant__ int c_W[4]  = {128, 64, 32, 16};
__device__ __constant__ int c_S[4]  = {0, 16384, 20480, 21504};

// ---------------- Scratch ----------------
__device__ __nv_bfloat16 g_value[(size_t)LIN * NB * DIM];   // 89 MB (bf16)
__device__ float g_q    [(size_t)NQ * DIM];
__device__ float g_oa   [(size_t)NQ * NOA];
__device__ float g_samp [(size_t)NQ * DIM];
__device__ float g_ms   [(size_t)NQ * DIM];
__device__ float g_tgt  [(size_t)NQ * DIM];
__device__ float g_ffh  [(size_t)NQ * DFF];
__device__ float g_ff   [(size_t)NQ * DIM];
__device__ float g_WvT  [DIM * DIM];
__device__ float g_WoaT [NOA * DIM];
__device__ float g_boa  [NOA];
__device__ float g_WoutT[DIM * DIM];
__device__ float g_W1T  [DFF * DIM];
__device__ float g_W2T  [DIM * DFF];

// ---------------- helpers ----------------
__device__ __forceinline__ float tf32r(float x) {
    uint32_t u;
    asm("cvt.rna.tf32.f32 %0, %1;" : "=r"(u) : "f"(x));
    return __uint_as_float(u);
}
__device__ __forceinline__ void mma_tf32(float* d, const uint32_t* a, const uint32_t* b) {
    asm volatile(
        "mma.sync.aligned.m16n8k8.row.col.f32.tf32.tf32.f32 "
        "{%0,%1,%2,%3}, {%4,%5,%6,%7}, {%8,%9}, {%0,%1,%2,%3};"
        : "+f"(d[0]), "+f"(d[1]), "+f"(d[2]), "+f"(d[3])
        : "r"(a[0]), "r"(a[1]), "r"(a[2]), "r"(a[3]), "r"(b[0]), "r"(b[1]));
}
__device__ __forceinline__ void mma_bf16(float* d, const uint32_t* a, const uint32_t* b) {
    asm volatile(
        "mma.sync.aligned.m16n8k16.row.col.f32.bf16.bf16.f32 "
        "{%0,%1,%2,%3}, {%4,%5,%6,%7}, {%8,%9}, {%0,%1,%2,%3};"
        : "+f"(d[0]), "+f"(d[1]), "+f"(d[2]), "+f"(d[3])
        : "r"(a[0]), "r"(a[1]), "r"(a[2]), "r"(a[3]), "r"(b[0]), "r"(b[1]));
}
__device__ __forceinline__ void ldmx4(uint32_t* r, uint32_t addr) {
    asm volatile("ldmatrix.sync.aligned.m8n8.x4.shared.b16 {%0,%1,%2,%3}, [%4];"
        : "=r"(r[0]), "=r"(r[1]), "=r"(r[2]), "=r"(r[3]) : "r"(addr));
}
__device__ __forceinline__ uint32_t packbf(float lo, float hi) {
    __nv_bfloat162 h = __floats2bfloat162_rn(lo, hi);
    return *reinterpret_cast<uint32_t*>(&h);
}
// 64B-row swizzle: XOR 16B-group bits [4:5] with row bits (addr bits [7:8])
#define SW64(o) ((uint32_t)(o) ^ (((uint32_t)(o) >> 3) & 0x30u))

// ================= bf16 mma GEMM v5: C = A@Bt^T + bias =================
// BM=128, BN=128, BK=32. 256 threads (8 warps 2x4, warp tile 64x32).
// Double-buffered swizzled smem (32KB), 2 CTAs/SM. K mult of 32, N mult of 128.
template<int ACT, bool MASK, int OUT>
__global__ void __launch_bounds__(256, 2) mma_gemm_v5(
    const float* __restrict__ A, const float* __restrict__ Bt,
    const float* __restrict__ bias, void* __restrict__ Cv,
    int M, int N, int K, const unsigned char* __restrict__ rowmask)
{
    __shared__ __align__(128) __nv_bfloat16 As[2][128 * 32];   // 2 x 8 KB
    __shared__ __align__(128) __nv_bfloat16 Bs[2][128 * 32];   // 2 x 8 KB

    const int tid  = threadIdx.x;
    const int lane = tid & 31;
    const int wid  = tid >> 5;
    const int wr   = wid & 1;       // 2 warp rows of 64
    const int wc   = wid >> 1;      // 4 warp cols of 32
    const int gid  = lane >> 2;
    const int tig  = lane & 3;
    const int brow = blockIdx.y * 128;
    const int bcol = blockIdx.x * 128;

    const int r_st = tid >> 3;          // 0..31
    const int kq   = (tid & 7) * 4;     // float col (coalesced 128B rows)
    const int sts_col = (tid & 7) * 8;  // byte col in 64B row

    float acc[4][4][4];
    #pragma unroll
    for (int i = 0; i < 4; i++)
        #pragma unroll
        for (int j = 0; j < 4; j++)
            #pragma unroll
            for (int l = 0; l < 4; l++) acc[i][j][l] = 0.f;

    const uint32_t asb = (uint32_t)__cvta_generic_to_shared(&As[0][0]);
    const uint32_t bsb = (uint32_t)__cvta_generic_to_shared(&Bs[0][0]);
    const uint32_t bufoff = 128 * 32 * 2;   // 8 KB

    // ldmatrix lane address components (bytes)
    const int a_row = (lane & 7) + ((lane >> 3) & 1) * 8;
    const int a_col = (lane >> 4) * 16;
    const int b_row = (lane & 7) + ((lane >> 4) & 1) * 8;
    const int b_col = ((lane >> 3) & 1) * 16;

    uint2 pa[4], pb[4];

    #define LD_CHUNK(kc) do {                                                            \
        _Pragma("unroll")                                                                \
        for (int i = 0; i < 4; i++) {                                                    \
            int gr = brow + r_st + 32 * i; if (gr >= M) gr = M - 1;                      \
            float4 v = *reinterpret_cast<const float4*>(A + (size_t)gr * K + (kc) + kq); \
            pa[i].x = packbf(v.x, v.y); pa[i].y = packbf(v.z, v.w);                      \
        }                                                                                \
        _Pragma("unroll")                                                                \
        for (int j = 0; j < 4; j++) {                                                    \
            float4 v = *reinterpret_cast<const float4*>(Bt + (size_t)(bcol + r_st + 32 * j) * K + (kc) + kq); \
            pb[j].x = packbf(v.x, v.y); pb[j].y = packbf(v.z, v.w);                      \
        }                                                                                \
    } while (0)

    #define ST_CHUNK(buf) do {                                                           \
        char* sa = reinterpret_cast<char*>(&As[buf][0]);                                 \
        char* sb = reinterpret_cast<char*>(&Bs[buf][0]);                                 \
        _Pragma("unroll")                                                                \
        for (int i = 0; i < 4; i++)                                                      \
            *reinterpret_cast<uint2*>(sa + SW64((r_st + 32 * i) * 64 + sts_col)) = pa[i];\
        _Pragma("unroll")                                                                \
        for (int j = 0; j < 4; j++)                                                      \
            *reinterpret_cast<uint2*>(sb + SW64((r_st + 32 * j) * 64 + sts_col)) = pb[j];\
    } while (0)

    const int KT = K >> 5;
    LD_CHUNK(0);
    ST_CHUNK(0);
    __syncthreads();

    for (int kt = 0; kt < KT; kt++) {
        const int buf = kt & 1;
        if (kt + 1 < KT) LD_CHUNK((kt + 1) * 32);

        const uint32_t ab = asb + buf * bufoff;
        const uint32_t bb = bsb + buf * bufoff;
        #pragma unroll
        for (int ks = 0; ks < 2; ks++) {
            uint32_t af[4][4], bfq[2][4];
            #pragma unroll
            for (int mt = 0; mt < 4; mt++)
                ldmx4(af[mt], ab + SW64((wr * 64 + mt * 16 + a_row) * 64 + a_col + ks * 32));
            #pragma unroll
            for (int p = 0; p < 2; p++)
                ldmx4(bfq[p], bb + SW64((wc * 32 + p * 16 + b_row) * 64 + b_col + ks * 32));
            #pragma unroll
            for (int mt = 0; mt < 4; mt++)
                #pragma unroll
                for (int nt = 0; nt < 4; nt++)
                    mma_bf16(acc[mt][nt], af[mt], &bfq[nt >> 1][(nt & 1) * 2]);
        }

        if (kt + 1 < KT) {
            ST_CHUNK(buf ^ 1);     // other buffer: safe, everyone read it last kt
            __syncthreads();
        }
    }
    #undef LD_CHUNK
    #undef ST_CHUNK

    float* Cf = (float*)Cv;
    __nv_bfloat16* Cb = (__nv_bfloat16*)Cv;

    #pragma unroll
    for (int mt = 0; mt < 4; mt++) {
        const int r0 = brow + wr * 64 + mt * 16 + gid;
        const int r1 = r0 + 8;
        const bool v0 = r0 < M, v1 = r1 < M;
        bool z0 = false, z1 = false;
        if (MASK) {
            if (v0) z0 = (rowmask[r0] != 0);
            if (v1) z1 = (rowmask[r1] != 0);
        }
        #pragma unroll
        for (int nt = 0; nt < 4; nt++) {
            const int col = bcol + wc * 32 + nt * 8 + 2 * tig;
            const float b0 = bias[col], b1 = bias[col + 1];
            float2 u, v;
            u.x = acc[mt][nt][0] + b0; u.y = acc[mt][nt][1] + b1;
            v.x = acc[mt][nt][2] + b0; v.y = acc[mt][nt][3] + b1;
            if (ACT == 1) {
                u.x = fmaxf(u.x, 0.f); u.y = fmaxf(u.y, 0.f);
                v.x = fmaxf(v.x, 0.f); v.y = fmaxf(v.y, 0.f);
            }
            if (MASK) {
                if (z0) { u.x = 0.f; u.y = 0.f; }
                if (z1) { v.x = 0.f; v.y = 0.f; }
            }
            if (OUT == 0) {
                if (v0) *reinterpret_cast<float2*>(Cf + (size_t)r0 * N + col) = u;
                if (v1) *reinterpret_cast<float2*>(Cf + (size_t)r1 * N + col) = v;
            } else {
                __nv_bfloat162 hu = __floats2bfloat162_rn(u.x, u.y);
                __nv_bfloat162 hv = __floats2bfloat162_rn(v.x, v.y);
                if (v0) *reinterpret_cast<__nv_bfloat162*>(Cb + (size_t)r0 * N + col) = hu;
                if (v1) *reinterpret_cast<__nv_bfloat162*>(Cb + (size_t)r1 * N + col) = hv;
            }
        }
    }
}

// ================= tf32 mma GEMM (precision-sensitive oa GEMM) =================
#define SMS 20
template<int ACT>
__global__ void __launch_bounds__(256, 2) mma_gemm_tf32(
    const float* __restrict__ A, const float* __restrict__ Bt,
    const float* __restrict__ bias, float* __restrict__ C,
    int M, int N, int K)
{
    __shared__ float As[2][128 * SMS];
    __shared__ float Bs[2][128 * SMS];

    const int tid  = threadIdx.x;
    const int lane = tid & 31;
    const int wid  = tid >> 5;
    const int wr   = wid & 3;
    const int wc   = wid >> 2;
    const int gid  = lane >> 2;
    const int tig  = lane & 3;
    const int brow = blockIdx.y * 128;
    const int bcol = blockIdx.x * 128;

    const int r_st = tid >> 2;
    const int k_st = (tid & 3) * 4;

    float acc[2][8][4];
    #pragma unroll
    for (int i = 0; i < 2; i++)
        #pragma unroll
        for (int j = 0; j < 8; j++)
            #pragma unroll
            for (int l = 0; l < 4; l++) acc[i][j][l] = 0.f;

    const int KT = K >> 4;
    float4 ra[2], rb[2];

    #pragma unroll
    for (int i = 0; i < 2; i++) {
        int r = r_st + i * 64;
        int garow = brow + r; if (garow >= M) garow = M - 1;
        ra[i] = *reinterpret_cast<const float4*>(A  + (size_t)garow * K + k_st);
        rb[i] = *reinterpret_cast<const float4*>(Bt + (size_t)(bcol + r) * K + k_st);
    }
    #pragma unroll
    for (int i = 0; i < 2; i++) {
        int r = r_st + i * 64;
        float4 av = make_float4(tf32r(ra[i].x), tf32r(ra[i].y), tf32r(ra[i].z), tf32r(ra[i].w));
        float4 bv = make_float4(tf32r(rb[i].x), tf32r(rb[i].y), tf32r(rb[i].z), tf32r(rb[i].w));
        *reinterpret_cast<float4*>(&As[0][r * SMS + k_st]) = av;
        *reinterpret_cast<float4*>(&Bs[0][r * SMS + k_st]) = bv;
    }
    __syncthreads();

    for (int kt = 0; kt < KT; kt++) {
        const int buf = kt & 1;
        if (kt + 1 < KT) {
            const int kc = (kt + 1) * 16;
            #pragma unroll
            for (int i = 0; i < 2; i++) {
                int r = r_st + i * 64;
                int garow = brow + r; if (garow >= M) garow = M - 1;
                ra[i] = *reinterpret_cast<const float4*>(A  + (size_t)garow * K + kc + k_st);
                rb[i] = *reinterpret_cast<const float4*>(Bt + (size_t)(bcol + r) * K + kc + k_st);
            }
        }
        const float* as = As[buf];
        const float* bs = Bs[buf];
        #pragma unroll
        for (int ks = 0; ks < 2; ks++) {
            const int k0 = ks * 8;
            uint32_t af[2][4];
            #pragma unroll
            for (int mt = 0; mt < 2; mt++) {
                const int mb = wr * 32 + mt * 16;
                af[mt][0] = __float_as_uint(as[(mb + gid    ) * SMS + k0 + tig    ]);
                af[mt][1] = __float_as_uint(as[(mb + gid + 8) * SMS + k0 + tig    ]);
                af[mt][2] = __float_as_uint(as[(mb + gid    ) * SMS + k0 + tig + 4]);
                af[mt][3] = __float_as_uint(as[(mb + gid + 8) * SMS + k0 + tig + 4]);
            }
            #pragma unroll
            for (int nt = 0; nt < 8; nt++) {
                const int nb = wc * 64 + nt * 8 + gid;
                uint32_t bfr[2];
                bfr[0] = __float_as_uint(bs[nb * SMS + k0 + tig    ]);
                bfr[1] = __float_as_uint(bs[nb * SMS + k0 + tig + 4]);
                mma_tf32(acc[0][nt], af[0], bfr);
                mma_tf32(acc[1][nt], af[1], bfr);
            }
        }
        if (kt + 1 < KT) {
            const int nb2 = (kt + 1) & 1;
            #pragma unroll
            for (int i = 0; i < 2; i++) {
                int r = r_st + i * 64;
                float4 av = make_float4(tf32r(ra[i].x), tf32r(ra[i].y), tf32r(ra[i].z), tf32r(ra[i].w));
                float4 bv = make_float4(tf32r(rb[i].x), tf32r(rb[i].y), tf32r(rb[i].z), tf32r(rb[i].w));
                *reinterpret_cast<float4*>(&As[nb2][r * SMS + k_st]) = av;
                *reinterpret_cast<float4*>(&Bs[nb2][r * SMS + k_st]) = bv;
            }
            __syncthreads();
        }
    }

    #pragma unroll
    for (int mt = 0; mt < 2; mt++) {
        const int r0 = brow + wr * 32 + mt * 16 + gid;
        const int r1 = r0 + 8;
        const bool v0 = r0 < M, v1 = r1 < M;
        #pragma unroll
        for (int nt = 0; nt < 8; nt++) {
            const int col = bcol + wc * 64 + nt * 8 + 2 * tig;
            const float b0 = bias[col], b1 = bias[col + 1];
            float2 u, v;
            u.x = acc[mt][nt][0] + b0; u.y = acc[mt][nt][1] + b1;
            v.x = acc[mt][nt][2] + b0; v.y = acc[mt][nt][3] + b1;
            if (v0) *reinterpret_cast<float2*>(C + (size_t)r0 * N + col) = u;
            if (v1) *reinterpret_cast<float2*>(C + (size_t)r1 * N + col) = v;
        }
    }
}

// ---------------- batched weight prep A ----------------
__global__ void wprepA_kernel(const float* __restrict__ Wv,  float* __restrict__ WvT,
                              const float* __restrict__ Wo,  float* __restrict__ WoT,
                              const float* __restrict__ W1,  float* __restrict__ W1T,
                              const float* __restrict__ W2,  float* __restrict__ W2T)
{
    __shared__ float t[32][33];
    const float* W; float* Wt; int K, N;
    switch (blockIdx.z) {
        case 0: W = Wv; Wt = WvT; K = DIM; N = DIM; break;
        case 1: W = Wo; Wt = WoT; K = DIM; N = DIM; break;
        case 2: W = W1; Wt = W1T; K = DIM; N = DFF; break;
        default:W = W2; Wt = W2T; K = DFF; N = DIM; break;
    }
    const int bx = blockIdx.x * 32;
    const int by = blockIdx.y * 32;
    if (bx >= N || by >= K) return;
    const int x = threadIdx.x, y = threadIdx.y;
    #pragma unroll
    for (int i = 0; i < 32; i += 8)
        t[y + i][x] = W[(size_t)(by + y + i) * N + bx + x];
    __syncthreads();
    #pragma unroll
    for (int i = 0; i < 32; i += 8)
        Wt[(size_t)(bx + y + i) * K + by + x] = t[x][y + i];
}

// ---------------- weight prep B: WoaT = [W_off^T ; W_attn^T] ----------------
__global__ void wprepB_kernel(const float* __restrict__ Woff, const float* __restrict__ boff,
                              const float* __restrict__ Watt, const float* __restrict__ batt,
                              float* __restrict__ WoaT, float* __restrict__ boa)
{
    __shared__ float t[32][33];
    const int bx = blockIdx.x * 32;
    const int by = blockIdx.y * 32;
    const int x = threadIdx.x, y = threadIdx.y;
    const bool isAtt = (bx >= 256);
    const float* W = isAtt ? Watt : Woff;
    const int    nN = isAtt ? 128 : 256;
    const int    nb = isAtt ? bx - 256 : bx;
    #pragma unroll
    for (int i = 0; i < 32; i += 8)
        t[y + i][x] = W[(size_t)(by + y + i) * nN + nb + x];
    __syncthreads();
    #pragma unroll
    for (int i = 0; i < 32; i += 8)
        WoaT[(size_t)(bx + y + i) * DIM + by + x] = t[x][y + i];
    if (blockIdx.y == 0 && y == 0) {
        int n = bx + x;
        boa[n] = (n < 256) ? boff[n] : batt[n - 256];
    }
}

// ---------------- elementwise q = a + b ----------------
__global__ void addq_kernel(const float* __restrict__ a, const float* __restrict__ b,
                            float* __restrict__ o, int n)
{
    int i = blockIdx.x * blockDim.x + threadIdx.x;
    if (i < n) o[i] = a[i] + b[i];
}

// ---------------- MS-deform sampling (softmax fused), bf16 value ----------
__global__ void msda_kernel(const __nv_bfloat16* __restrict__ value,
                            const float* __restrict__ oa,
                            const float* __restrict__ refpts,
                            float* __restrict__ samp)
{
    const int nq   = blockIdx.x;
    const int h    = threadIdx.x >> 5;
    const int lane = threadIdx.x & 31;
    const int n    = nq / LQ;

    float logit = (lane < 16) ? oa[(size_t)nq * NOA + 256 + h * 16 + lane] : -1e30f;
    float m = logit;
    #pragma unroll
    for (int o = 8; o > 0; o >>= 1) m = fmaxf(m, __shfl_xor_sync(0xffffffffu, m, o, 16));
    float e = (lane < 16) ? __expf(logit - m) : 0.f;
    float s = e;
    #pragma unroll
    for (int o = 8; o > 0; o >>= 1) s += __shfl_xor_sync(0xffffffffu, s, o, 16);
    float w = e / s;

    float offv = oa[(size_t)nq * NOA + h * 32 + lane];
    float refv = (lane < 8) ? refpts[(size_t)nq * 8 + lane] : 0.f;

    const __nv_bfloat16* vbase = value + ((size_t)n * LIN * HEADS + h) * HD + lane;

    float acc = 0.f;
    #pragma unroll
    for (int i = 0; i < 16; i++) {
        const int l = i >> 2;
        const int p = i & 3;
        const float wi   = __shfl_sync(0xffffffffu, w,    i);
        const float offx = __shfl_sync(0xffffffffu, offv, l * 8 + p * 2 + 0);
        const float offy = __shfl_sync(0xffffffffu, offv, l * 8 + p * 2 + 1);
        const float refx = __shfl_sync(0xffffffffu, refv, l * 2 + 0);
        const float refy = __shfl_sync(0xffffffffu, refv, l * 2 + 1);

        const int Hl = c_H[l], Wl = c_W[l], st = c_S[l];
        const float x = refx * (float)Wl + offx - 0.5f;
        const float y = refy * (float)Hl + offy - 0.5f;
        const float x0f = floorf(x), y0f = floorf(y);
        const float fx = x - x0f, fy = y - y0f;
        const int x0 = (int)x0f, y0 = (int)y0f;
        const int x1 = x0 + 1,   y1 = y0 + 1;

        const bool vx0 = (x0 >= 0) & (x0 < Wl);
        const bool vx1 = (x1 >= 0) & (x1 < Wl);
        const bool vy0 = (y0 >= 0) & (y0 < Hl);
        const bool vy1 = (y1 >= 0) & (y1 < Hl);

        float sv = 0.f;
        if (vy0) {
            const __nv_bfloat16* rowp = vbase + (size_t)(st + y0 * Wl) * HEADS * HD;
            if (vx0) sv += (1.f - fx) * (1.f - fy) * __bfloat162float(rowp[(size_t)x0 * HEADS * HD]);
            if (vx1) sv += fx * (1.f - fy)         * __bfloat162float(rowp[(size_t)x1 * HEADS * HD]);
        }
        if (vy1) {
            const __nv_bfloat16* rowp = vbase + (size_t)(st + y1 * Wl) * HEADS * HD;
            if (vx0) sv += (1.f - fx) * fy * __bfloat162float(rowp[(size_t)x0 * HEADS * HD]);
            if (vx1) sv += fx * fy         * __bfloat162float(rowp[(size_t)x1 * HEADS * HD]);
        }
        acc += wi * sv;
    }
    samp[(size_t)nq * 256 + h * 32 + lane] = acc;
}

// ---------------- fused residual + LayerNorm (warp per row) ----------------
__global__ void ln_kernel(const float* __restrict__ a, const float* __restrict__ b,
                          const float* __restrict__ g, const float* __restrict__ be,
                          float* __restrict__ out)
{
    const int row  = blockIdx.x * 8 + (threadIdx.x >> 5);
    const int lane = threadIdx.x & 31;
    const size_t base = (size_t)row * 256;

    float4 a0 = *reinterpret_cast<const float4*>(a + base + lane * 4);
    float4 a1 = *reinterpret_cast<const float4*>(a + base + 128 + lane * 4);
    float4 b0 = *reinterpret_cast<const float4*>(b + base + lane * 4);
    float4 b1 = *reinterpret_cast<const float4*>(b + base + 128 + lane * 4);
    float x0 = a0.x + b0.x, x1 = a0.y + b0.y, x2 = a0.z + b0.z, x3 = a0.w + b0.w;
    float x4 = a1.x + b1.x, x5 = a1.y + b1.y, x6 = a1.z + b1.z, x7 = a1.w + b1.w;

    float s  = x0 + x1 + x2 + x3 + x4 + x5 + x6 + x7;
    float s2 = x0*x0 + x1*x1 + x2*x2 + x3*x3 + x4*x4 + x5*x5 + x6*x6 + x7*x7;
    #pragma unroll
    for (int o = 16; o > 0; o >>= 1) {
        s  += __shfl_xor_sync(0xffffffffu, s,  o);
        s2 += __shfl_xor_sync(0xffffffffu, s2, o);
    }
    const float mean = s * (1.f / 256.f);
    const float rstd = rsqrtf(s2 * (1.f / 256.f) - mean * mean + 1e-5f);

    float4 g0 = *reinterpret_cast<const float4*>(g + lane * 4);
    float4 g1 = *reinterpret_cast<const float4*>(g + 128 + lane * 4);
    float4 e0 = *reinterpret_cast<const float4*>(be + lane * 4);
    float4 e1 = *reinterpret_cast<const float4*>(be + 128 + lane * 4);

    float4 o0, o1;
    o0.x = (x0 - mean) * rstd * g0.x + e0.x;
    o0.y = (x1 - mean) * rstd * g0.y + e0.y;
    o0.z = (x2 - mean) * rstd * g0.z + e0.z;
    o0.w = (x3 - mean) * rstd * g0.w + e0.w;
    o1.x = (x4 - mean) * rstd * g1.x + e1.x;
    o1.y = (x5 - mean) * rstd * g1.y + e1.y;
    o1.z = (x6 - mean) * rstd * g1.z + e1.z;
    o1.w = (x7 - mean) * rstd * g1.w + e1.w;
    *reinterpret_cast<float4*>(out + base + lane * 4)       = o0;
    *reinterpret_cast<float4*>(out + base + 128 + lane * 4) = o1;
}

// ---------------- launch ----------------
extern "C" void kernel_launch(void* const* d_in, const int* in_sizes, int n_in,
                              void* d_out, int out_size)
{
    const float* pre_tgt  = (const float*)d_in[0];
    const float* pre_qpos = (const float*)d_in[1];
    const float* src      = (const float*)d_in[2];
    const float* ref_pts  = (const float*)d_in[3];
    const unsigned char* mask = (const unsigned char*)d_in[4];
    const float* W_value = (const float*)d_in[7];
    const float* b_value = (const float*)d_in[8];
    const float* W_off   = (const float*)d_in[9];
    const float* b_off   = (const float*)d_in[10];
    const float* W_attn  = (const float*)d_in[11];
    const float* b_attn  = (const float*)d_in[12];
    const float* W_out   = (const float*)d_in[13];
    const float* b_out   = (const float*)d_in[14];
    const float* g1      = (const float*)d_in[15];
    const float* be1     = (const float*)d_in[16];
    const float* W1      = (const float*)d_in[17];
    const float* b1      = (const float*)d_in[18];
    const float* W2      = (const float*)d_in[19];
    const float* b2      = (const float*)d_in[20];
    const float* g3      = (const float*)d_in[21];
    const float* be3     = (const float*)d_in[22];

    __nv_bfloat16* p_value;
    float *p_q, *p_oa, *p_samp, *p_ms, *p_tgt, *p_ffh, *p_ff;
    float *p_WvT, *p_WoaT, *p_boa, *p_WoutT, *p_W1T, *p_W2T;
    cudaGetSymbolAddress((void**)&p_value, g_value);
    cudaGetSymbolAddress((void**)&p_q,     g_q);
    cudaGetSymbolAddress((void**)&p_oa,    g_oa);
    cudaGetSymbolAddress((void**)&p_samp,  g_samp);
    cudaGetSymbolAddress((void**)&p_ms,    g_ms);
    cudaGetSymbolAddress((void**)&p_tgt,   g_tgt);
    cudaGetSymbolAddress((void**)&p_ffh,   g_ffh);
    cudaGetSymbolAddress((void**)&p_ff,    g_ff);
    cudaGetSymbolAddress((void**)&p_WvT,   g_WvT);
    cudaGetSymbolAddress((void**)&p_WoaT,  g_WoaT);
    cudaGetSymbolAddress((void**)&p_boa,   g_boa);
    cudaGetSymbolAddress((void**)&p_WoutT, g_WoutT);
    cudaGetSymbolAddress((void**)&p_W1T,   g_W1T);
    cudaGetSymbolAddress((void**)&p_W2T,   g_W2T);

    const int MV = NB * LIN;   // 174080
    dim3 tb(32, 8);

    // 1. q = pre_tgt + pre_query_pos
    addq_kernel<<<(NQ * DIM + 255) / 256, 256>>>(pre_tgt, pre_qpos, p_q, NQ * DIM);
    // 2-3. weight prep
    wprepA_kernel<<<dim3(16, 16, 4), tb>>>(W_value, p_WvT, W_out, p_WoutT, W1, p_W1T, W2, p_W2T);
    wprepB_kernel<<<dim3(12, 8), tb>>>(W_off, b_off, W_attn, b_attn, p_WoaT, p_boa);
    // 4. value = mask(src @ Wv + bv) -> bf16   [174080, 256]
    mma_gemm_v5<0, true, 1><<<dim3(2, MV / 128), 256>>>(
        src, p_WvT, b_value, p_value, MV, DIM, DIM, mask);
    // 5. oa = q @ [Woff|Wattn] + [boff|battn]   (tf32 — guards sampling coords)
    mma_gemm_tf32<0><<<dim3(NOA / 128, (NQ + 127) / 128), 256>>>(
        p_q, p_WoaT, p_boa, p_oa, NQ, NOA, DIM);
    // 6. sampling
    msda_kernel<<<NQ, 256>>>(p_value, p_oa, ref_pts, p_samp);
    // 7. ms = samp @ Wout + bout
    mma_gemm_v5<0, false, 0><<<dim3(2, (NQ + 127) / 128), 256>>>(
        p_samp, p_WoutT, b_out, p_ms, NQ, DIM, DIM, nullptr);
    // 8. tgt = LN(pre_tgt + ms)
    ln_kernel<<<NQ / 8, 256>>>(pre_tgt, p_ms, g1, be1, p_tgt);
    // 9. ffh = relu(tgt @ W1 + b1)   [8000, 512]
    mma_gemm_v5<1, false, 0><<<dim3(4, (NQ + 127) / 128), 256>>>(
        p_tgt, p_W1T, b1, p_ffh, NQ, DFF, DIM, nullptr);
    // 10. ff = ffh @ W2 + b2   [8000, 256], K=512
    mma_gemm_v5<0, false, 0><<<dim3(2, (NQ + 127) / 128), 256>>>(
        p_ffh, p_W2T, b2, p_ff, NQ, DIM, DFF, nullptr);
    // 11. out = LN(tgt + ff)
    ln_kernel<<<NQ / 8, 256>>>(p_tgt, p_ff, g3, be3, (float*)d_out);
}

// round 9
// speedup vs baseline: 3.4709x; 1.0647x over previous
#include <cuda_runtime.h>
#include <cuda_bf16.h>
#include <cstdint>

// ---------------- Problem constants ----------------
#define NB   8
#define LQ   1000
#define NQ   (NB*LQ)
#define DIM  256
#define HEADS 8
#define HD   32
#define LIN  21760
#define DFF  512
#define NOA  384    // concat off(256) + attn(128)

__device__ __constant__ int c_H[4]  = {128, 64, 32, 16};
__device__ __constant__ int c_W[4]  = {128, 64, 32, 16};
__device__ __constant__ int c_S[4]  = {0, 16384, 20480, 21504};

// ---------------- Scratch ----------------
__device__ __nv_bfloat16 g_value[(size_t)LIN * NB * DIM];   // 89 MB (bf16)
__device__ float g_oa   [(size_t)NQ * NOA];
__device__ float g_samp [(size_t)NQ * DIM];
__device__ float g_ms   [(size_t)NQ * DIM];
__device__ float g_tgt  [(size_t)NQ * DIM];
__device__ float g_ffh  [(size_t)NQ * DFF];
__device__ float g_ff   [(size_t)NQ * DIM];
__device__ __nv_bfloat16 g_WvTb [DIM * DIM];   // bf16 transposed weights
__device__ __nv_bfloat16 g_WoutTb[DIM * DIM];
__device__ __nv_bfloat16 g_W1Tb [DFF * DIM];
__device__ __nv_bfloat16 g_W2Tb [DIM * DFF];
__device__ float g_WoaT [NOA * DIM];           // fp32 (tf32 path)
__device__ float g_boa  [NOA];

// ---------------- helpers ----------------
__device__ __forceinline__ float tf32r(float x) {
    uint32_t u;
    asm("cvt.rna.tf32.f32 %0, %1;" : "=r"(u) : "f"(x));
    return __uint_as_float(u);
}
__device__ __forceinline__ void mma_tf32(float* d, const uint32_t* a, const uint32_t* b) {
    asm volatile(
        "mma.sync.aligned.m16n8k8.row.col.f32.tf32.tf32.f32 "
        "{%0,%1,%2,%3}, {%4,%5,%6,%7}, {%8,%9}, {%0,%1,%2,%3};"
        : "+f"(d[0]), "+f"(d[1]), "+f"(d[2]), "+f"(d[3])
        : "r"(a[0]), "r"(a[1]), "r"(a[2]), "r"(a[3]), "r"(b[0]), "r"(b[1]));
}
__device__ __forceinline__ void mma_bf16(float* d, const uint32_t* a, const uint32_t* b) {
    asm volatile(
        "mma.sync.aligned.m16n8k16.row.col.f32.bf16.bf16.f32 "
        "{%0,%1,%2,%3}, {%4,%5,%6,%7}, {%8,%9}, {%0,%1,%2,%3};"
        : "+f"(d[0]), "+f"(d[1]), "+f"(d[2]), "+f"(d[3])
        : "r"(a[0]), "r"(a[1]), "r"(a[2]), "r"(a[3]), "r"(b[0]), "r"(b[1]));
}
__device__ __forceinline__ void ldmx4(uint32_t* r, uint32_t addr) {
    asm volatile("ldmatrix.sync.aligned.m8n8.x4.shared.b16 {%0,%1,%2,%3}, [%4];"
        : "=r"(r[0]), "=r"(r[1]), "=r"(r[2]), "=r"(r[3]) : "r"(addr));
}
__device__ __forceinline__ uint32_t packbf(float lo, float hi) {
    __nv_bfloat162 h = __floats2bfloat162_rn(lo, hi);
    return *reinterpret_cast<uint32_t*>(&h);
}
__device__ __forceinline__ void cpa16(uint32_t dst, const void* src) {
    asm volatile("cp.async.cg.shared.global [%0], [%1], 16;" :: "r"(dst), "l"(src) : "memory");
}
#define CPA_COMMIT() asm volatile("cp.async.commit_group;" ::: "memory")
#define CPA_WAIT0()  asm volatile("cp.async.wait_group 0;"  ::: "memory")
// 64B-row swizzle: XOR 16B-group bits [4:5] with row bits (addr bits [7:8])
#define SW64(o) ((uint32_t)(o) ^ (((uint32_t)(o) >> 3) & 0x30u))

// ================= bf16 mma GEMM v6: C = A(fp32) @ Bb(bf16,[N,K])^T + bias =========
// BM=128, BN=128, BK=32. 256 threads (8 warps 2x4, warp tile 64x32).
// A: LDG+cvt+STS register path. B: cp.async 16B direct (weights pre-converted).
// Double-buffered swizzled smem (32KB), 2 CTAs/SM. K mult of 32, N mult of 128.
template<int ACT, bool MASK, int OUT>
__global__ void __launch_bounds__(256, 2) mma_gemm_v6(
    const float* __restrict__ A, const __nv_bfloat16* __restrict__ Bb,
    const float* __restrict__ bias, void* __restrict__ Cv,
    int M, int N, int K, const unsigned char* __restrict__ rowmask)
{
    __shared__ __align__(128) __nv_bfloat16 As[2][128 * 32];   // 2 x 8 KB
    __shared__ __align__(128) __nv_bfloat16 Bs[2][128 * 32];   // 2 x 8 KB

    const int tid  = threadIdx.x;
    const int lane = tid & 31;
    const int wid  = tid >> 5;
    const int wr   = wid & 1;       // 2 warp rows of 64
    const int wc   = wid >> 1;      // 4 warp cols of 32
    const int gid  = lane >> 2;
    const int tig  = lane & 3;
    const int brow = blockIdx.y * 128;
    const int bcol = blockIdx.x * 128;

    // A staging: row = tid>>3 (+32i), 16B col group
    const int r_st = tid >> 3;
    const int kq   = (tid & 7) * 4;
    const int sts_col = (tid & 7) * 8;
    // B cp.async: row = tid>>2 (+64), 16B col group
    const int b_row_cp = tid >> 2;
    const int b_cg     = (tid & 3);

    float acc[4][4][4];
    #pragma unroll
    for (int i = 0; i < 4; i++)
        #pragma unroll
        for (int j = 0; j < 4; j++)
            #pragma unroll
            for (int l = 0; l < 4; l++) acc[i][j][l] = 0.f;

    const uint32_t asb = (uint32_t)__cvta_generic_to_shared(&As[0][0]);
    const uint32_t bsb = (uint32_t)__cvta_generic_to_shared(&Bs[0][0]);
    const uint32_t bufoff = 128 * 32 * 2;   // 8 KB

    const int a_row = (lane & 7) + ((lane >> 3) & 1) * 8;
    const int a_col = (lane >> 4) * 16;
    const int b_row = (lane & 7) + ((lane >> 4) & 1) * 8;
    const int b_col = ((lane >> 3) & 1) * 16;

    uint2 pa[4];

    #define LD_A(kc) do {                                                               \
        _Pragma("unroll")                                                               \
        for (int i = 0; i < 4; i++) {                                                   \
            int gr = brow + r_st + 32 * i; if (gr >= M) gr = M - 1;                     \
            float4 v = *reinterpret_cast<const float4*>(A + (size_t)gr * K + (kc) + kq);\
            pa[i].x = packbf(v.x, v.y); pa[i].y = packbf(v.z, v.w);                     \
        }                                                                               \
    } while (0)

    #define ST_A(buf) do {                                                              \
        char* sa = reinterpret_cast<char*>(&As[buf][0]);                                \
        _Pragma("unroll")                                                               \
        for (int i = 0; i < 4; i++)                                                     \
            *reinterpret_cast<uint2*>(sa + SW64((r_st + 32 * i) * 64 + sts_col)) = pa[i];\
    } while (0)

    #define CPA_B(kc, buf) do {                                                         \
        _Pragma("unroll")                                                               \
        for (int j = 0; j < 2; j++) {                                                   \
            int row = b_row_cp + 64 * j;                                                \
            cpa16(bsb + (buf) * bufoff + SW64(row * 64 + b_cg * 16),                    \
                  Bb + (size_t)(bcol + row) * K + (kc) + b_cg * 8);                     \
        }                                                                               \
    } while (0)

    const int KT = K >> 5;
    CPA_B(0, 0);
    CPA_COMMIT();
    LD_A(0);
    ST_A(0);
    CPA_WAIT0();
    __syncthreads();

    for (int kt = 0; kt < KT; kt++) {
        const int buf = kt & 1;
        if (kt + 1 < KT) {
            CPA_B((kt + 1) * 32, buf ^ 1);
            CPA_COMMIT();
            LD_A((kt + 1) * 32);
        }

        const uint32_t ab = asb + buf * bufoff;
        const uint32_t bb = bsb + buf * bufoff;
        #pragma unroll
        for (int ks = 0; ks < 2; ks++) {
            uint32_t af[4][4], bfq[2][4];
            #pragma unroll
            for (int mt = 0; mt < 4; mt++)
                ldmx4(af[mt], ab + SW64((wr * 64 + mt * 16 + a_row) * 64 + a_col + ks * 32));
            #pragma unroll
            for (int p = 0; p < 2; p++)
                ldmx4(bfq[p], bb + SW64((wc * 32 + p * 16 + b_row) * 64 + b_col + ks * 32));
            #pragma unroll
            for (int mt = 0; mt < 4; mt++)
                #pragma unroll
                for (int nt = 0; nt < 4; nt++)
                    mma_bf16(acc[mt][nt], af[mt], &bfq[nt >> 1][(nt & 1) * 2]);
        }

        if (kt + 1 < KT) {
            ST_A(buf ^ 1);     // other buffer: everyone finished reading it last kt
            CPA_WAIT0();
            __syncthreads();
        }
    }
    #undef LD_A
    #undef ST_A
    #undef CPA_B

    float* Cf = (float*)Cv;
    __nv_bfloat16* Cb = (__nv_bfloat16*)Cv;

    #pragma unroll
    for (int mt = 0; mt < 4; mt++) {
        const int r0 = brow + wr * 64 + mt * 16 + gid;
        const int r1 = r0 + 8;
        const bool v0 = r0 < M, v1 = r1 < M;
        bool z0 = false, z1 = false;
        if (MASK) {
            if (v0) z0 = (rowmask[r0] != 0);
            if (v1) z1 = (rowmask[r1] != 0);
        }
        #pragma unroll
        for (int nt = 0; nt < 4; nt++) {
            const int col = bcol + wc * 32 + nt * 8 + 2 * tig;
            const float b0 = bias[col], b1 = bias[col + 1];
            float2 u, v;
            u.x = acc[mt][nt][0] + b0; u.y = acc[mt][nt][1] + b1;
            v.x = acc[mt][nt][2] + b0; v.y = acc[mt][nt][3] + b1;
            if (ACT == 1) {
                u.x = fmaxf(u.x, 0.f); u.y = fmaxf(u.y, 0.f);
                v.x = fmaxf(v.x, 0.f); v.y = fmaxf(v.y, 0.f);
            }
            if (MASK) {
                if (z0) { u.x = 0.f; u.y = 0.f; }
                if (z1) { v.x = 0.f; v.y = 0.f; }
            }
            if (OUT == 0) {
                if (v0) *reinterpret_cast<float2*>(Cf + (size_t)r0 * N + col) = u;
                if (v1) *reinterpret_cast<float2*>(Cf + (size_t)r1 * N + col) = v;
            } else {
                __nv_bfloat162 hu = __floats2bfloat162_rn(u.x, u.y);
                __nv_bfloat162 hv = __floats2bfloat162_rn(v.x, v.y);
                if (v0) *reinterpret_cast<__nv_bfloat162*>(Cb + (size_t)r0 * N + col) = hu;
                if (v1) *reinterpret_cast<__nv_bfloat162*>(Cb + (size_t)r1 * N + col) = hv;
            }
        }
    }
}

// ================= tf32 mma GEMM (oa GEMM; optional fused A = A + A2) ============
#define SMS 20
template<int ADDQ>
__global__ void __launch_bounds__(256, 2) mma_gemm_tf32(
    const float* __restrict__ A, const float* __restrict__ A2,
    const float* __restrict__ Bt,
    const float* __restrict__ bias, float* __restrict__ C,
    int M, int N, int K)
{
    __shared__ float As[2][128 * SMS];
    __shared__ float Bs[2][128 * SMS];

    const int tid  = threadIdx.x;
    const int lane = tid & 31;
    const int wid  = tid >> 5;
    const int wr   = wid & 3;
    const int wc   = wid >> 2;
    const int gid  = lane >> 2;
    const int tig  = lane & 3;
    const int brow = blockIdx.y * 128;
    const int bcol = blockIdx.x * 128;

    const int r_st = tid >> 2;
    const int k_st = (tid & 3) * 4;

    float acc[2][8][4];
    #pragma unroll
    for (int i = 0; i < 2; i++)
        #pragma unroll
        for (int j = 0; j < 8; j++)
            #pragma unroll
            for (int l = 0; l < 4; l++) acc[i][j][l] = 0.f;

    const int KT = K >> 4;
    float4 ra[2], rb[2];

    #define LD_T(kc) do {                                                              \
        _Pragma("unroll")                                                              \
        for (int i = 0; i < 2; i++) {                                                  \
            int r = r_st + i * 64;                                                     \
            int garow = brow + r; if (garow >= M) garow = M - 1;                       \
            ra[i] = *reinterpret_cast<const float4*>(A + (size_t)garow * K + (kc) + k_st); \
            if (ADDQ) {                                                                \
                float4 q2 = *reinterpret_cast<const float4*>(A2 + (size_t)garow * K + (kc) + k_st); \
                ra[i].x += q2.x; ra[i].y += q2.y; ra[i].z += q2.z; ra[i].w += q2.w;    \
            }                                                                          \
            rb[i] = *reinterpret_cast<const float4*>(Bt + (size_t)(bcol + r) * K + (kc) + k_st); \
        }                                                                              \
    } while (0)

    #define ST_T(buf) do {                                                             \
        _Pragma("unroll")                                                              \
        for (int i = 0; i < 2; i++) {                                                  \
            int r = r_st + i * 64;                                                     \
            float4 av = make_float4(tf32r(ra[i].x), tf32r(ra[i].y), tf32r(ra[i].z), tf32r(ra[i].w)); \
            float4 bv = make_float4(tf32r(rb[i].x), tf32r(rb[i].y), tf32r(rb[i].z), tf32r(rb[i].w)); \
            *reinterpret_cast<float4*>(&As[buf][r * SMS + k_st]) = av;                 \
            *reinterpret_cast<float4*>(&Bs[buf][r * SMS + k_st]) = bv;                 \
        }                                                                              \
    } while (0)

    LD_T(0);
    ST_T(0);
    __syncthreads();

    for (int kt = 0; kt < KT; kt++) {
        const int buf = kt & 1;
        if (kt + 1 < KT) LD_T((kt + 1) * 16);

        const float* as = As[buf];
        const float* bs = Bs[buf];
        #pragma unroll
        for (int ks = 0; ks < 2; ks++) {
            const int k0 = ks * 8;
            uint32_t af[2][4];
            #pragma unroll
            for (int mt = 0; mt < 2; mt++) {
                const int mb = wr * 32 + mt * 16;
                af[mt][0] = __float_as_uint(as[(mb + gid    ) * SMS + k0 + tig    ]);
                af[mt][1] = __float_as_uint(as[(mb + gid + 8) * SMS + k0 + tig    ]);
                af[mt][2] = __float_as_uint(as[(mb + gid    ) * SMS + k0 + tig + 4]);
                af[mt][3] = __float_as_uint(as[(mb + gid + 8) * SMS + k0 + tig + 4]);
            }
            #pragma unroll
            for (int nt = 0; nt < 8; nt++) {
                const int nb = wc * 64 + nt * 8 + gid;
                uint32_t bfr[2];
                bfr[0] = __float_as_uint(bs[nb * SMS + k0 + tig    ]);
                bfr[1] = __float_as_uint(bs[nb * SMS + k0 + tig + 4]);
                mma_tf32(acc[0][nt], af[0], bfr);
                mma_tf32(acc[1][nt], af[1], bfr);
            }
        }
        if (kt + 1 < KT) {
            ST_T(buf ^ 1);
            __syncthreads();
        }
    }
    #undef LD_T
    #undef ST_T

    #pragma unroll
    for (int mt = 0; mt < 2; mt++) {
        const int r0 = brow + wr * 32 + mt * 16 + gid;
        const int r1 = r0 + 8;
        const bool v0 = r0 < M, v1 = r1 < M;
        #pragma unroll
        for (int nt = 0; nt < 8; nt++) {
            const int col = bcol + wc * 64 + nt * 8 + 2 * tig;
            const float b0 = bias[col], b1 = bias[col + 1];
            float2 u, v;
            u.x = acc[mt][nt][0] + b0; u.y = acc[mt][nt][1] + b1;
            v.x = acc[mt][nt][2] + b0; v.y = acc[mt][nt][3] + b1;
            if (v0) *reinterpret_cast<float2*>(C + (size_t)r0 * N + col) = u;
            if (v1) *reinterpret_cast<float2*>(C + (size_t)r1 * N + col) = v;
        }
    }
}

// ---------------- batched weight prep A: transpose -> bf16 ----------------
__global__ void wprepA_kernel(const float* __restrict__ Wv,  __nv_bfloat16* __restrict__ WvT,
                              const float* __restrict__ Wo,  __nv_bfloat16* __restrict__ WoT,
                              const float* __restrict__ W1,  __nv_bfloat16* __restrict__ W1T,
                              const float* __restrict__ W2,  __nv_bfloat16* __restrict__ W2T)
{
    __shared__ float t[32][33];
    const float* W; __nv_bfloat16* Wt; int K, N;
    switch (blockIdx.z) {
        case 0: W = Wv; Wt = WvT; K = DIM; N = DIM; break;
        case 1: W = Wo; Wt = WoT; K = DIM; N = DIM; break;
        case 2: W = W1; Wt = W1T; K = DIM; N = DFF; break;
        default:W = W2; Wt = W2T; K = DFF; N = DIM; break;
    }
    const int bx = blockIdx.x * 32;
    const int by = blockIdx.y * 32;
    if (bx >= N || by >= K) return;
    const int x = threadIdx.x, y = threadIdx.y;
    #pragma unroll
    for (int i = 0; i < 32; i += 8)
        t[y + i][x] = W[(size_t)(by + y + i) * N + bx + x];
    __syncthreads();
    #pragma unroll
    for (int i = 0; i < 32; i += 8)
        Wt[(size_t)(bx + y + i) * K + by + x] = __float2bfloat16(t[x][y + i]);
}

// ---------------- weight prep B: WoaT = [W_off^T ; W_attn^T] (fp32) ------------
__global__ void wprepB_kernel(const float* __restrict__ Woff, const float* __restrict__ boff,
                              const float* __restrict__ Watt, const float* __restrict__ batt,
                              float* __restrict__ WoaT, float* __restrict__ boa)
{
    __shared__ float t[32][33];
    const int bx = blockIdx.x * 32;
    const int by = blockIdx.y * 32;
    const int x = threadIdx.x, y = threadIdx.y;
    const bool isAtt = (bx >= 256);
    const float* W = isAtt ? Watt : Woff;
    const int    nN = isAtt ? 128 : 256;
    const int    nb = isAtt ? bx - 256 : bx;
    #pragma unroll
    for (int i = 0; i < 32; i += 8)
        t[y + i][x] = W[(size_t)(by + y + i) * nN + nb + x];
    __syncthreads();
    #pragma unroll
    for (int i = 0; i < 32; i += 8)
        WoaT[(size_t)(bx + y + i) * DIM + by + x] = t[x][y + i];
    if (blockIdx.y == 0 && y == 0) {
        int n = bx + x;
        boa[n] = (n < 256) ? boff[n] : batt[n - 256];
    }
}

// ---------------- MS-deform sampling (softmax fused), bf16 value ----------
__global__ void msda_kernel(const __nv_bfloat16* __restrict__ value,
                            const float* __restrict__ oa,
                            const float* __restrict__ refpts,
                            float* __restrict__ samp)
{
    const int nq   = blockIdx.x;
    const int h    = threadIdx.x >> 5;
    const int lane = threadIdx.x & 31;
    const int n    = nq / LQ;

    float logit = (lane < 16) ? oa[(size_t)nq * NOA + 256 + h * 16 + lane] : -1e30f;
    float m = logit;
    #pragma unroll
    for (int o = 8; o > 0; o >>= 1) m = fmaxf(m, __shfl_xor_sync(0xffffffffu, m, o, 16));
    float e = (lane < 16) ? __expf(logit - m) : 0.f;
    float s = e;
    #pragma unroll
    for (int o = 8; o > 0; o >>= 1) s += __shfl_xor_sync(0xffffffffu, s, o, 16);
    float w = e / s;

    float offv = oa[(size_t)nq * NOA + h * 32 + lane];
    float refv = (lane < 8) ? refpts[(size_t)nq * 8 + lane] : 0.f;

    const __nv_bfloat16* vbase = value + ((size_t)n * LIN * HEADS + h) * HD + lane;

    float acc = 0.f;
    #pragma unroll
    for (int i = 0; i < 16; i++) {
        const int l = i >> 2;
        const int p = i & 3;
        const float wi   = __shfl_sync(0xffffffffu, w,    i);
        const float offx = __shfl_sync(0xffffffffu, offv, l * 8 + p * 2 + 0);
        const float offy = __shfl_sync(0xffffffffu, offv, l * 8 + p * 2 + 1);
        const float refx = __shfl_sync(0xffffffffu, refv, l * 2 + 0);
        const float refy = __shfl_sync(0xffffffffu, refv, l * 2 + 1);

        const int Hl = c_H[l], Wl = c_W[l], st = c_S[l];
        const float x = refx * (float)Wl + offx - 0.5f;
        const float y = refy * (float)Hl + offy - 0.5f;
        const float x0f = floorf(x), y0f = floorf(y);
        const float fx = x - x0f, fy = y - y0f;
        const int x0 = (int)x0f, y0 = (int)y0f;
        const int x1 = x0 + 1,   y1 = y0 + 1;

        const bool vx0 = (x0 >= 0) & (x0 < Wl);
        const bool vx1 = (x1 >= 0) & (x1 < Wl);
        const bool vy0 = (y0 >= 0) & (y0 < Hl);
        const bool vy1 = (y1 >= 0) & (y1 < Hl);

        float sv = 0.f;
        if (vy0) {
            const __nv_bfloat16* rowp = vbase + (size_t)(st + y0 * Wl) * HEADS * HD;
            if (vx0) sv += (1.f - fx) * (1.f - fy) * __bfloat162float(rowp[(size_t)x0 * HEADS * HD]);
            if (vx1) sv += fx * (1.f - fy)         * __bfloat162float(rowp[(size_t)x1 * HEADS * HD]);
        }
        if (vy1) {
            const __nv_bfloat16* rowp = vbase + (size_t)(st + y1 * Wl) * HEADS * HD;
            if (vx0) sv += (1.f - fx) * fy * __bfloat162float(rowp[(size_t)x0 * HEADS * HD]);
            if (vx1) sv += fx * fy         * __bfloat162float(rowp[(size_t)x1 * HEADS * HD]);
        }
        acc += wi * sv;
    }
    samp[(size_t)nq * 256 + h * 32 + lane] = acc;
}

// ---------------- fused residual + LayerNorm (warp per row) ----------------
__global__ void ln_kernel(const float* __restrict__ a, const float* __restrict__ b,
                          const float* __restrict__ g, const float* __restrict__ be,
                          float* __restrict__ out)
{
    const int row  = blockIdx.x * 8 + (threadIdx.x >> 5);
    const int lane = threadIdx.x & 31;
    const size_t base = (size_t)row * 256;

    float4 a0 = *reinterpret_cast<const float4*>(a + base + lane * 4);
    float4 a1 = *reinterpret_cast<const float4*>(a + base + 128 + lane * 4);
    float4 b0 = *reinterpret_cast<const float4*>(b + base + lane * 4);
    float4 b1 = *reinterpret_cast<const float4*>(b + base + 128 + lane * 4);
    float x0 = a0.x + b0.x, x1 = a0.y + b0.y, x2 = a0.z + b0.z, x3 = a0.w + b0.w;
    float x4 = a1.x + b1.x, x5 = a1.y + b1.y, x6 = a1.z + b1.z, x7 = a1.w + b1.w;

    float s  = x0 + x1 + x2 + x3 + x4 + x5 + x6 + x7;
    float s2 = x0*x0 + x1*x1 + x2*x2 + x3*x3 + x4*x4 + x5*x5 + x6*x6 + x7*x7;
    #pragma unroll
    for (int o = 16; o > 0; o >>= 1) {
        s  += __shfl_xor_sync(0xffffffffu, s,  o);
        s2 += __shfl_xor_sync(0xffffffffu, s2, o);
    }
    const float mean = s * (1.f / 256.f);
    const float rstd = rsqrtf(s2 * (1.f / 256.f) - mean * mean + 1e-5f);

    float4 g0 = *reinterpret_cast<const float4*>(g + lane * 4);
    float4 g1 = *reinterpret_cast<const float4*>(g + 128 + lane * 4);
    float4 e0 = *reinterpret_cast<const float4*>(be + lane * 4);
    float4 e1 = *reinterpret_cast<const float4*>(be + 128 + lane * 4);

    float4 o0, o1;
    o0.x = (x0 - mean) * rstd * g0.x + e0.x;
    o0.y = (x1 - mean) * rstd * g0.y + e0.y;
    o0.z = (x2 - mean) * rstd * g0.z + e0.z;
    o0.w = (x3 - mean) * rstd * g0.w + e0.w;
    o1.x = (x4 - mean) * rstd * g1.x + e1.x;
    o1.y = (x5 - mean) * rstd * g1.y + e1.y;
    o1.z = (x6 - mean) * rstd * g1.z + e1.z;
    o1.w = (x7 - mean) * rstd * g1.w + e1.w;
    *reinterpret_cast<float4*>(out + base + lane * 4)       = o0;
    *reinterpret_cast<float4*>(out + base + 128 + lane * 4) = o1;
}

// ---------------- launch ----------------
extern "C" void kernel_launch(void* const* d_in, const int* in_sizes, int n_in,
                              void* d_out, int out_size)
{
    const float* pre_tgt  = (const float*)d_in[0];
    const float* pre_qpos = (const float*)d_in[1];
    const float* src      = (const float*)d_in[2];
    const float* ref_pts  = (const float*)d_in[3];
    const unsigned char* mask = (const unsigned char*)d_in[4];
    const float* W_value = (const float*)d_in[7];
    const float* b_value = (const float*)d_in[8];
    const float* W_off   = (const float*)d_in[9];
    const float* b_off   = (const float*)d_in[10];
    const float* W_attn  = (const float*)d_in[11];
    const float* b_attn  = (const float*)d_in[12];
    const float* W_out   = (const float*)d_in[13];
    const float* b_out   = (const float*)d_in[14];
    const float* g1      = (const float*)d_in[15];
    const float* be1     = (const float*)d_in[16];
    const float* W1      = (const float*)d_in[17];
    const float* b1      = (const float*)d_in[18];
    const float* W2      = (const float*)d_in[19];
    const float* b2      = (const float*)d_in[20];
    const float* g3      = (const float*)d_in[21];
    const float* be3     = (const float*)d_in[22];

    __nv_bfloat16 *p_value, *p_WvTb, *p_WoutTb, *p_W1Tb, *p_W2Tb;
    float *p_oa, *p_samp, *p_ms, *p_tgt, *p_ffh, *p_ff, *p_WoaT, *p_boa;
    cudaGetSymbolAddress((void**)&p_value, g_value);
    cudaGetSymbolAddress((void**)&p_oa,    g_oa);
    cudaGetSymbolAddress((void**)&p_samp,  g_samp);
    cudaGetSymbolAddress((void**)&p_ms,    g_ms);
    cudaGetSymbolAddress((void**)&p_tgt,   g_tgt);
    cudaGetSymbolAddress((void**)&p_ffh,   g_ffh);
    cudaGetSymbolAddress((void**)&p_ff,    g_ff);
    cudaGetSymbolAddress((void**)&p_WvTb,  g_WvTb);
    cudaGetSymbolAddress((void**)&p_WoutTb,g_WoutTb);
    cudaGetSymbolAddress((void**)&p_W1Tb,  g_W1Tb);
    cudaGetSymbolAddress((void**)&p_W2Tb,  g_W2Tb);
    cudaGetSymbolAddress((void**)&p_WoaT,  g_WoaT);
    cudaGetSymbolAddress((void**)&p_boa,   g_boa);

    const int MV = NB * LIN;   // 174080
    dim3 tb(32, 8);

    // 1-2. weight prep
    wprepA_kernel<<<dim3(16, 16, 4), tb>>>(W_value, p_WvTb, W_out, p_WoutTb, W1, p_W1Tb, W2, p_W2Tb);
    wprepB_kernel<<<dim3(12, 8), tb>>>(W_off, b_off, W_attn, b_attn, p_WoaT, p_boa);
    // 3. value = mask(src @ Wv + bv) -> bf16   [174080, 256]
    mma_gemm_v6<0, true, 1><<<dim3(2, MV / 128), 256>>>(
        src, p_WvTb, b_value, p_value, MV, DIM, DIM, mask);
    // 4. oa = (pre_tgt + pre_qpos) @ [Woff|Wattn] + [boff|battn]   (tf32, fused q-add)
    mma_gemm_tf32<1><<<dim3(NOA / 128, (NQ + 127) / 128), 256>>>(
        pre_tgt, pre_qpos, p_WoaT, p_boa, p_oa, NQ, NOA, DIM);
    // 5. sampling
    msda_kernel<<<NQ, 256>>>(p_value, p_oa, ref_pts, p_samp);
    // 6. ms = samp @ Wout + bout
    mma_gemm_v6<0, false, 0><<<dim3(2, (NQ + 127) / 128), 256>>>(
        p_samp, p_WoutTb, b_out, p_ms, NQ, DIM, DIM, nullptr);
    // 7. tgt = LN(pre_tgt + ms)
    ln_kernel<<<NQ / 8, 256>>>(pre_tgt, p_ms, g1, be1, p_tgt);
    // 8. ffh = relu(tgt @ W1 + b1)   [8000, 512]
    mma_gemm_v6<1, false, 0><<<dim3(4, (NQ + 127) / 128), 256>>>(
        p_tgt, p_W1Tb, b1, p_ffh, NQ, DFF, DIM, nullptr);
    // 9. ff = ffh @ W2 + b2   [8000, 256], K=512
    mma_gemm_v6<0, false, 0><<<dim3(2, (NQ + 127) / 128), 256>>>(
        p_ffh, p_W2Tb, b2, p_ff, NQ, DIM, DFF, nullptr);
    // 10. out = LN(tgt + ff)
    ln_kernel<<<NQ / 8, 256>>>(p_tgt, p_ff, g3, be3, (float*)d_out);
}

// round 10
// speedup vs baseline: 3.9305x; 1.1324x over previous
#include <cuda_runtime.h>
#include <cuda_bf16.h>
#include <cstdint>

// ---------------- Problem constants ----------------
#define NB   8
#define LQ   1000
#define NQ   (NB*LQ)
#define DIM  256
#define HEADS 8
#define HD   32
#define LIN  21760
#define DFF  512
#define NOA  384    // concat off(256) + attn(128)

__device__ __constant__ int c_H[4]  = {128, 64, 32, 16};
__device__ __constant__ int c_W[4]  = {128, 64, 32, 16};
__device__ __constant__ int c_S[4]  = {0, 16384, 20480, 21504};

// ---------------- Scratch ----------------
__device__ __nv_bfloat16 g_value[(size_t)LIN * NB * DIM];   // 89 MB (bf16)
__device__ float g_oa   [(size_t)NQ * NOA];
__device__ float g_samp [(size_t)NQ * DIM];
__device__ float g_ms   [(size_t)NQ * DIM];
__device__ float g_tgt  [(size_t)NQ * DIM];
__device__ float g_ffh  [(size_t)NQ * DFF];
__device__ float g_ff   [(size_t)NQ * DIM];
__device__ __nv_bfloat16 g_WvTb [DIM * DIM];   // bf16 transposed weights
__device__ __nv_bfloat16 g_WoutTb[DIM * DIM];
__device__ __nv_bfloat16 g_W1Tb [DFF * DIM];
__device__ __nv_bfloat16 g_W2Tb [DIM * DFF];
__device__ float g_WoaT [NOA * DIM];           // fp32 (tf32 path)
__device__ float g_boa  [NOA];

// ---------------- helpers ----------------
__device__ __forceinline__ float tf32r(float x) {
    uint32_t u;
    asm("cvt.rna.tf32.f32 %0, %1;" : "=r"(u) : "f"(x));
    return __uint_as_float(u);
}
__device__ __forceinline__ void mma_tf32(float* d, const uint32_t* a, const uint32_t* b) {
    asm volatile(
        "mma.sync.aligned.m16n8k8.row.col.f32.tf32.tf32.f32 "
        "{%0,%1,%2,%3}, {%4,%5,%6,%7}, {%8,%9}, {%0,%1,%2,%3};"
        : "+f"(d[0]), "+f"(d[1]), "+f"(d[2]), "+f"(d[3])
        : "r"(a[0]), "r"(a[1]), "r"(a[2]), "r"(a[3]), "r"(b[0]), "r"(b[1]));
}
__device__ __forceinline__ void mma_bf16(float* d, const uint32_t* a, const uint32_t* b) {
    asm volatile(
        "mma.sync.aligned.m16n8k16.row.col.f32.bf16.bf16.f32 "
        "{%0,%1,%2,%3}, {%4,%5,%6,%7}, {%8,%9}, {%0,%1,%2,%3};"
        : "+f"(d[0]), "+f"(d[1]), "+f"(d[2]), "+f"(d[3])
        : "r"(a[0]), "r"(a[1]), "r"(a[2]), "r"(a[3]), "r"(b[0]), "r"(b[1]));
}
__device__ __forceinline__ void ldmx4(uint32_t* r, uint32_t addr) {
    asm volatile("ldmatrix.sync.aligned.m8n8.x4.shared.b16 {%0,%1,%2,%3}, [%4];"
        : "=r"(r[0]), "=r"(r[1]), "=r"(r[2]), "=r"(r[3]) : "r"(addr));
}
__device__ __forceinline__ uint32_t packbf(float lo, float hi) {
    __nv_bfloat162 h = __floats2bfloat162_rn(lo, hi);
    return *reinterpret_cast<uint32_t*>(&h);
}
__device__ __forceinline__ void cpa16(uint32_t dst, const void* src) {
    asm volatile("cp.async.cg.shared.global [%0], [%1], 16;" :: "r"(dst), "l"(src) : "memory");
}
#define CPA_COMMIT() asm volatile("cp.async.commit_group;" ::: "memory")
#define CPA_WAIT0()  asm volatile("cp.async.wait_group 0;"  ::: "memory")
// 64B-row swizzle
#define SW64(o) ((uint32_t)(o) ^ (((uint32_t)(o) >> 3) & 0x30u))

// ================= bf16 mma GEMM v6: C = A(fp32) @ Bb(bf16,[N,K])^T + bias =========
template<int ACT, bool MASK, int OUT>
__global__ void __launch_bounds__(256, 2) mma_gemm_v6(
    const float* __restrict__ A, const __nv_bfloat16* __restrict__ Bb,
    const float* __restrict__ bias, void* __restrict__ Cv,
    int M, int N, int K, const unsigned char* __restrict__ rowmask)
{
    __shared__ __align__(128) __nv_bfloat16 As[2][128 * 32];
    __shared__ __align__(128) __nv_bfloat16 Bs[2][128 * 32];

    const int tid  = threadIdx.x;
    const int lane = tid & 31;
    const int wid  = tid >> 5;
    const int wr   = wid & 1;
    const int wc   = wid >> 1;
    const int gid  = lane >> 2;
    const int tig  = lane & 3;
    const int brow = blockIdx.y * 128;
    const int bcol = blockIdx.x * 128;

    const int r_st = tid >> 3;
    const int kq   = (tid & 7) * 4;
    const int sts_col = (tid & 7) * 8;
    const int b_row_cp = tid >> 2;
    const int b_cg     = (tid & 3);

    float acc[4][4][4];
    #pragma unroll
    for (int i = 0; i < 4; i++)
        #pragma unroll
        for (int j = 0; j < 4; j++)
            #pragma unroll
            for (int l = 0; l < 4; l++) acc[i][j][l] = 0.f;

    const uint32_t asb = (uint32_t)__cvta_generic_to_shared(&As[0][0]);
    const uint32_t bsb = (uint32_t)__cvta_generic_to_shared(&Bs[0][0]);
    const uint32_t bufoff = 128 * 32 * 2;

    const int a_row = (lane & 7) + ((lane >> 3) & 1) * 8;
    const int a_col = (lane >> 4) * 16;
    const int b_row = (lane & 7) + ((lane >> 4) & 1) * 8;
    const int b_col = ((lane >> 3) & 1) * 16;

    uint2 pa[4];

    #define LD_A(kc) do {                                                               \
        _Pragma("unroll")                                                               \
        for (int i = 0; i < 4; i++) {                                                   \
            int gr = brow + r_st + 32 * i; if (gr >= M) gr = M - 1;                     \
            float4 v = *reinterpret_cast<const float4*>(A + (size_t)gr * K + (kc) + kq);\
            pa[i].x = packbf(v.x, v.y); pa[i].y = packbf(v.z, v.w);                     \
        }                                                                               \
    } while (0)

    #define ST_A(buf) do {                                                              \
        char* sa = reinterpret_cast<char*>(&As[buf][0]);                                \
        _Pragma("unroll")                                                               \
        for (int i = 0; i < 4; i++)                                                     \
            *reinterpret_cast<uint2*>(sa + SW64((r_st + 32 * i) * 64 + sts_col)) = pa[i];\
    } while (0)

    #define CPA_B(kc, buf) do {                                                         \
        _Pragma("unroll")                                                               \
        for (int j = 0; j < 2; j++) {                                                   \
            int row = b_row_cp + 64 * j;                                                \
            cpa16(bsb + (buf) * bufoff + SW64(row * 64 + b_cg * 16),                    \
                  Bb + (size_t)(bcol + row) * K + (kc) + b_cg * 8);                     \
        }                                                                               \
    } while (0)

    const int KT = K >> 5;
    CPA_B(0, 0);
    CPA_COMMIT();
    LD_A(0);
    ST_A(0);
    CPA_WAIT0();
    __syncthreads();

    for (int kt = 0; kt < KT; kt++) {
        const int buf = kt & 1;
        if (kt + 1 < KT) {
            CPA_B((kt + 1) * 32, buf ^ 1);
            CPA_COMMIT();
            LD_A((kt + 1) * 32);
        }

        const uint32_t ab = asb + buf * bufoff;
        const uint32_t bb = bsb + buf * bufoff;
        #pragma unroll
        for (int ks = 0; ks < 2; ks++) {
            uint32_t af[4][4], bfq[2][4];
            #pragma unroll
            for (int mt = 0; mt < 4; mt++)
                ldmx4(af[mt], ab + SW64((wr * 64 + mt * 16 + a_row) * 64 + a_col + ks * 32));
            #pragma unroll
            for (int p = 0; p < 2; p++)
                ldmx4(bfq[p], bb + SW64((wc * 32 + p * 16 + b_row) * 64 + b_col + ks * 32));
            #pragma unroll
            for (int mt = 0; mt < 4; mt++)
                #pragma unroll
                for (int nt = 0; nt < 4; nt++)
                    mma_bf16(acc[mt][nt], af[mt], &bfq[nt >> 1][(nt & 1) * 2]);
        }

        if (kt + 1 < KT) {
            ST_A(buf ^ 1);
            CPA_WAIT0();
            __syncthreads();
        }
    }
    #undef LD_A
    #undef ST_A
    #undef CPA_B

    float* Cf = (float*)Cv;
    __nv_bfloat16* Cb = (__nv_bfloat16*)Cv;

    #pragma unroll
    for (int mt = 0; mt < 4; mt++) {
        const int r0 = brow + wr * 64 + mt * 16 + gid;
        const int r1 = r0 + 8;
        const bool v0 = r0 < M, v1 = r1 < M;
        bool z0 = false, z1 = false;
        if (MASK) {
            if (v0) z0 = (rowmask[r0] != 0);
            if (v1) z1 = (rowmask[r1] != 0);
        }
        #pragma unroll
        for (int nt = 0; nt < 4; nt++) {
            const int col = bcol + wc * 32 + nt * 8 + 2 * tig;
            const float b0 = bias[col], b1 = bias[col + 1];
            float2 u, v;
            u.x = acc[mt][nt][0] + b0; u.y = acc[mt][nt][1] + b1;
            v.x = acc[mt][nt][2] + b0; v.y = acc[mt][nt][3] + b1;
            if (ACT == 1) {
                u.x = fmaxf(u.x, 0.f); u.y = fmaxf(u.y, 0.f);
                v.x = fmaxf(v.x, 0.f); v.y = fmaxf(v.y, 0.f);
            }
            if (MASK) {
                if (z0) { u.x = 0.f; u.y = 0.f; }
                if (z1) { v.x = 0.f; v.y = 0.f; }
            }
            if (OUT == 0) {
                if (v0) *reinterpret_cast<float2*>(Cf + (size_t)r0 * N + col) = u;
                if (v1) *reinterpret_cast<float2*>(Cf + (size_t)r1 * N + col) = v;
            } else {
                __nv_bfloat162 hu = __floats2bfloat162_rn(u.x, u.y);
                __nv_bfloat162 hv = __floats2bfloat162_rn(v.x, v.y);
                if (v0) *reinterpret_cast<__nv_bfloat162*>(Cb + (size_t)r0 * N + col) = hu;
                if (v1) *reinterpret_cast<__nv_bfloat162*>(Cb + (size_t)r1 * N + col) = hv;
            }
        }
    }
}

// ================= tf32 mma GEMM (oa GEMM; fused A = A + A2) ============
#define SMS 20
template<int ADDQ>
__global__ void __launch_bounds__(256, 2) mma_gemm_tf32(
    const float* __restrict__ A, const float* __restrict__ A2,
    const float* __restrict__ Bt,
    const float* __restrict__ bias, float* __restrict__ C,
    int M, int N, int K)
{
    __shared__ float As[2][128 * SMS];
    __shared__ float Bs[2][128 * SMS];

    const int tid  = threadIdx.x;
    const int lane = tid & 31;
    const int wid  = tid >> 5;
    const int wr   = wid & 3;
    const int wc   = wid >> 2;
    const int gid  = lane >> 2;
    const int tig  = lane & 3;
    const int brow = blockIdx.y * 128;
    const int bcol = blockIdx.x * 128;

    const int r_st = tid >> 2;
    const int k_st = (tid & 3) * 4;

    float acc[2][8][4];
    #pragma unroll
    for (int i = 0; i < 2; i++)
        #pragma unroll
        for (int j = 0; j < 8; j++)
            #pragma unroll
            for (int l = 0; l < 4; l++) acc[i][j][l] = 0.f;

    const int KT = K >> 4;
    float4 ra[2], rb[2];

    #define LD_T(kc) do {                                                              \
        _Pragma("unroll")                                                              \
        for (int i = 0; i < 2; i++) {                                                  \
            int r = r_st + i * 64;                                                     \
            int garow = brow + r; if (garow >= M) garow = M - 1;                       \
            ra[i] = *reinterpret_cast<const float4*>(A + (size_t)garow * K + (kc) + k_st); \
            if (ADDQ) {                                                                \
                float4 q2 = *reinterpret_cast<const float4*>(A2 + (size_t)garow * K + (kc) + k_st); \
                ra[i].x += q2.x; ra[i].y += q2.y; ra[i].z += q2.z; ra[i].w += q2.w;    \
            }                                                                          \
            rb[i] = *reinterpret_cast<const float4*>(Bt + (size_t)(bcol + r) * K + (kc) + k_st); \
        }                                                                              \
    } while (0)

    #define ST_T(buf) do {                                                             \
        _Pragma("unroll")                                                              \
        for (int i = 0; i < 2; i++) {                                                  \
            int r = r_st + i * 64;                                                     \
            float4 av = make_float4(tf32r(ra[i].x), tf32r(ra[i].y), tf32r(ra[i].z), tf32r(ra[i].w)); \
            float4 bv = make_float4(tf32r(rb[i].x), tf32r(rb[i].y), tf32r(rb[i].z), tf32r(rb[i].w)); \
            *reinterpret_cast<float4*>(&As[buf][r * SMS + k_st]) = av;                 \
            *reinterpret_cast<float4*>(&Bs[buf][r * SMS + k_st]) = bv;                 \
        }                                                                              \
    } while (0)

    LD_T(0);
    ST_T(0);
    __syncthreads();

    for (int kt = 0; kt < KT; kt++) {
        const int buf = kt & 1;
        if (kt + 1 < KT) LD_T((kt + 1) * 16);

        const float* as = As[buf];
        const float* bs = Bs[buf];
        #pragma unroll
        for (int ks = 0; ks < 2; ks++) {
            const int k0 = ks * 8;
            uint32_t af[2][4];
            #pragma unroll
            for (int mt = 0; mt < 2; mt++) {
                const int mb = wr * 32 + mt * 16;
                af[mt][0] = __float_as_uint(as[(mb + gid    ) * SMS + k0 + tig    ]);
                af[mt][1] = __float_as_uint(as[(mb + gid + 8) * SMS + k0 + tig    ]);
                af[mt][2] = __float_as_uint(as[(mb + gid    ) * SMS + k0 + tig + 4]);
                af[mt][3] = __float_as_uint(as[(mb + gid + 8) * SMS + k0 + tig + 4]);
            }
            #pragma unroll
            for (int nt = 0; nt < 8; nt++) {
                const int nb = wc * 64 + nt * 8 + gid;
                uint32_t bfr[2];
                bfr[0] = __float_as_uint(bs[nb * SMS + k0 + tig    ]);
                bfr[1] = __float_as_uint(bs[nb * SMS + k0 + tig + 4]);
                mma_tf32(acc[0][nt], af[0], bfr);
                mma_tf32(acc[1][nt], af[1], bfr);
            }
        }
        if (kt + 1 < KT) {
            ST_T(buf ^ 1);
            __syncthreads();
        }
    }
    #undef LD_T
    #undef ST_T

    #pragma unroll
    for (int mt = 0; mt < 2; mt++) {
        const int r0 = brow + wr * 32 + mt * 16 + gid;
        const int r1 = r0 + 8;
        const bool v0 = r0 < M, v1 = r1 < M;
        #pragma unroll
        for (int nt = 0; nt < 8; nt++) {
            const int col = bcol + wc * 64 + nt * 8 + 2 * tig;
            const float b0 = bias[col], b1 = bias[col + 1];
            float2 u, v;
            u.x = acc[mt][nt][0] + b0; u.y = acc[mt][nt][1] + b1;
            v.x = acc[mt][nt][2] + b0; v.y = acc[mt][nt][3] + b1;
            if (v0) *reinterpret_cast<float2*>(C + (size_t)r0 * N + col) = u;
            if (v1) *reinterpret_cast<float2*>(C + (size_t)r1 * N + col) = v;
        }
    }
}

// ---------------- unified weight prep: z=0..3 transpose->bf16, z=4 oa concat ------
__global__ void wprep_kernel(const float* __restrict__ Wv,  __nv_bfloat16* __restrict__ WvT,
                             const float* __restrict__ Wo,  __nv_bfloat16* __restrict__ WoT,
                             const float* __restrict__ W1,  __nv_bfloat16* __restrict__ W1T,
                             const float* __restrict__ W2,  __nv_bfloat16* __restrict__ W2T,
                             const float* __restrict__ Woff, const float* __restrict__ boff,
                             const float* __restrict__ Watt, const float* __restrict__ batt,
                             float* __restrict__ WoaT, float* __restrict__ boa)
{
    __shared__ float t[32][33];
    const int x = threadIdx.x, y = threadIdx.y;
    const int z = blockIdx.z;

    if (z == 4) {   // oa concat (fp32 out, [384,256])
        const int bx = blockIdx.x * 32;
        const int by = blockIdx.y * 32;
        if (bx >= NOA || by >= DIM) return;
        const bool isAtt = (bx >= 256);
        const float* W = isAtt ? Watt : Woff;
        const int    nN = isAtt ? 128 : 256;
        const int    nb = isAtt ? bx - 256 : bx;
        #pragma unroll
        for (int i = 0; i < 32; i += 8)
            t[y + i][x] = W[(size_t)(by + y + i) * nN + nb + x];
        __syncthreads();
        #pragma unroll
        for (int i = 0; i < 32; i += 8)
            WoaT[(size_t)(bx + y + i) * DIM + by + x] = t[x][y + i];
        if (blockIdx.y == 0 && y == 0) {
            int n = bx + x;
            boa[n] = (n < 256) ? boff[n] : batt[n - 256];
        }
        return;
    }

    const float* W; __nv_bfloat16* Wt; int K, N;
    switch (z) {
        case 0: W = Wv; Wt = WvT; K = DIM; N = DIM; break;
        case 1: W = Wo; Wt = WoT; K = DIM; N = DIM; break;
        case 2: W = W1; Wt = W1T; K = DIM; N = DFF; break;
        default:W = W2; Wt = W2T; K = DFF; N = DIM; break;
    }
    const int bx = blockIdx.x * 32;
    const int by = blockIdx.y * 32;
    if (bx >= N || by >= K) return;
    #pragma unroll
    for (int i = 0; i < 32; i += 8)
        t[y + i][x] = W[(size_t)(by + y + i) * N + bx + x];
    __syncthreads();
    #pragma unroll
    for (int i = 0; i < 32; i += 8)
        Wt[(size_t)(bx + y + i) * K + by + x] = __float2bfloat16(t[x][y + i]);
}

// ---------------- MS-deform sampling v2: warp = 2 heads, bf16x2 loads -----------
// block = 128 threads (4 warps), grid = NQ. Per warp: heads 2*wh, 2*wh+1.
// lane = g*16 + ci: g = head-in-pair, ci = channel pair (channels 2ci, 2ci+1).
__global__ void __launch_bounds__(128) msda_kernel(
    const __nv_bfloat16* __restrict__ value,
    const float* __restrict__ oa,
    const float* __restrict__ refpts,
    float* __restrict__ samp)
{
    const int nq   = blockIdx.x;
    const int wh   = threadIdx.x >> 5;      // head pair 0..3
    const int lane = threadIdx.x & 31;
    const int g    = lane >> 4;             // head within pair
    const int ci   = lane & 15;             // channel pair
    const int h    = wh * 2 + g;
    const int n    = nq / LQ;

    // logits: 32 contiguous per warp (16 per head); softmax per 16-group
    float logit = oa[(size_t)nq * NOA + 256 + wh * 32 + lane];
    float m = logit;
    #pragma unroll
    for (int o = 8; o > 0; o >>= 1) m = fmaxf(m, __shfl_xor_sync(0xffffffffu, m, o, 16));
    float e = __expf(logit - m);
    float s = e;
    #pragma unroll
    for (int o = 8; o > 0; o >>= 1) s += __shfl_xor_sync(0xffffffffu, s, o, 16);
    const float w = e / s;    // lane g*16+i holds weight for head (2wh+g), point i

    // offsets: heads 2wh,2wh+1 occupy 64 floats; lane l holds (offx, offy) of
    // point i = (l&15) for head g = l>>4 (off index 2i, 2i+1 within head's 32)
    const float2 offv = *reinterpret_cast<const float2*>(oa + (size_t)nq * NOA + wh * 64 + 2 * lane);
    // ref: 8 floats; lanes 0..3 hold level l's (x,y)
    float2 refv = make_float2(0.f, 0.f);
    if (lane < 4) refv = *reinterpret_cast<const float2*>(refpts + (size_t)nq * 8 + 2 * lane);

    const __nv_bfloat16* vbase = value + ((size_t)n * LIN * HEADS + h) * HD + 2 * ci;

    float2 acc = make_float2(0.f, 0.f);
    #pragma unroll
    for (int i = 0; i < 16; i++) {
        const int l = i >> 2;
        const int src = g * 16 + i;
        const float wi   = __shfl_sync(0xffffffffu, w,      src);
        const float offx = __shfl_sync(0xffffffffu, offv.x, src);
        const float offy = __shfl_sync(0xffffffffu, offv.y, src);
        const float refx = __shfl_sync(0xffffffffu, refv.x, l);
        const float refy = __shfl_sync(0xffffffffu, refv.y, l);

        const int Hl = c_H[l], Wl = c_W[l], st = c_S[l];
        const float x = refx * (float)Wl + offx - 0.5f;
        const float y = refy * (float)Hl + offy - 0.5f;
        const float x0f = floorf(x), y0f = floorf(y);
        const float fx = x - x0f, fy = y - y0f;
        const int x0 = (int)x0f, y0 = (int)y0f;
        const int x1 = x0 + 1,   y1 = y0 + 1;

        const bool vx0 = (x0 >= 0) & (x0 < Wl);
        const bool vx1 = (x1 >= 0) & (x1 < Wl);
        const bool vy0 = (y0 >= 0) & (y0 < Hl);
        const bool vy1 = (y1 >= 0) & (y1 < Hl);

        float2 sv = make_float2(0.f, 0.f);
        if (vy0) {
            const __nv_bfloat16* rowp = vbase + (size_t)(st + y0 * Wl) * (HEADS * HD);
            if (vx0) {
                float2 v = __bfloat1622float2(*reinterpret_cast<const __nv_bfloat162*>(rowp + (size_t)x0 * (HEADS * HD)));
                float c = (1.f - fx) * (1.f - fy);
                sv.x += c * v.x; sv.y += c * v.y;
            }
            if (vx1) {
                float2 v = __bfloat1622float2(*reinterpret_cast<const __nv_bfloat162*>(rowp + (size_t)x1 * (HEADS * HD)));
                float c = fx * (1.f - fy);
                sv.x += c * v.x; sv.y += c * v.y;
            }
        }
        if (vy1) {
            const __nv_bfloat16* rowp = vbase + (size_t)(st + y1 * Wl) * (HEADS * HD);
            if (vx0) {
                float2 v = __bfloat1622float2(*reinterpret_cast<const __nv_bfloat162*>(rowp + (size_t)x0 * (HEADS * HD)));
                float c = (1.f - fx) * fy;
                sv.x += c * v.x; sv.y += c * v.y;
            }
            if (vx1) {
                float2 v = __bfloat1622float2(*reinterpret_cast<const __nv_bfloat162*>(rowp + (size_t)x1 * (HEADS * HD)));
                float c = fx * fy;
                sv.x += c * v.x; sv.y += c * v.y;
            }
        }
        acc.x += wi * sv.x;
        acc.y += wi * sv.y;
    }
    *reinterpret_cast<float2*>(samp + (size_t)nq * 256 + h * 32 + 2 * ci) = acc;
}

// ---------------- fused residual + LayerNorm (warp per row) ----------------
__global__ void ln_kernel(const float* __restrict__ a, const float* __restrict__ b,
                          const float* __restrict__ g, const float* __restrict__ be,
                          float* __restrict__ out)
{
    const int row  = blockIdx.x * 8 + (threadIdx.x >> 5);
    const int lane = threadIdx.x & 31;
    const size_t base = (size_t)row * 256;

    float4 a0 = *reinterpret_cast<const float4*>(a + base + lane * 4);
    float4 a1 = *reinterpret_cast<const float4*>(a + base + 128 + lane * 4);
    float4 b0 = *reinterpret_cast<const float4*>(b + base + lane * 4);
    float4 b1 = *reinterpret_cast<const float4*>(b + base + 128 + lane * 4);
    float x0 = a0.x + b0.x, x1 = a0.y + b0.y, x2 = a0.z + b0.z, x3 = a0.w + b0.w;
    float x4 = a1.x + b1.x, x5 = a1.y + b1.y, x6 = a1.z + b1.z, x7 = a1.w + b1.w;

    float s  = x0 + x1 + x2 + x3 + x4 + x5 + x6 + x7;
    float s2 = x0*x0 + x1*x1 + x2*x2 + x3*x3 + x4*x4 + x5*x5 + x6*x6 + x7*x7;
    #pragma unroll
    for (int o = 16; o > 0; o >>= 1) {
        s  += __shfl_xor_sync(0xffffffffu, s,  o);
        s2 += __shfl_xor_sync(0xffffffffu, s2, o);
    }
    const float mean = s * (1.f / 256.f);
    const float rstd = rsqrtf(s2 * (1.f / 256.f) - mean * mean + 1e-5f);

    float4 g0 = *reinterpret_cast<const float4*>(g + lane * 4);
    float4 g1 = *reinterpret_cast<const float4*>(g + 128 + lane * 4);
    float4 e0 = *reinterpret_cast<const float4*>(be + lane * 4);
    float4 e1 = *reinterpret_cast<const float4*>(be + 128 + lane * 4);

    float4 o0, o1;
    o0.x = (x0 - mean) * rstd * g0.x + e0.x;
    o0.y = (x1 - mean) * rstd * g0.y + e0.y;
    o0.z = (x2 - mean) * rstd * g0.z + e0.z;
    o0.w = (x3 - mean) * rstd * g0.w + e0.w;
    o1.x = (x4 - mean) * rstd * g1.x + e1.x;
    o1.y = (x5 - mean) * rstd * g1.y + e1.y;
    o1.z = (x6 - mean) * rstd * g1.z + e1.z;
    o1.w = (x7 - mean) * rstd * g1.w + e1.w;
    *reinterpret_cast<float4*>(out + base + lane * 4)       = o0;
    *reinterpret_cast<float4*>(out + base + 128 + lane * 4) = o1;
}

// ---------------- launch ----------------
extern "C" void kernel_launch(void* const* d_in, const int* in_sizes, int n_in,
                              void* d_out, int out_size)
{
    const float* pre_tgt  = (const float*)d_in[0];
    const float* pre_qpos = (const float*)d_in[1];
    const float* src      = (const float*)d_in[2];
    const float* ref_pts  = (const float*)d_in[3];
    const unsigned char* mask = (const unsigned char*)d_in[4];
    const float* W_value = (const float*)d_in[7];
    const float* b_value = (const float*)d_in[8];
    const float* W_off   = (const float*)d_in[9];
    const float* b_off   = (const float*)d_in[10];
    const float* W_attn  = (const float*)d_in[11];
    const float* b_attn  = (const float*)d_in[12];
    const float* W_out   = (const float*)d_in[13];
    const float* b_out   = (const float*)d_in[14];
    const float* g1      = (const float*)d_in[15];
    const float* be1     = (const float*)d_in[16];
    const float* W1      = (const float*)d_in[17];
    const float* b1      = (const float*)d_in[18];
    const float* W2      = (const float*)d_in[19];
    const float* b2      = (const float*)d_in[20];
    const float* g3      = (const float*)d_in[21];
    const float* be3     = (const float*)d_in[22];

    __nv_bfloat16 *p_value, *p_WvTb, *p_WoutTb, *p_W1Tb, *p_W2Tb;
    float *p_oa, *p_samp, *p_ms, *p_tgt, *p_ffh, *p_ff, *p_WoaT, *p_boa;
    cudaGetSymbolAddress((void**)&p_value, g_value);
    cudaGetSymbolAddress((void**)&p_oa,    g_oa);
    cudaGetSymbolAddress((void**)&p_samp,  g_samp);
    cudaGetSymbolAddress((void**)&p_ms,    g_ms);
    cudaGetSymbolAddress((void**)&p_tgt,   g_tgt);
    cudaGetSymbolAddress((void**)&p_ffh,   g_ffh);
    cudaGetSymbolAddress((void**)&p_ff,    g_ff);
    cudaGetSymbolAddress((void**)&p_WvTb,  g_WvTb);
    cudaGetSymbolAddress((void**)&p_WoutTb,g_WoutTb);
    cudaGetSymbolAddress((void**)&p_W1Tb,  g_W1Tb);
    cudaGetSymbolAddress((void**)&p_W2Tb,  g_W2Tb);
    cudaGetSymbolAddress((void**)&p_WoaT,  g_WoaT);
    cudaGetSymbolAddress((void**)&p_boa,   g_boa);

    const int MV = NB * LIN;   // 174080
    dim3 tb(32, 8);

    // 1. unified weight prep
    wprep_kernel<<<dim3(16, 16, 5), tb>>>(W_value, p_WvTb, W_out, p_WoutTb,
                                          W1, p_W1Tb, W2, p_W2Tb,
                                          W_off, b_off, W_attn, b_attn, p_WoaT, p_boa);
    // 2. value = mask(src @ Wv + bv) -> bf16
    mma_gemm_v6<0, true, 1><<<dim3(2, MV / 128), 256>>>(
        src, p_WvTb, b_value, p_value, MV, DIM, DIM, mask);
    // 3. oa = (pre_tgt + pre_qpos) @ [Woff|Wattn] + [boff|battn]
    mma_gemm_tf32<1><<<dim3(NOA / 128, (NQ + 127) / 128), 256>>>(
        pre_tgt, pre_qpos, p_WoaT, p_boa, p_oa, NQ, NOA, DIM);
    // 4. sampling (launch #4 -> profiled next round)
    msda_kernel<<<NQ, 128>>>(p_value, p_oa, ref_pts, p_samp);
    // 5. ms = samp @ Wout + bout
    mma_gemm_v6<0, false, 0><<<dim3(2, (NQ + 127) / 128), 256>>>(
        p_samp, p_WoutTb, b_out, p_ms, NQ, DIM, DIM, nullptr);
    // 6. tgt = LN(pre_tgt + ms)
    ln_kernel<<<NQ / 8, 256>>>(pre_tgt, p_ms, g1, be1, p_tgt);
    // 7. ffh = relu(tgt @ W1 + b1)
    mma_gemm_v6<1, false, 0><<<dim3(4, (NQ + 127) / 128), 256>>>(
        p_tgt, p_W1Tb, b1, p_ffh, NQ, DFF, DIM, nullptr);
    // 8. ff = ffh @ W2 + b2
    mma_gemm_v6<0, false, 0><<<dim3(2, (NQ + 127) / 128), 256>>>(
        p_ffh, p_W2Tb, b2, p_ff, NQ, DIM, DFF, nullptr);
    // 9. out = LN(tgt + ff)
    ln_kernel<<<NQ / 8, 256>>>(p_tgt, p_ff, g3, be3, (float*)d_out);
}

// round 11
// speedup vs baseline: 4.2623x; 1.0844x over previous
#include <cuda_runtime.h>
#include <cuda_bf16.h>
#include <cstdint>

// ---------------- Problem constants ----------------
#define NB   8
#define LQ   1000
#define NQ   (NB*LQ)
#define DIM  256
#define HEADS 8
#define HD   32
#define LIN  21760
#define DFF  512
#define NOA  384    // concat off(256) + attn(128)

__device__ __constant__ int c_H[4]  = {128, 64, 32, 16};
__device__ __constant__ int c_W[4]  = {128, 64, 32, 16};
__device__ __constant__ int c_S[4]  = {0, 16384, 20480, 21504};

// ---------------- Scratch ----------------
__device__ __nv_bfloat16 g_value[(size_t)LIN * NB * DIM];   // 89 MB (bf16)
__device__ float g_oa   [(size_t)NQ * NOA];
__device__ float g_samp [(size_t)NQ * DIM];
__device__ float g_ms   [(size_t)NQ * DIM];
__device__ float g_tgt  [(size_t)NQ * DIM];
__device__ float g_ffh  [(size_t)NQ * DFF];
__device__ float g_ff   [(size_t)NQ * DIM];
__device__ __nv_bfloat16 g_WvTb [DIM * DIM];
__device__ __nv_bfloat16 g_WoutTb[DIM * DIM];
__device__ __nv_bfloat16 g_W1Tb [DFF * DIM];
__device__ __nv_bfloat16 g_W2Tb [DIM * DFF];
__device__ __nv_bfloat16 g_WoaTh[NOA * DIM];   // hi/lo bf16 decomposition
__device__ __nv_bfloat16 g_WoaTl[NOA * DIM];
__device__ float g_boa  [NOA];

// ---------------- helpers ----------------
__device__ __forceinline__ void mma_bf16(float* d, const uint32_t* a, const uint32_t* b) {
    asm volatile(
        "mma.sync.aligned.m16n8k16.row.col.f32.bf16.bf16.f32 "
        "{%0,%1,%2,%3}, {%4,%5,%6,%7}, {%8,%9}, {%0,%1,%2,%3};"
        : "+f"(d[0]), "+f"(d[1]), "+f"(d[2]), "+f"(d[3])
        : "r"(a[0]), "r"(a[1]), "r"(a[2]), "r"(a[3]), "r"(b[0]), "r"(b[1]));
}
__device__ __forceinline__ void ldmx4(uint32_t* r, uint32_t addr) {
    asm volatile("ldmatrix.sync.aligned.m8n8.x4.shared.b16 {%0,%1,%2,%3}, [%4];"
        : "=r"(r[0]), "=r"(r[1]), "=r"(r[2]), "=r"(r[3]) : "r"(addr));
}
__device__ __forceinline__ uint32_t packbf(float lo, float hi) {
    __nv_bfloat162 h = __floats2bfloat162_rn(lo, hi);
    return *reinterpret_cast<uint32_t*>(&h);
}
__device__ __forceinline__ void cpa16(uint32_t dst, const void* src) {
    asm volatile("cp.async.cg.shared.global [%0], [%1], 16;" :: "r"(dst), "l"(src) : "memory");
}
#define CPA_COMMIT() asm volatile("cp.async.commit_group;" ::: "memory")
#define CPA_WAIT0()  asm volatile("cp.async.wait_group 0;"  ::: "memory")
#define SW64(o) ((uint32_t)(o) ^ (((uint32_t)(o) >> 3) & 0x30u))

// ================= bf16 mma GEMM v6: C = A(fp32) @ Bb(bf16,[N,K])^T + bias =========
template<int ACT, bool MASK, int OUT>
__global__ void __launch_bounds__(256, 2) mma_gemm_v6(
    const float* __restrict__ A, const __nv_bfloat16* __restrict__ Bb,
    const float* __restrict__ bias, void* __restrict__ Cv,
    int M, int N, int K, const unsigned char* __restrict__ rowmask)
{
    __shared__ __align__(128) __nv_bfloat16 As[2][128 * 32];
    __shared__ __align__(128) __nv_bfloat16 Bs[2][128 * 32];

    const int tid  = threadIdx.x;
    const int lane = tid & 31;
    const int wid  = tid >> 5;
    const int wr   = wid & 1;
    const int wc   = wid >> 1;
    const int gid  = lane >> 2;
    const int tig  = lane & 3;
    const int brow = blockIdx.y * 128;
    const int bcol = blockIdx.x * 128;

    const int r_st = tid >> 3;
    const int kq   = (tid & 7) * 4;
    const int sts_col = (tid & 7) * 8;
    const int b_row_cp = tid >> 2;
    const int b_cg     = (tid & 3);

    float acc[4][4][4];
    #pragma unroll
    for (int i = 0; i < 4; i++)
        #pragma unroll
        for (int j = 0; j < 4; j++)
            #pragma unroll
            for (int l = 0; l < 4; l++) acc[i][j][l] = 0.f;

    const uint32_t asb = (uint32_t)__cvta_generic_to_shared(&As[0][0]);
    const uint32_t bsb = (uint32_t)__cvta_generic_to_shared(&Bs[0][0]);
    const uint32_t bufoff = 128 * 32 * 2;

    const int a_row = (lane & 7) + ((lane >> 3) & 1) * 8;
    const int a_col = (lane >> 4) * 16;
    const int b_row = (lane & 7) + ((lane >> 4) & 1) * 8;
    const int b_col = ((lane >> 3) & 1) * 16;

    uint2 pa[4];

    #define LD_A(kc) do {                                                               \
        _Pragma("unroll")                                                               \
        for (int i = 0; i < 4; i++) {                                                   \
            int gr = brow + r_st + 32 * i; if (gr >= M) gr = M - 1;                     \
            float4 v = *reinterpret_cast<const float4*>(A + (size_t)gr * K + (kc) + kq);\
            pa[i].x = packbf(v.x, v.y); pa[i].y = packbf(v.z, v.w);                     \
        }                                                                               \
    } while (0)

    #define ST_A(buf) do {                                                              \
        char* sa = reinterpret_cast<char*>(&As[buf][0]);                                \
        _Pragma("unroll")                                                               \
        for (int i = 0; i < 4; i++)                                                     \
            *reinterpret_cast<uint2*>(sa + SW64((r_st + 32 * i) * 64 + sts_col)) = pa[i];\
    } while (0)

    #define CPA_B(kc, buf) do {                                                         \
        _Pragma("unroll")                                                               \
        for (int j = 0; j < 2; j++) {                                                   \
            int row = b_row_cp + 64 * j;                                                \
            cpa16(bsb + (buf) * bufoff + SW64(row * 64 + b_cg * 16),                    \
                  Bb + (size_t)(bcol + row) * K + (kc) + b_cg * 8);                     \
        }                                                                               \
    } while (0)

    const int KT = K >> 5;
    CPA_B(0, 0);
    CPA_COMMIT();
    LD_A(0);
    ST_A(0);
    CPA_WAIT0();
    __syncthreads();

    for (int kt = 0; kt < KT; kt++) {
        const int buf = kt & 1;
        if (kt + 1 < KT) {
            CPA_B((kt + 1) * 32, buf ^ 1);
            CPA_COMMIT();
            LD_A((kt + 1) * 32);
        }

        const uint32_t ab = asb + buf * bufoff;
        const uint32_t bb = bsb + buf * bufoff;
        #pragma unroll
        for (int ks = 0; ks < 2; ks++) {
            uint32_t af[4][4], bfq[2][4];
            #pragma unroll
            for (int mt = 0; mt < 4; mt++)
                ldmx4(af[mt], ab + SW64((wr * 64 + mt * 16 + a_row) * 64 + a_col + ks * 32));
            #pragma unroll
            for (int p = 0; p < 2; p++)
                ldmx4(bfq[p], bb + SW64((wc * 32 + p * 16 + b_row) * 64 + b_col + ks * 32));
            #pragma unroll
            for (int mt = 0; mt < 4; mt++)
                #pragma unroll
                for (int nt = 0; nt < 4; nt++)
                    mma_bf16(acc[mt][nt], af[mt], &bfq[nt >> 1][(nt & 1) * 2]);
        }

        if (kt + 1 < KT) {
            ST_A(buf ^ 1);
            CPA_WAIT0();
            __syncthreads();
        }
    }
    #undef LD_A
    #undef ST_A
    #undef CPA_B

    float* Cf = (float*)Cv;
    __nv_bfloat16* Cb = (__nv_bfloat16*)Cv;

    #pragma unroll
    for (int mt = 0; mt < 4; mt++) {
        const int r0 = brow + wr * 64 + mt * 16 + gid;
        const int r1 = r0 + 8;
        const bool v0 = r0 < M, v1 = r1 < M;
        bool z0 = false, z1 = false;
        if (MASK) {
            if (v0) z0 = (rowmask[r0] != 0);
            if (v1) z1 = (rowmask[r1] != 0);
        }
        #pragma unroll
        for (int nt = 0; nt < 4; nt++) {
            const int col = bcol + wc * 32 + nt * 8 + 2 * tig;
            const float b0 = bias[col], b1 = bias[col + 1];
            float2 u, v;
            u.x = acc[mt][nt][0] + b0; u.y = acc[mt][nt][1] + b1;
            v.x = acc[mt][nt][2] + b0; v.y = acc[mt][nt][3] + b1;
            if (ACT == 1) {
                u.x = fmaxf(u.x, 0.f); u.y = fmaxf(u.y, 0.f);
                v.x = fmaxf(v.x, 0.f); v.y = fmaxf(v.y, 0.f);
            }
            if (MASK) {
                if (z0) { u.x = 0.f; u.y = 0.f; }
                if (z1) { v.x = 0.f; v.y = 0.f; }
            }
            if (OUT == 0) {
                if (v0) *reinterpret_cast<float2*>(Cf + (size_t)r0 * N + col) = u;
                if (v1) *reinterpret_cast<float2*>(Cf + (size_t)r1 * N + col) = v;
            } else {
                __nv_bfloat162 hu = __floats2bfloat162_rn(u.x, u.y);
                __nv_bfloat162 hv = __floats2bfloat162_rn(v.x, v.y);
                if (v0) *reinterpret_cast<__nv_bfloat162*>(Cb + (size_t)r0 * N + col) = hu;
                if (v1) *reinterpret_cast<__nv_bfloat162*>(Cb + (size_t)r1 * N + col) = hv;
            }
        }
    }
}

// ================= bf16x3 GEMM (oa): C = (A+A2) @ [Bh+Bl]^T + bias, ~fp32 precision
// q split hi/lo bf16, W pre-split hi/lo. acc += qh*Wh + qh*Wl + ql*Wh.
// BM=128, BN=128, BK=32. Single-buffered 32KB smem, 2 CTAs/SM.
__global__ void __launch_bounds__(256, 2) mma_gemm_x3(
    const float* __restrict__ A, const float* __restrict__ A2,
    const __nv_bfloat16* __restrict__ Bh, const __nv_bfloat16* __restrict__ Bl,
    const float* __restrict__ bias, float* __restrict__ C,
    int M, int N, int K)
{
    __shared__ __align__(128) __nv_bfloat16 Ahs[128 * 32];
    __shared__ __align__(128) __nv_bfloat16 Als[128 * 32];
    __shared__ __align__(128) __nv_bfloat16 Bhs[128 * 32];
    __shared__ __align__(128) __nv_bfloat16 Bls[128 * 32];

    const int tid  = threadIdx.x;
    const int lane = tid & 31;
    const int wid  = tid >> 5;
    const int wr   = wid & 1;
    const int wc   = wid >> 1;
    const int gid  = lane >> 2;
    const int tig  = lane & 3;
    const int brow = blockIdx.y * 128;
    const int bcol = blockIdx.x * 128;

    const int r_st = tid >> 3;
    const int kq   = (tid & 7) * 4;
    const int sts_col = (tid & 7) * 8;
    const int b_row_cp = tid >> 2;
    const int b_cg     = (tid & 3);

    float acc[4][4][4];
    #pragma unroll
    for (int i = 0; i < 4; i++)
        #pragma unroll
        for (int j = 0; j < 4; j++)
            #pragma unroll
            for (int l = 0; l < 4; l++) acc[i][j][l] = 0.f;

    const uint32_t ahb = (uint32_t)__cvta_generic_to_shared(&Ahs[0]);
    const uint32_t alb = (uint32_t)__cvta_generic_to_shared(&Als[0]);
    const uint32_t bhb = (uint32_t)__cvta_generic_to_shared(&Bhs[0]);
    const uint32_t blb = (uint32_t)__cvta_generic_to_shared(&Bls[0]);

    const int a_row = (lane & 7) + ((lane >> 3) & 1) * 8;
    const int a_col = (lane >> 4) * 16;
    const int b_row = (lane & 7) + ((lane >> 4) & 1) * 8;
    const int b_col = ((lane >> 3) & 1) * 16;

    uint2 pah[4], pal[4];

    #define LD_AX(kc) do {                                                              \
        _Pragma("unroll")                                                               \
        for (int i = 0; i < 4; i++) {                                                   \
            int gr = brow + r_st + 32 * i; if (gr >= M) gr = M - 1;                     \
            float4 v  = *reinterpret_cast<const float4*>(A  + (size_t)gr * K + (kc) + kq);\
            float4 v2 = *reinterpret_cast<const float4*>(A2 + (size_t)gr * K + (kc) + kq);\
            v.x += v2.x; v.y += v2.y; v.z += v2.z; v.w += v2.w;                         \
            __nv_bfloat162 h0 = __floats2bfloat162_rn(v.x, v.y);                        \
            __nv_bfloat162 h1 = __floats2bfloat162_rn(v.z, v.w);                        \
            float2 f0 = __bfloat1622float2(h0);                                         \
            float2 f1 = __bfloat1622float2(h1);                                         \
            pah[i].x = *reinterpret_cast<uint32_t*>(&h0);                               \
            pah[i].y = *reinterpret_cast<uint32_t*>(&h1);                               \
            pal[i].x = packbf(v.x - f0.x, v.y - f0.y);                                  \
            pal[i].y = packbf(v.z - f1.x, v.w - f1.y);                                  \
        }                                                                               \
    } while (0)

    #define ST_AX() do {                                                                \
        char* sh = reinterpret_cast<char*>(&Ahs[0]);                                    \
        char* sl = reinterpret_cast<char*>(&Als[0]);                                    \
        _Pragma("unroll")                                                               \
        for (int i = 0; i < 4; i++) {                                                   \
            uint32_t o = SW64((r_st + 32 * i) * 64 + sts_col);                          \
            *reinterpret_cast<uint2*>(sh + o) = pah[i];                                 \
            *reinterpret_cast<uint2*>(sl + o) = pal[i];                                 \
        }                                                                               \
    } while (0)

    #define CPA_BX(kc) do {                                                             \
        _Pragma("unroll")                                                               \
        for (int j = 0; j < 2; j++) {                                                   \
            int row = b_row_cp + 64 * j;                                                \
            uint32_t o = SW64(row * 64 + b_cg * 16);                                    \
            size_t gsrc = (size_t)(bcol + row) * K + (kc) + b_cg * 8;                   \
            cpa16(bhb + o, Bh + gsrc);                                                  \
            cpa16(blb + o, Bl + gsrc);                                                  \
        }                                                                               \
    } while (0)

    const int KT = K >> 5;
    LD_AX(0);
    for (int kt = 0; kt < KT; kt++) {
        if (kt) __syncthreads();                 // previous compute done
        ST_AX();
        CPA_BX(kt * 32);
        CPA_COMMIT();
        if (kt + 1 < KT) LD_AX((kt + 1) * 32);   // LDGs in flight during wait
        CPA_WAIT0();
        __syncthreads();

        #pragma unroll
        for (int ks = 0; ks < 2; ks++) {
            uint32_t afh[4][4], bfh[2][4];
            #pragma unroll
            for (int mt = 0; mt < 4; mt++)
                ldmx4(afh[mt], ahb + SW64((wr * 64 + mt * 16 + a_row) * 64 + a_col + ks * 32));
            #pragma unroll
            for (int p = 0; p < 2; p++)
                ldmx4(bfh[p], bhb + SW64((wc * 32 + p * 16 + b_row) * 64 + b_col + ks * 32));
            #pragma unroll
            for (int mt = 0; mt < 4; mt++)
                #pragma unroll
                for (int nt = 0; nt < 4; nt++)
                    mma_bf16(acc[mt][nt], afh[mt], &bfh[nt >> 1][(nt & 1) * 2]);

            {   // qh * Wl
                uint32_t bfl[2][4];
                #pragma unroll
                for (int p = 0; p < 2; p++)
                    ldmx4(bfl[p], blb + SW64((wc * 32 + p * 16 + b_row) * 64 + b_col + ks * 32));
                #pragma unroll
                for (int mt = 0; mt < 4; mt++)
                    #pragma unroll
                    for (int nt = 0; nt < 4; nt++)
                        mma_bf16(acc[mt][nt], afh[mt], &bfl[nt >> 1][(nt & 1) * 2]);
            }
            {   // ql * Wh
                uint32_t afl[4][4];
                #pragma unroll
                for (int mt = 0; mt < 4; mt++)
                    ldmx4(afl[mt], alb + SW64((wr * 64 + mt * 16 + a_row) * 64 + a_col + ks * 32));
                #pragma unroll
                for (int mt = 0; mt < 4; mt++)
                    #pragma unroll
                    for (int nt = 0; nt < 4; nt++)
                        mma_bf16(acc[mt][nt], afl[mt], &bfh[nt >> 1][(nt & 1) * 2]);
            }
        }
    }
    #undef LD_AX
    #undef ST_AX
    #undef CPA_BX

    #pragma unroll
    for (int mt = 0; mt < 4; mt++) {
        const int r0 = brow + wr * 64 + mt * 16 + gid;
        const int r1 = r0 + 8;
        const bool v0 = r0 < M, v1 = r1 < M;
        #pragma unroll
        for (int nt = 0; nt < 4; nt++) {
            const int col = bcol + wc * 32 + nt * 8 + 2 * tig;
            const float b0 = bias[col], b1 = bias[col + 1];
            float2 u, v;
            u.x = acc[mt][nt][0] + b0; u.y = acc[mt][nt][1] + b1;
            v.x = acc[mt][nt][2] + b0; v.y = acc[mt][nt][3] + b1;
            if (v0) *reinterpret_cast<float2*>(C + (size_t)r0 * N + col) = u;
            if (v1) *reinterpret_cast<float2*>(C + (size_t)r1 * N + col) = v;
        }
    }
}

// ---------------- unified weight prep: z=0..3 transpose->bf16, z=4 oa concat hi/lo --
__global__ void wprep_kernel(const float* __restrict__ Wv,  __nv_bfloat16* __restrict__ WvT,
                             const float* __restrict__ Wo,  __nv_bfloat16* __restrict__ WoT,
                             const float* __restrict__ W1,  __nv_bfloat16* __restrict__ W1T,
                             const float* __restrict__ W2,  __nv_bfloat16* __restrict__ W2T,
                             const float* __restrict__ Woff, const float* __restrict__ boff,
                             const float* __restrict__ Watt, const float* __restrict__ batt,
                             __nv_bfloat16* __restrict__ WoaTh, __nv_bfloat16* __restrict__ WoaTl,
                             float* __restrict__ boa)
{
    __shared__ float t[32][33];
    const int x = threadIdx.x, y = threadIdx.y;
    const int z = blockIdx.z;

    if (z == 4) {   // oa concat -> hi/lo bf16 [384,256]
        const int bx = blockIdx.x * 32;
        const int by = blockIdx.y * 32;
        if (bx >= NOA || by >= DIM) return;
        const bool isAtt = (bx >= 256);
        const float* W = isAtt ? Watt : Woff;
        const int    nN = isAtt ? 128 : 256;
        const int    nb = isAtt ? bx - 256 : bx;
        #pragma unroll
        for (int i = 0; i < 32; i += 8)
            t[y + i][x] = W[(size_t)(by + y + i) * nN + nb + x];
        __syncthreads();
        #pragma unroll
        for (int i = 0; i < 32; i += 8) {
            float w = t[x][y + i];
            __nv_bfloat16 h = __float2bfloat16(w);
            size_t idx = (size_t)(bx + y + i) * DIM + by + x;
            WoaTh[idx] = h;
            WoaTl[idx] = __float2bfloat16(w - __bfloat162float(h));
        }
        if (blockIdx.y == 0 && y == 0) {
            int n = bx + x;
            boa[n] = (n < 256) ? boff[n] : batt[n - 256];
        }
        return;
    }

    const float* W; __nv_bfloat16* Wt; int K, N;
    switch (z) {
        case 0: W = Wv; Wt = WvT; K = DIM; N = DIM; break;
        case 1: W = Wo; Wt = WoT; K = DIM; N = DIM; break;
        case 2: W = W1; Wt = W1T; K = DIM; N = DFF; break;
        default:W = W2; Wt = W2T; K = DFF; N = DIM; break;
    }
    const int bx = blockIdx.x * 32;
    const int by = blockIdx.y * 32;
    if (bx >= N || by >= K) return;
    #pragma unroll
    for (int i = 0; i < 32; i += 8)
        t[y + i][x] = W[(size_t)(by + y + i) * N + bx + x];
    __syncthreads();
    #pragma unroll
    for (int i = 0; i < 32; i += 8)
        Wt[(size_t)(bx + y + i) * K + by + x] = __float2bfloat16(t[x][y + i]);
}

// ---------------- MS-deform sampling v3: hoisted point math, fused weights --------
// block = 128 (4 warps), grid = NQ. warp = heads 2wh, 2wh+1.
// lane = g*16 + j: lane OWNS point j of head (2wh+g) for precompute,
// and PROCESSES channel pair j of head (2wh+g) in the gather loop.
__global__ void __launch_bounds__(128) msda_kernel(
    const __nv_bfloat16* __restrict__ value,
    const float* __restrict__ oa,
    const float* __restrict__ refpts,
    float* __restrict__ samp)
{
    const int nq   = blockIdx.x;
    const int wh   = threadIdx.x >> 5;
    const int lane = threadIdx.x & 31;
    const int g    = lane >> 4;
    const int j    = lane & 15;          // point index (as owner) / channel pair (as gatherer)
    const int h    = wh * 2 + g;
    const int n    = nq / LQ;

    // softmax over 16 logits per head
    float logit = oa[(size_t)nq * NOA + 256 + wh * 32 + lane];
    float m = logit;
    #pragma unroll
    for (int o = 8; o > 0; o >>= 1) m = fmaxf(m, __shfl_xor_sync(0xffffffffu, m, o, 16));
    float e = __expf(logit - m);
    float s = e;
    #pragma unroll
    for (int o = 8; o > 0; o >>= 1) s += __shfl_xor_sync(0xffffffffu, s, o, 16);
    const float wi = e / s;              // weight of this lane's own point

    // own point's offsets and ref
    const float2 offv = *reinterpret_cast<const float2*>(oa + (size_t)nq * NOA + wh * 64 + 2 * lane);
    float2 refv = make_float2(0.f, 0.f);
    if (lane < 4) refv = *reinterpret_cast<const float2*>(refpts + (size_t)nq * 8 + 2 * lane);
    const int l = j >> 2;
    const float refx = __shfl_sync(0xffffffffu, refv.x, l);
    const float refy = __shfl_sync(0xffffffffu, refv.y, l);

    // ---- precompute own point's 4 corner byte-offsets + fused weights ----
    const int Hl = c_H[l], Wl = c_W[l], st = c_S[l];
    const float x = refx * (float)Wl + offv.x - 0.5f;
    const float y = refy * (float)Hl + offv.y - 0.5f;
    const float x0f = floorf(x), y0f = floorf(y);
    const float fx = x - x0f, fy = y - y0f;
    const int x0 = (int)x0f, y0 = (int)y0f;
    const int x1 = x0 + 1,   y1 = y0 + 1;
    const float vx0 = (x0 >= 0 && x0 < Wl) ? 1.f : 0.f;
    const float vx1 = (x1 >= 0 && x1 < Wl) ? 1.f : 0.f;
    const float vy0 = (y0 >= 0 && y0 < Hl) ? 1.f : 0.f;
    const float vy1 = (y1 >= 0 && y1 < Hl) ? 1.f : 0.f;
    const int xc0 = min(max(x0, 0), Wl - 1), xc1 = min(max(x1, 0), Wl - 1);
    const int yc0 = min(max(y0, 0), Hl - 1), yc1 = min(max(y1, 0), Hl - 1);
    // byte offsets into the (n,h)-plane: element stride per spatial pos = 256 bf16 = 512 B
    const uint32_t o00 = (uint32_t)(st + yc0 * Wl + xc0) * 512u;
    const uint32_t o01 = (uint32_t)(st + yc0 * Wl + xc1) * 512u;
    const uint32_t o10 = (uint32_t)(st + yc1 * Wl + xc0) * 512u;
    const uint32_t o11 = (uint32_t)(st + yc1 * Wl + xc1) * 512u;
    const float w00 = (1.f - fx) * (1.f - fy) * vx0 * vy0 * wi;
    const float w01 = fx * (1.f - fy) * vx1 * vy0 * wi;
    const float w10 = (1.f - fx) * fy * vx0 * vy1 * wi;
    const float w11 = fx * fy * vx1 * vy1 * wi;

    const char* vb = reinterpret_cast<const char*>(
        value + ((size_t)n * LIN * HEADS + h) * HD + 2 * j);

    float2 acc = make_float2(0.f, 0.f);
    #pragma unroll
    for (int i = 0; i < 16; i++) {
        const int src = g * 16 + i;
        const uint32_t q00 = __shfl_sync(0xffffffffu, o00, src);
        const uint32_t q01 = __shfl_sync(0xffffffffu, o01, src);
        const uint32_t q10 = __shfl_sync(0xffffffffu, o10, src);
        const uint32_t q11 = __shfl_sync(0xffffffffu, o11, src);
        const float u00 = __shfl_sync(0xffffffffu, w00, src);
        const float u01 = __shfl_sync(0xffffffffu, w01, src);
        const float u10 = __shfl_sync(0xffffffffu, w10, src);
        const float u11 = __shfl_sync(0xffffffffu, w11, src);

        float2 v00 = __bfloat1622float2(*reinterpret_cast<const __nv_bfloat162*>(vb + q00));
        float2 v01 = __bfloat1622float2(*reinterpret_cast<const __nv_bfloat162*>(vb + q01));
        float2 v10 = __bfloat1622float2(*reinterpret_cast<const __nv_bfloat162*>(vb + q10));
        float2 v11 = __bfloat1622float2(*reinterpret_cast<const __nv_bfloat162*>(vb + q11));

        acc.x += u00 * v00.x + u01 * v01.x + u10 * v10.x + u11 * v11.x;
        acc.y += u00 * v00.y + u01 * v01.y + u10 * v10.y + u11 * v11.y;
    }
    *reinterpret_cast<float2*>(samp + (size_t)nq * 256 + h * 32 + 2 * j) = acc;
}

// ---------------- fused residual + LayerNorm (warp per row) ----------------
__global__ void ln_kernel(const float* __restrict__ a, const float* __restrict__ b,
                          const float* __restrict__ g, const float* __restrict__ be,
                          float* __restrict__ out)
{
    const int row  = blockIdx.x * 8 + (threadIdx.x >> 5);
    const int lane = threadIdx.x & 31;
    const size_t base = (size_t)row * 256;

    float4 a0 = *reinterpret_cast<const float4*>(a + base + lane * 4);
    float4 a1 = *reinterpret_cast<const float4*>(a + base + 128 + lane * 4);
    float4 b0 = *reinterpret_cast<const float4*>(b + base + lane * 4);
    float4 b1 = *reinterpret_cast<const float4*>(b + base + 128 + lane * 4);
    float x0 = a0.x + b0.x, x1 = a0.y + b0.y, x2 = a0.z + b0.z, x3 = a0.w + b0.w;
    float x4 = a1.x + b1.x, x5 = a1.y + b1.y, x6 = a1.z + b1.z, x7 = a1.w + b1.w;

    float s  = x0 + x1 + x2 + x3 + x4 + x5 + x6 + x7;
    float s2 = x0*x0 + x1*x1 + x2*x2 + x3*x3 + x4*x4 + x5*x5 + x6*x6 + x7*x7;
    #pragma unroll
    for (int o = 16; o > 0; o >>= 1) {
        s  += __shfl_xor_sync(0xffffffffu, s,  o);
        s2 += __shfl_xor_sync(0xffffffffu, s2, o);
    }
    const float mean = s * (1.f / 256.f);
    const float rstd = rsqrtf(s2 * (1.f / 256.f) - mean * mean + 1e-5f);

    float4 g0 = *reinterpret_cast<const float4*>(g + lane * 4);
    float4 g1 = *reinterpret_cast<const float4*>(g + 128 + lane * 4);
    float4 e0 = *reinterpret_cast<const float4*>(be + lane * 4);
    float4 e1 = *reinterpret_cast<const float4*>(be + 128 + lane * 4);

    float4 o0, o1;
    o0.x = (x0 - mean) * rstd * g0.x + e0.x;
    o0.y = (x1 - mean) * rstd * g0.y + e0.y;
    o0.z = (x2 - mean) * rstd * g0.z + e0.z;
    o0.w = (x3 - mean) * rstd * g0.w + e0.w;
    o1.x = (x4 - mean) * rstd * g1.x + e1.x;
    o1.y = (x5 - mean) * rstd * g1.y + e1.y;
    o1.z = (x6 - mean) * rstd * g1.z + e1.z;
    o1.w = (x7 - mean) * rstd * g1.w + e1.w;
    *reinterpret_cast<float4*>(out + base + lane * 4)       = o0;
    *reinterpret_cast<float4*>(out + base + 128 + lane * 4) = o1;
}

// ---------------- launch ----------------
extern "C" void kernel_launch(void* const* d_in, const int* in_sizes, int n_in,
                              void* d_out, int out_size)
{
    const float* pre_tgt  = (const float*)d_in[0];
    const float* pre_qpos = (const float*)d_in[1];
    const float* src      = (const float*)d_in[2];
    const float* ref_pts  = (const float*)d_in[3];
    const unsigned char* mask = (const unsigned char*)d_in[4];
    const float* W_value = (const float*)d_in[7];
    const float* b_value = (const float*)d_in[8];
    const float* W_off   = (const float*)d_in[9];
    const float* b_off   = (const float*)d_in[10];
    const float* W_attn  = (const float*)d_in[11];
    const float* b_attn  = (const float*)d_in[12];
    const float* W_out   = (const float*)d_in[13];
    const float* b_out   = (const float*)d_in[14];
    const float* g1      = (const float*)d_in[15];
    const float* be1     = (const float*)d_in[16];
    const float* W1      = (const float*)d_in[17];
    const float* b1      = (const float*)d_in[18];
    const float* W2      = (const float*)d_in[19];
    const float* b2      = (const float*)d_in[20];
    const float* g3      = (const float*)d_in[21];
    const float* be3     = (const float*)d_in[22];

    __nv_bfloat16 *p_value, *p_WvTb, *p_WoutTb, *p_W1Tb, *p_W2Tb, *p_WoaTh, *p_WoaTl;
    float *p_oa, *p_samp, *p_ms, *p_tgt, *p_ffh, *p_ff, *p_boa;
    cudaGetSymbolAddress((void**)&p_value, g_value);
    cudaGetSymbolAddress((void**)&p_oa,    g_oa);
    cudaGetSymbolAddress((void**)&p_samp,  g_samp);
    cudaGetSymbolAddress((void**)&p_ms,    g_ms);
    cudaGetSymbolAddress((void**)&p_tgt,   g_tgt);
    cudaGetSymbolAddress((void**)&p_ffh,   g_ffh);
    cudaGetSymbolAddress((void**)&p_ff,    g_ff);
    cudaGetSymbolAddress((void**)&p_WvTb,  g_WvTb);
    cudaGetSymbolAddress((void**)&p_WoutTb,g_WoutTb);
    cudaGetSymbolAddress((void**)&p_W1Tb,  g_W1Tb);
    cudaGetSymbolAddress((void**)&p_W2Tb,  g_W2Tb);
    cudaGetSymbolAddress((void**)&p_WoaTh, g_WoaTh);
    cudaGetSymbolAddress((void**)&p_WoaTl, g_WoaTl);
    cudaGetSymbolAddress((void**)&p_boa,   g_boa);

    const int MV = NB * LIN;   // 174080
    dim3 tb(32, 8);

    // 1. unified weight prep
    wprep_kernel<<<dim3(16, 16, 5), tb>>>(W_value, p_WvTb, W_out, p_WoutTb,
                                          W1, p_W1Tb, W2, p_W2Tb,
                                          W_off, b_off, W_attn, b_attn,
                                          p_WoaTh, p_WoaTl, p_boa);
    // 2. value = mask(src @ Wv + bv) -> bf16
    mma_gemm_v6<0, true, 1><<<dim3(2, MV / 128), 256>>>(
        src, p_WvTb, b_value, p_value, MV, DIM, DIM, mask);
    // 3. oa = (pre_tgt + pre_qpos) @ [Woff|Wattn] + bias   (bf16x3, ~fp32 precision)
    mma_gemm_x3<<<dim3(NOA / 128, (NQ + 127) / 128), 256>>>(
        pre_tgt, pre_qpos, p_WoaTh, p_WoaTl, p_boa, p_oa, NQ, NOA, DIM);
    // 4. sampling (launch #4 -> profiled)
    msda_kernel<<<NQ, 128>>>(p_value, p_oa, ref_pts, p_samp);
    // 5. ms = samp @ Wout + bout
    mma_gemm_v6<0, false, 0><<<dim3(2, (NQ + 127) / 128), 256>>>(
        p_samp, p_WoutTb, b_out, p_ms, NQ, DIM, DIM, nullptr);
    // 6. tgt = LN(pre_tgt + ms)
    ln_kernel<<<NQ / 8, 256>>>(pre_tgt, p_ms, g1, be1, p_tgt);
    // 7. ffh = relu(tgt @ W1 + b1)
    mma_gemm_v6<1, false, 0><<<dim3(4, (NQ + 127) / 128), 256>>>(
        p_tgt, p_W1Tb, b1, p_ffh, NQ, DFF, DIM, nullptr);
    // 8. ff = ffh @ W2 + b2
    mma_gemm_v6<0, false, 0><<<dim3(2, (NQ + 127) / 128), 256>>>(
        p_ffh, p_W2Tb, b2, p_ff, NQ, DIM, DFF, nullptr);
    // 9. out = LN(tgt + ff)
    ln_kernel<<<NQ / 8, 256>>>(p_tgt, p_ff, g3, be3, (float*)d_out);
}